// round 1
// baseline (speedup 1.0000x reference)
#include <cuda_runtime.h>
#include <math.h>

#define BB  4
#define PP  2048
#define QQ  1024
#define QNN 32
#define DD  256
#define HH  128

// ---------------- persistent scratch (no allocations allowed) ----------------
__device__ float g_pA[BB*PP*DD];
__device__ float g_pB[BB*PP*DD];
__device__ float g_qA[BB*QQ*DD];
__device__ float g_qB[BB*QQ*DD];
__device__ float g_quA[BB*QNN*DD];
__device__ float g_quB[BB*QNN*DD];
__device__ float g_selfp[BB*PP*DD];
__device__ float g_Yp[BB*PP*DD];
__device__ float g_selfq[BB*QQ*DD];
__device__ float g_Yq[BB*QQ*DD];
__device__ float g_selfqu[BB*QNN*DD];
__device__ float g_rsp[BB*PP];    // pm * sigmoid(p @ W_node + b)
__device__ float g_rsq[BB*QQ];    // qm * sigmoid(q @ W_node + b)
__device__ float g_coefp[BB*PP];  // pm_i / max(p_nb, 1)
__device__ float g_coefq[BB*QQ];
__device__ float g_coefqu[BB*QNN];
__device__ float g_sp[BB*DD];     // sum_j rsp_j * p_node[j,:]
__device__ float g_sq[BB*DD];
__device__ float g_vqd[BB*DD];    // s_p @ W_qd
__device__ float g_vqup[BB*DD];   // s_p @ W_qup
__device__ float g_vquq[BB*DD];   // s_q @ W_quq
__device__ float g_summ[2*BB];    // [sum_pm per b, sum_qm per b]

// ---------------- small kernels ----------------

__global__ void zero_s_kernel() {
    int i = blockIdx.x * blockDim.x + threadIdx.x;
    if (i < BB*DD) { g_sp[i] = 0.f; g_sq[i] = 0.f; }
}

__global__ void summask_kernel(const int* __restrict__ pm, const int* __restrict__ qm) {
    int b = blockIdx.x, tid = threadIdx.x;
    __shared__ float red[256];
    float s = 0.f;
    for (int i = tid; i < PP; i += 256) s += (float)pm[b*PP + i];
    red[tid] = s; __syncthreads();
    for (int o = 128; o; o >>= 1) { if (tid < o) red[tid] += red[tid + o]; __syncthreads(); }
    if (tid == 0) g_summ[b] = red[0];
    __syncthreads();
    s = 0.f;
    for (int i = tid; i < QQ; i += 256) s += (float)qm[b*QQ + i];
    red[tid] = s; __syncthreads();
    for (int o = 128; o; o >>= 1) { if (tid < o) red[tid] += red[tid + o]; __syncthreads(); }
    if (tid == 0) g_summ[BB + b] = red[0];
}

// coef_p[b,i] = pm_i ? 1/max(sum_j pm_j*ppg[i,j], 1) : 0
__global__ void coefp_kernel(const int* __restrict__ G, const int* __restrict__ pm) {
    int b = blockIdx.y;
    __shared__ float spm[PP];
    int tid = threadIdx.x;
    for (int i = tid; i < PP; i += 256) spm[i] = (float)pm[b*PP + i];
    __syncthreads();
    int warp = tid >> 5, lane = tid & 31;
    int row = blockIdx.x * 8 + warp;
    const int* g = G + ((size_t)b*PP + row) * PP;
    float s = 0.f;
    for (int j = lane; j < PP; j += 32) s += spm[j] * (float)g[j];
    for (int o = 16; o; o >>= 1) s += __shfl_xor_sync(0xffffffffu, s, o);
    if (lane == 0)
        g_coefp[b*PP + row] = pm[b*PP + row] ? 1.f / fmaxf(s, 1.f) : 0.f;
}

// coef_q[b,i] = qm_i ? 1/max(sum_pm + sum_j qm_j*qqg[i,j], 1) : 0
__global__ void coefq_kernel(const int* __restrict__ G, const int* __restrict__ qm) {
    int b = blockIdx.y;
    __shared__ float sqm[QQ];
    int tid = threadIdx.x;
    for (int i = tid; i < QQ; i += 256) sqm[i] = (float)qm[b*QQ + i];
    __syncthreads();
    int warp = tid >> 5, lane = tid & 31;
    int row = blockIdx.x * 8 + warp;
    const int* g = G + ((size_t)b*QQ + row) * QQ;
    float s = 0.f;
    for (int j = lane; j < QQ; j += 32) s += sqm[j] * (float)g[j];
    for (int o = 16; o; o >>= 1) s += __shfl_xor_sync(0xffffffffu, s, o);
    if (lane == 0)
        g_coefq[b*QQ + row] = qm[b*QQ + row] ? 1.f / fmaxf(g_summ[b] + s, 1.f) : 0.f;
}

__global__ void coefqu_kernel(const int* __restrict__ qum) {
    int i = blockIdx.x * blockDim.x + threadIdx.x;
    if (i >= BB*QNN) return;
    int b = i / QNN;
    float t = g_summ[b] + g_summ[BB + b];
    g_coefqu[i] = qum[i] ? 1.f / fmaxf(t, 1.f) : 0.f;
}

// node-importance weights: rs = mask * sigmoid(node @ W_node + b_node)
__global__ void pw_kernel(const float* __restrict__ pcur, const float* __restrict__ qcur,
                          const int* __restrict__ pmask, const int* __restrict__ qmask,
                          const float* __restrict__ Wn, const float* __restrict__ bn) {
    __shared__ float w[DD];
    int tid = threadIdx.x;
    for (int k = tid; k < DD; k += 256) w[k] = Wn[k];
    __syncthreads();
    int warp = tid >> 5, lane = tid & 31;
    int row = blockIdx.x * 8 + warp;
    const float* node; const int* mask; float* out; int idx;
    const int NP = BB*PP;
    if (row < NP) { node = pcur + (size_t)row*DD; mask = pmask; idx = row; out = g_rsp; }
    else {
        int r = row - NP;
        if (r >= BB*QQ) return;
        node = qcur + (size_t)r*DD; mask = qmask; idx = r; out = g_rsq;
    }
    float s = 0.f;
    for (int k = lane; k < DD; k += 32) s += node[k] * w[k];
    for (int o = 16; o; o >>= 1) s += __shfl_xor_sync(0xffffffffu, s, o);
    if (lane == 0) {
        float sig = 1.f / (1.f + expf(-(s + bn[0])));
        out[idx] = mask[idx] ? sig : 0.f;
    }
}

// s_p[b,:] = sum_i rsp[b,i]*p_node[b,i,:]   (and s_q)
__global__ void s_kernel(const float* __restrict__ pcur, const float* __restrict__ qcur) {
    int b = blockIdx.x;
    int chunk = blockIdx.y;
    int tid = threadIdx.x; // = d
    float acc = 0.f;
    if (chunk < 16) {
        int i0 = chunk * 128;
        for (int i = 0; i < 128; i++) {
            float w = g_rsp[b*PP + i0 + i];
            if (w != 0.f) acc += w * pcur[((size_t)(b*PP + i0 + i))*DD + tid];
        }
        atomicAdd(&g_sp[b*DD + tid], acc);
    } else {
        int i0 = (chunk - 16) * 128;
        for (int i = 0; i < 128; i++) {
            float w = g_rsq[b*QQ + i0 + i];
            if (w != 0.f) acc += w * qcur[((size_t)(b*QQ + i0 + i))*DD + tid];
        }
        atomicAdd(&g_sq[b*DD + tid], acc);
    }
}

// v = s @ W  (three small GEMVs)
__global__ void vec_kernel(const float* __restrict__ Wqd, const float* __restrict__ Wqup,
                           const float* __restrict__ Wquq) {
    int b = blockIdx.x, sel = blockIdx.y, tid = threadIdx.x;
    __shared__ float sh[DD];
    const float* s = (sel == 2) ? g_sq : g_sp;
    const float* W = (sel == 0) ? Wqd : (sel == 1) ? Wqup : Wquq;
    float* out = (sel == 0) ? g_vqd : (sel == 1) ? g_vqup : g_vquq;
    sh[tid] = s[b*DD + tid];
    __syncthreads();
    float acc = 0.f;
    #pragma unroll 8
    for (int k = 0; k < DD; k++) acc += sh[k] * W[(size_t)k*DD + tid];
    out[b*DD + tid] = acc;
}

// qu_new = relu(self_qu + coef_qu * (vqup + vquq))
__global__ void qu_update_kernel(float* __restrict__ qunxt) {
    int r = blockIdx.x;          // 0..B*QN-1
    int d = threadIdx.x;         // 0..255
    int b = r / QNN;
    float v = g_selfqu[(size_t)r*DD + d] + g_coefqu[r] * (g_vqup[b*DD + d] + g_vquq[b*DD + d]);
    qunxt[(size_t)r*DD + d] = fmaxf(v, 0.f);
}

// ---------------- tiled fp32 GEMMs ----------------
// C[M,N] = A[M,256] @ W[256,N], epilogue: +bias[n] or *rowscale[row]
__global__ __launch_bounds__(256)
void gemm_feat_kernel(const float* __restrict__ A, const float* __restrict__ W,
                      float* __restrict__ C, int Mrows, int N,
                      const float* __restrict__ bias, const float* __restrict__ rowscale) {
    __shared__ float As[16][68];
    __shared__ float Bs[16][64];
    int bm = blockIdx.x * 64, bn = blockIdx.y * 64;
    int tid = threadIdx.x;
    int tx = tid & 15, ty = tid >> 4;
    int arow = tid >> 4, ak = tid & 15;
    int bk = tid >> 6, bnl = tid & 63;
    float acc[4][4] = {};
    for (int k0 = 0; k0 < DD; k0 += 16) {
        #pragma unroll
        for (int p2 = 0; p2 < 4; p2++) {
            int r = arow + p2*16;
            int row = bm + r;
            As[ak][r] = (row < Mrows) ? A[(size_t)row*DD + k0 + ak] : 0.f;
        }
        #pragma unroll
        for (int p2 = 0; p2 < 4; p2++) {
            int kk = bk + p2*4;
            Bs[kk][bnl] = W[(size_t)(k0 + kk)*N + bn + bnl];
        }
        __syncthreads();
        #pragma unroll
        for (int kk = 0; kk < 16; kk++) {
            float ar[4], br[4];
            #pragma unroll
            for (int i = 0; i < 4; i++) ar[i] = As[kk][ty*4 + i];
            #pragma unroll
            for (int j = 0; j < 4; j++) br[j] = Bs[kk][tx*4 + j];
            #pragma unroll
            for (int i = 0; i < 4; i++)
                #pragma unroll
                for (int j = 0; j < 4; j++) acc[i][j] += ar[i] * br[j];
        }
        __syncthreads();
    }
    #pragma unroll
    for (int i = 0; i < 4; i++) {
        int row = bm + ty*4 + i;
        if (row >= Mrows) continue;
        float rs = rowscale ? rowscale[row] : 1.f;
        #pragma unroll
        for (int j = 0; j < 4; j++) {
            int n = bn + tx*4 + j;
            float v = acc[i][j] * rs + (bias ? bias[n] : 0.f);
            C[(size_t)row*N + n] = v;
        }
    }
}

// O[b,i,:] = relu(S[b,i,:] + coef[b,i]*(sum_j G[b,i,j]*Y[b,j,:] + ev[b,:]))
__global__ __launch_bounds__(256)
void gemm_adj_kernel(const int* __restrict__ Gf, const float* __restrict__ Yf,
                     const float* __restrict__ Sf, const float* __restrict__ coefF,
                     const float* __restrict__ ev, float* __restrict__ Of, int NN) {
    int b = blockIdx.z;
    const int*   G    = Gf + (size_t)b*NN*NN;
    const float* Y    = Yf + (size_t)b*NN*DD;
    const float* S    = Sf + (size_t)b*NN*DD;
    const float* coef = coefF + (size_t)b*NN;
    float*       O    = Of + (size_t)b*NN*DD;
    __shared__ float As[16][68];
    __shared__ float Bs[16][64];
    int bm = blockIdx.x * 64, bn = blockIdx.y * 64;
    int tid = threadIdx.x;
    int tx = tid & 15, ty = tid >> 4;
    int arow = tid >> 4, ak = tid & 15;
    int bk = tid >> 6, bnl = tid & 63;
    float acc[4][4] = {};
    for (int k0 = 0; k0 < NN; k0 += 16) {
        #pragma unroll
        for (int p2 = 0; p2 < 4; p2++) {
            int r = arow + p2*16;
            As[ak][r] = (float)G[(size_t)(bm + r)*NN + k0 + ak];
        }
        #pragma unroll
        for (int p2 = 0; p2 < 4; p2++) {
            int kk = bk + p2*4;
            Bs[kk][bnl] = Y[(size_t)(k0 + kk)*DD + bn + bnl];
        }
        __syncthreads();
        #pragma unroll
        for (int kk = 0; kk < 16; kk++) {
            float ar[4], br[4];
            #pragma unroll
            for (int i = 0; i < 4; i++) ar[i] = As[kk][ty*4 + i];
            #pragma unroll
            for (int j = 0; j < 4; j++) br[j] = Bs[kk][tx*4 + j];
            #pragma unroll
            for (int i = 0; i < 4; i++)
                #pragma unroll
                for (int j = 0; j < 4; j++) acc[i][j] += ar[i] * br[j];
        }
        __syncthreads();
    }
    #pragma unroll
    for (int i = 0; i < 4; i++) {
        int row = bm + ty*4 + i;
        float c = coef[row];
        #pragma unroll
        for (int j = 0; j < 4; j++) {
            int n = bn + tx*4 + j;
            float e = ev ? ev[(size_t)b*DD + n] : 0.f;
            float v = S[(size_t)row*DD + n] + c * (acc[i][j] + e);
            O[(size_t)row*DD + n] = fmaxf(v, 0.f);
        }
    }
}

// ---------------- launch ----------------
extern "C" void kernel_launch(void* const* d_in, const int* in_sizes, int n_in,
                              void* d_out, int out_size) {
    const float* p_in   = (const float*)d_in[0];
    const float* q_in   = (const float*)d_in[1];
    const float* qu_in  = (const float*)d_in[2];
    const int*   pmask  = (const int*)d_in[3];
    const int*   qmask  = (const int*)d_in[4];
    const int*   qumask = (const int*)d_in[5];
    const int*   ppg    = (const int*)d_in[6];
    const int*   qqg    = (const int*)d_in[7];
    // d_in[8], d_in[9]: evidence tensors — unused by the reference
    const float* W_node = (const float*)d_in[10];
    const float* b_node = (const float*)d_in[11];
    const float* W_self = (const float*)d_in[12];
    const float* b_self = (const float*)d_in[13];
    const float* W_pp   = (const float*)d_in[14];
    const float* W_qd   = (const float*)d_in[15];
    const float* W_qq   = (const float*)d_in[16];
    const float* W_qup  = (const float*)d_in[17];
    const float* W_quq  = (const float*)d_in[18];
    const float* W_p    = (const float*)d_in[19];
    const float* b_p    = (const float*)d_in[20];
    const float* W_q    = (const float*)d_in[21];
    const float* b_q    = (const float*)d_in[22];
    const float* W_qu   = (const float*)d_in[23];
    const float* b_qu   = (const float*)d_in[24];
    float* out = (float*)d_out;

    float *pA, *pB, *qA, *qB, *quA, *quB, *selfp, *Yp, *selfq, *Yq, *selfqu;
    float *rsp, *rsq, *coefp, *coefq, *vqd;
    cudaGetSymbolAddress((void**)&pA, g_pA);
    cudaGetSymbolAddress((void**)&pB, g_pB);
    cudaGetSymbolAddress((void**)&qA, g_qA);
    cudaGetSymbolAddress((void**)&qB, g_qB);
    cudaGetSymbolAddress((void**)&quA, g_quA);
    cudaGetSymbolAddress((void**)&quB, g_quB);
    cudaGetSymbolAddress((void**)&selfp, g_selfp);
    cudaGetSymbolAddress((void**)&Yp, g_Yp);
    cudaGetSymbolAddress((void**)&selfq, g_selfq);
    cudaGetSymbolAddress((void**)&Yq, g_Yq);
    cudaGetSymbolAddress((void**)&selfqu, g_selfqu);
    cudaGetSymbolAddress((void**)&rsp, g_rsp);
    cudaGetSymbolAddress((void**)&rsq, g_rsq);
    cudaGetSymbolAddress((void**)&coefp, g_coefp);
    cudaGetSymbolAddress((void**)&coefq, g_coefq);
    cudaGetSymbolAddress((void**)&vqd, g_vqd);

    // step-invariant mask coefficients
    summask_kernel<<<BB, 256>>>(pmask, qmask);
    coefp_kernel<<<dim3(PP/8, BB), 256>>>(ppg, pmask);
    coefq_kernel<<<dim3(QQ/8, BB), 256>>>(qqg, qmask);
    coefqu_kernel<<<1, 128>>>(qumask);

    const float* pc = p_in;  const float* qc = q_in;  const float* quc = qu_in;
    float* pn = pA;  float* qn = qA;  float* qun = quA;

    for (int step = 0; step < 2; step++) {
        zero_s_kernel<<<4, 256>>>();
        pw_kernel<<<(BB*PP + BB*QQ)/8, 256>>>(pc, qc, pmask, qmask, W_node, b_node);
        s_kernel<<<dim3(BB, 24), 256>>>(pc, qc);
        vec_kernel<<<dim3(BB, 3), 256>>>(W_qd, W_qup, W_quq);

        gemm_feat_kernel<<<dim3(BB*PP/64, DD/64), 256>>>(pc, W_self, selfp, BB*PP, DD, b_self, nullptr);
        gemm_feat_kernel<<<dim3(BB*PP/64, DD/64), 256>>>(pc, W_pp,   Yp,    BB*PP, DD, nullptr, rsp);
        gemm_feat_kernel<<<dim3(BB*QQ/64, DD/64), 256>>>(qc, W_self, selfq, BB*QQ, DD, b_self, nullptr);
        gemm_feat_kernel<<<dim3(BB*QQ/64, DD/64), 256>>>(qc, W_qq,   Yq,    BB*QQ, DD, nullptr, rsq);
        gemm_feat_kernel<<<dim3((BB*QNN + 63)/64, DD/64), 256>>>(quc, W_self, selfqu, BB*QNN, DD, b_self, nullptr);

        gemm_adj_kernel<<<dim3(PP/64, DD/64, BB), 256>>>(ppg, Yp, selfp, coefp, nullptr, pn, PP);
        gemm_adj_kernel<<<dim3(QQ/64, DD/64, BB), 256>>>(qqg, Yq, selfq, coefq, vqd,     qn, QQ);
        qu_update_kernel<<<BB*QNN, DD>>>(qun);

        pc = pn; qc = qn; quc = qun;
        pn = pB; qn = qB; qun = quB;
    }

    // output projections
    gemm_feat_kernel<<<dim3(BB*PP/64, HH/64), 256>>>(pc, W_p, out, BB*PP, HH, b_p, nullptr);
    gemm_feat_kernel<<<dim3(BB*QQ/64, HH/64), 256>>>(qc, W_q, out + (size_t)BB*PP*HH, BB*QQ, HH, b_q, nullptr);
    gemm_feat_kernel<<<dim3((BB*QNN + 63)/64, HH/64), 256>>>(quc, W_qu,
        out + (size_t)BB*PP*HH + (size_t)BB*QQ*HH, BB*QNN, HH, b_qu, nullptr);
}

// round 3
// speedup vs baseline: 1.4297x; 1.4297x over previous
#include <cuda_runtime.h>
#include <cuda_bf16.h>
#include <math.h>
#include <stdint.h>

#define BB  4
#define PP  2048
#define QQ  1024
#define QNN 32
#define DD  256
#define HH  128

// ---------------- persistent scratch ----------------
__device__ float g_pA[BB*PP*DD];
__device__ float g_pB[BB*PP*DD];
__device__ float g_qA[BB*QQ*DD];
__device__ float g_qB[BB*QQ*DD];
__device__ float g_quA[BB*QNN*DD];
__device__ float g_quB[BB*QNN*DD];
__device__ float g_selfp[BB*PP*DD];
__device__ float g_selfq[BB*QQ*DD];
__device__ float g_selfqu[BB*QNN*DD];
__device__ __nv_bfloat16 g_Yphi[BB*DD*PP];
__device__ __nv_bfloat16 g_Yplo[BB*DD*PP];
__device__ __nv_bfloat16 g_Yqhi[BB*DD*QQ];
__device__ __nv_bfloat16 g_Yqlo[BB*DD*QQ];
__device__ float g_rsp[BB*PP];
__device__ float g_rsq[BB*QQ];
__device__ float g_coefp[BB*PP];
__device__ float g_coefq[BB*QQ];
__device__ float g_coefqu[BB*QNN];
__device__ float g_sp[BB*DD];
__device__ float g_sq[BB*DD];
__device__ float g_vqd[BB*DD];
__device__ float g_vqup[BB*DD];
__device__ float g_vquq[BB*DD];
__device__ float g_summ[2*BB];

// ---------------- small kernels ----------------
__global__ void zero_s_kernel() {
    int i = blockIdx.x * blockDim.x + threadIdx.x;
    if (i < BB*DD) { g_sp[i] = 0.f; g_sq[i] = 0.f; }
}

__global__ void summask_kernel(const int* __restrict__ pm, const int* __restrict__ qm) {
    int b = blockIdx.x, tid = threadIdx.x;
    __shared__ float red[256];
    float s = 0.f;
    for (int i = tid; i < PP; i += 256) s += (float)pm[b*PP + i];
    red[tid] = s; __syncthreads();
    for (int o = 128; o; o >>= 1) { if (tid < o) red[tid] += red[tid + o]; __syncthreads(); }
    if (tid == 0) g_summ[b] = red[0];
    __syncthreads();
    s = 0.f;
    for (int i = tid; i < QQ; i += 256) s += (float)qm[b*QQ + i];
    red[tid] = s; __syncthreads();
    for (int o = 128; o; o >>= 1) { if (tid < o) red[tid] += red[tid + o]; __syncthreads(); }
    if (tid == 0) g_summ[BB + b] = red[0];
}

__global__ void coefp_kernel(const int* __restrict__ G, const int* __restrict__ pm) {
    int b = blockIdx.y;
    __shared__ float spm[PP];
    int tid = threadIdx.x;
    for (int i = tid; i < PP; i += 256) spm[i] = (float)pm[b*PP + i];
    __syncthreads();
    int warp = tid >> 5, lane = tid & 31;
    int row = blockIdx.x * 8 + warp;
    const int* g = G + ((size_t)b*PP + row) * PP;
    float s = 0.f;
    for (int j = lane; j < PP; j += 32) s += spm[j] * (float)g[j];
    for (int o = 16; o; o >>= 1) s += __shfl_xor_sync(0xffffffffu, s, o);
    if (lane == 0)
        g_coefp[b*PP + row] = pm[b*PP + row] ? 1.f / fmaxf(s, 1.f) : 0.f;
}

__global__ void coefq_kernel(const int* __restrict__ G, const int* __restrict__ qm) {
    int b = blockIdx.y;
    __shared__ float sqm[QQ];
    int tid = threadIdx.x;
    for (int i = tid; i < QQ; i += 256) sqm[i] = (float)qm[b*QQ + i];
    __syncthreads();
    int warp = tid >> 5, lane = tid & 31;
    int row = blockIdx.x * 8 + warp;
    const int* g = G + ((size_t)b*QQ + row) * QQ;
    float s = 0.f;
    for (int j = lane; j < QQ; j += 32) s += sqm[j] * (float)g[j];
    for (int o = 16; o; o >>= 1) s += __shfl_xor_sync(0xffffffffu, s, o);
    if (lane == 0)
        g_coefq[b*QQ + row] = qm[b*QQ + row] ? 1.f / fmaxf(g_summ[b] + s, 1.f) : 0.f;
}

__global__ void coefqu_kernel(const int* __restrict__ qum) {
    int i = blockIdx.x * blockDim.x + threadIdx.x;
    if (i >= BB*QNN) return;
    int b = i / QNN;
    float t = g_summ[b] + g_summ[BB + b];
    g_coefqu[i] = qum[i] ? 1.f / fmaxf(t, 1.f) : 0.f;
}

__global__ void pw_kernel(const float* __restrict__ pcur, const float* __restrict__ qcur,
                          const int* __restrict__ pmask, const int* __restrict__ qmask,
                          const float* __restrict__ Wn, const float* __restrict__ bn) {
    __shared__ float w[DD];
    int tid = threadIdx.x;
    for (int k = tid; k < DD; k += 256) w[k] = Wn[k];
    __syncthreads();
    int warp = tid >> 5, lane = tid & 31;
    int row = blockIdx.x * 8 + warp;
    const float* node; const int* mask; float* out; int idx;
    const int NP = BB*PP;
    if (row < NP) { node = pcur + (size_t)row*DD; mask = pmask; idx = row; out = g_rsp; }
    else {
        int r = row - NP;
        if (r >= BB*QQ) return;
        node = qcur + (size_t)r*DD; mask = qmask; idx = r; out = g_rsq;
    }
    float s = 0.f;
    for (int k = lane; k < DD; k += 32) s += node[k] * w[k];
    for (int o = 16; o; o >>= 1) s += __shfl_xor_sync(0xffffffffu, s, o);
    if (lane == 0) {
        float sig = 1.f / (1.f + expf(-(s + bn[0])));
        out[idx] = mask[idx] ? sig : 0.f;
    }
}

__global__ void s_kernel(const float* __restrict__ pcur, const float* __restrict__ qcur) {
    int b = blockIdx.x;
    int chunk = blockIdx.y;
    int tid = threadIdx.x;
    float acc = 0.f;
    if (chunk < 16) {
        int i0 = chunk * 128;
        for (int i = 0; i < 128; i++) {
            float w = g_rsp[b*PP + i0 + i];
            if (w != 0.f) acc += w * pcur[((size_t)(b*PP + i0 + i))*DD + tid];
        }
        atomicAdd(&g_sp[b*DD + tid], acc);
    } else {
        int i0 = (chunk - 16) * 128;
        for (int i = 0; i < 128; i++) {
            float w = g_rsq[b*QQ + i0 + i];
            if (w != 0.f) acc += w * qcur[((size_t)(b*QQ + i0 + i))*DD + tid];
        }
        atomicAdd(&g_sq[b*DD + tid], acc);
    }
}

__global__ void vec_kernel(const float* __restrict__ Wqd, const float* __restrict__ Wqup,
                           const float* __restrict__ Wquq) {
    int b = blockIdx.x, sel = blockIdx.y, tid = threadIdx.x;
    __shared__ float sh[DD];
    const float* s = (sel == 2) ? g_sq : g_sp;
    const float* W = (sel == 0) ? Wqd : (sel == 1) ? Wqup : Wquq;
    float* out = (sel == 0) ? g_vqd : (sel == 1) ? g_vqup : g_vquq;
    sh[tid] = s[b*DD + tid];
    __syncthreads();
    float acc = 0.f;
    #pragma unroll 8
    for (int k = 0; k < DD; k++) acc += sh[k] * W[(size_t)k*DD + tid];
    out[b*DD + tid] = acc;
}

__global__ void qu_update_kernel(float* __restrict__ qunxt) {
    int r = blockIdx.x;
    int d = threadIdx.x;
    int b = r / QNN;
    float v = g_selfqu[(size_t)r*DD + d] + g_coefqu[r] * (g_vqup[b*DD + d] + g_vquq[b*DD + d]);
    qunxt[(size_t)r*DD + d] = fmaxf(v, 0.f);
}

// ---------------- SIMT GEMM (feature / output projections) ----------------
__global__ __launch_bounds__(256)
void gemm_feat_kernel(const float* __restrict__ A, const float* __restrict__ W,
                      float* __restrict__ C, int Mrows, int N,
                      const float* __restrict__ bias) {
    __shared__ float As[16][68];
    __shared__ float Bs[16][64];
    int bm = blockIdx.x * 64, bn = blockIdx.y * 64;
    int tid = threadIdx.x;
    int tx = tid & 15, ty = tid >> 4;
    int arow = tid >> 4, ak = tid & 15;
    int bk = tid >> 6, bnl = tid & 63;
    float acc[4][4] = {};
    for (int k0 = 0; k0 < DD; k0 += 16) {
        #pragma unroll
        for (int p2 = 0; p2 < 4; p2++) {
            int r = arow + p2*16;
            int row = bm + r;
            As[ak][r] = (row < Mrows) ? A[(size_t)row*DD + k0 + ak] : 0.f;
        }
        #pragma unroll
        for (int p2 = 0; p2 < 4; p2++) {
            int kk = bk + p2*4;
            Bs[kk][bnl] = W[(size_t)(k0 + kk)*N + bn + bnl];
        }
        __syncthreads();
        #pragma unroll
        for (int kk = 0; kk < 16; kk++) {
            float ar[4], br[4];
            #pragma unroll
            for (int i = 0; i < 4; i++) ar[i] = As[kk][ty*4 + i];
            #pragma unroll
            for (int j = 0; j < 4; j++) br[j] = Bs[kk][tx*4 + j];
            #pragma unroll
            for (int i = 0; i < 4; i++)
                #pragma unroll
                for (int j = 0; j < 4; j++) acc[i][j] += ar[i] * br[j];
        }
        __syncthreads();
    }
    #pragma unroll
    for (int i = 0; i < 4; i++) {
        int row = bm + ty*4 + i;
        if (row >= Mrows) continue;
        #pragma unroll
        for (int j = 0; j < 4; j++) {
            int n = bn + tx*4 + j;
            C[(size_t)row*N + n] = acc[i][j] + (bias ? bias[n] : 0.f);
        }
    }
}

// V = rowscale[row] * (A @ W); write transposed hi/lo bf16 Yt[b][d][i]
__global__ __launch_bounds__(256)
void gemm_feat_t_kernel(const float* __restrict__ A, const float* __restrict__ W,
                        int NN, const float* __restrict__ rowscale,
                        __nv_bfloat16* __restrict__ Yhi, __nv_bfloat16* __restrict__ Ylo) {
    __shared__ float As[16][68];
    __shared__ float Bs[16][64];
    __shared__ float T[64][65];
    int bm = blockIdx.x * 64, bn = blockIdx.y * 64;
    int tid = threadIdx.x;
    int tx = tid & 15, ty = tid >> 4;
    int arow = tid >> 4, ak = tid & 15;
    int bk = tid >> 6, bnl = tid & 63;
    float acc[4][4] = {};
    for (int k0 = 0; k0 < DD; k0 += 16) {
        #pragma unroll
        for (int p2 = 0; p2 < 4; p2++) {
            int r = arow + p2*16;
            As[ak][r] = A[(size_t)(bm + r)*DD + k0 + ak];
        }
        #pragma unroll
        for (int p2 = 0; p2 < 4; p2++) {
            int kk = bk + p2*4;
            Bs[kk][bnl] = W[(size_t)(k0 + kk)*DD + bn + bnl];
        }
        __syncthreads();
        #pragma unroll
        for (int kk = 0; kk < 16; kk++) {
            float ar[4], br[4];
            #pragma unroll
            for (int i = 0; i < 4; i++) ar[i] = As[kk][ty*4 + i];
            #pragma unroll
            for (int j = 0; j < 4; j++) br[j] = Bs[kk][tx*4 + j];
            #pragma unroll
            for (int i = 0; i < 4; i++)
                #pragma unroll
                for (int j = 0; j < 4; j++) acc[i][j] += ar[i] * br[j];
        }
        __syncthreads();
    }
    #pragma unroll
    for (int i = 0; i < 4; i++) {
        int row = bm + ty*4 + i;
        float rs = rowscale[row];
        #pragma unroll
        for (int j = 0; j < 4; j++)
            T[tx*4 + j][ty*4 + i] = acc[i][j] * rs;
    }
    __syncthreads();
    for (int e = tid; e < 4096; e += 256) {
        int nl = e >> 6, rl = e & 63;
        float v = T[nl][rl];
        __nv_bfloat16 h = __float2bfloat16(v);
        float vl = v - __bfloat162float(h);
        __nv_bfloat16 l = __float2bfloat16(vl);
        int grow = bm + rl;
        int b = grow / NN;
        int i = grow - b * NN;
        size_t idx = ((size_t)b*DD + bn + nl) * NN + i;
        Yhi[idx] = h;
        Ylo[idx] = l;
    }
}

// ---------------- HMMA (mma.sync bf16) adjacency aggregation ----------------
// O[b,i,:] = relu(S[b,i,:] + coef[b,i]*(sum_j G[b,i,j]*(Yhi+Ylo)[:,j] + ev))
// CTA tile: M=64 (G rows) x N=256 (full D). K chunk = 32. 8 warps: 2(M) x 4(N).
#define KC 32
#define KCP 40   // padded k stride (bf16 elems) -> 80B rows, conflict-free frags

__device__ __forceinline__ void mma_bf16(float c[4], uint32_t a0, uint32_t a1,
                                         uint32_t a2, uint32_t a3,
                                         uint32_t b0, uint32_t b1) {
    asm volatile(
        "mma.sync.aligned.m16n8k16.row.col.f32.bf16.bf16.f32 "
        "{%0,%1,%2,%3}, {%4,%5,%6,%7}, {%8,%9}, {%0,%1,%2,%3};"
        : "+f"(c[0]), "+f"(c[1]), "+f"(c[2]), "+f"(c[3])
        : "r"(a0), "r"(a1), "r"(a2), "r"(a3), "r"(b0), "r"(b1));
}

__global__ __launch_bounds__(256)
void adj_hmma_kernel(const int* __restrict__ Gp, const int* __restrict__ Gq,
                     const __nv_bfloat16* __restrict__ Yphi, const __nv_bfloat16* __restrict__ Yplo,
                     const __nv_bfloat16* __restrict__ Yqhi, const __nv_bfloat16* __restrict__ Yqlo,
                     const float* __restrict__ selfp, const float* __restrict__ selfq,
                     const float* __restrict__ coefp, const float* __restrict__ coefq,
                     const float* __restrict__ vqd,
                     float* __restrict__ Op, float* __restrict__ Oq) {
    __shared__ __nv_bfloat16 As[64 * KCP];
    __shared__ __nv_bfloat16 Bh[256 * KCP];
    __shared__ __nv_bfloat16 Bl[256 * KCP];

    int bx = blockIdx.x;
    const int* G; const __nv_bfloat16 *Yh, *Yl; const float *S, *coef, *ev;
    float* O; int NN, b, mtile;
    if (bx < BB * (PP/64)) {
        b = bx >> 5; mtile = bx & 31; NN = PP;
        G = Gp + (size_t)b*PP*PP;
        Yh = Yphi + (size_t)b*DD*PP;  Yl = Yplo + (size_t)b*DD*PP;
        S = selfp + (size_t)b*PP*DD;  coef = coefp + b*PP;
        ev = nullptr;                 O = Op + (size_t)b*PP*DD;
    } else {
        int i2 = bx - BB * (PP/64);
        b = i2 >> 4; mtile = i2 & 15; NN = QQ;
        G = Gq + (size_t)b*QQ*QQ;
        Yh = Yqhi + (size_t)b*DD*QQ;  Yl = Yqlo + (size_t)b*DD*QQ;
        S = selfq + (size_t)b*QQ*DD;  coef = coefq + b*QQ;
        ev = vqd + b*DD;              O = Oq + (size_t)b*QQ*DD;
    }
    int bm = mtile * 64;
    int tid = threadIdx.x, wid = tid >> 5, lane = tid & 31;
    int wm = wid >> 2;            // 0..1  (M groups of 32)
    int wn = wid & 3;             // 0..3  (N groups of 64)

    float c[2][8][4];
    #pragma unroll
    for (int mt = 0; mt < 2; mt++)
        #pragma unroll
        for (int nt = 0; nt < 8; nt++)
            #pragma unroll
            for (int r = 0; r < 4; r++) c[mt][nt][r] = 0.f;

    const int nchunks = NN / KC;
    for (int ch = 0; ch < nchunks; ch++) {
        int k0 = ch * KC;
        // A: G tile [64 x 32] int32 -> bf16
        const int* gsrc = G + (size_t)bm * NN + k0;
        #pragma unroll
        for (int it = 0; it < 2; it++) {
            int idx = tid + it * 256;          // 0..511
            int row = idx >> 3, c4 = idx & 7;  // 8 x uint4 per row
            uint4 v = *(const uint4*)(gsrc + (size_t)row * NN + c4 * 4);
            uint32_t lo32 = (v.x ? 0x3F80u : 0u) | ((v.y ? 0x3F80u : 0u) << 16);
            uint32_t hi32 = (v.z ? 0x3F80u : 0u) | ((v.w ? 0x3F80u : 0u) << 16);
            *(uint2*)(As + row * KCP + c4 * 4) = make_uint2(lo32, hi32);
        }
        // B: Yt hi/lo tiles [256 x 32] bf16
        #pragma unroll
        for (int it = 0; it < 4; it++) {
            int idx = tid + it * 256;          // 0..1023
            int d = idx >> 2, c8 = idx & 3;    // 4 x uint4(8 bf16) per row
            size_t src = (size_t)d * NN + k0 + c8 * 8;
            *(uint4*)(Bh + d * KCP + c8 * 8) = *(const uint4*)(Yh + src);
            *(uint4*)(Bl + d * KCP + c8 * 8) = *(const uint4*)(Yl + src);
        }
        __syncthreads();
        #pragma unroll
        for (int kt = 0; kt < 2; kt++) {
            int gk = kt * 16 + (lane & 3) * 2;
            int r0 = lane >> 2;
            uint32_t a[2][4];
            #pragma unroll
            for (int mt = 0; mt < 2; mt++) {
                int mrow = wm * 32 + mt * 16 + r0;
                a[mt][0] = *(const uint32_t*)(As + mrow * KCP + gk);
                a[mt][1] = *(const uint32_t*)(As + (mrow + 8) * KCP + gk);
                a[mt][2] = *(const uint32_t*)(As + mrow * KCP + gk + 8);
                a[mt][3] = *(const uint32_t*)(As + (mrow + 8) * KCP + gk + 8);
            }
            #pragma unroll
            for (int nt = 0; nt < 8; nt++) {
                int n = wn * 64 + nt * 8 + r0;
                uint32_t bh0 = *(const uint32_t*)(Bh + n * KCP + gk);
                uint32_t bh1 = *(const uint32_t*)(Bh + n * KCP + gk + 8);
                uint32_t bl0 = *(const uint32_t*)(Bl + n * KCP + gk);
                uint32_t bl1 = *(const uint32_t*)(Bl + n * KCP + gk + 8);
                mma_bf16(c[0][nt], a[0][0], a[0][1], a[0][2], a[0][3], bh0, bh1);
                mma_bf16(c[1][nt], a[1][0], a[1][1], a[1][2], a[1][3], bh0, bh1);
                mma_bf16(c[0][nt], a[0][0], a[0][1], a[0][2], a[0][3], bl0, bl1);
                mma_bf16(c[1][nt], a[1][0], a[1][1], a[1][2], a[1][3], bl0, bl1);
            }
        }
        __syncthreads();
    }

    // epilogue: c[mt][nt][{c0,c1 @ row, c2,c3 @ row+8}], cols (lane&3)*2 + {0,1}
    #pragma unroll
    for (int mt = 0; mt < 2; mt++) {
        #pragma unroll
        for (int h = 0; h < 2; h++) {
            int row = bm + wm * 32 + mt * 16 + (lane >> 2) + h * 8;
            float cf = coef[row];
            const float* srow = S + (size_t)row * DD;
            float* orow = O + (size_t)row * DD;
            #pragma unroll
            for (int nt = 0; nt < 8; nt++) {
                int col = wn * 64 + nt * 8 + (lane & 3) * 2;
                float v0 = c[mt][nt][h * 2 + 0];
                float v1 = c[mt][nt][h * 2 + 1];
                if (ev) { v0 += ev[col]; v1 += ev[col + 1]; }
                float2 s2 = *(const float2*)(srow + col);
                float2 o;
                o.x = fmaxf(s2.x + cf * v0, 0.f);
                o.y = fmaxf(s2.y + cf * v1, 0.f);
                *(float2*)(orow + col) = o;
            }
        }
    }
}

// ---------------- launch ----------------
extern "C" void kernel_launch(void* const* d_in, const int* in_sizes, int n_in,
                              void* d_out, int out_size) {
    const float* p_in   = (const float*)d_in[0];
    const float* q_in   = (const float*)d_in[1];
    const float* qu_in  = (const float*)d_in[2];
    const int*   pmask  = (const int*)d_in[3];
    const int*   qmask  = (const int*)d_in[4];
    const int*   qumask = (const int*)d_in[5];
    const int*   ppg    = (const int*)d_in[6];
    const int*   qqg    = (const int*)d_in[7];
    const float* W_node = (const float*)d_in[10];
    const float* b_node = (const float*)d_in[11];
    const float* W_self = (const float*)d_in[12];
    const float* b_self = (const float*)d_in[13];
    const float* W_pp   = (const float*)d_in[14];
    const float* W_qd   = (const float*)d_in[15];
    const float* W_qq   = (const float*)d_in[16];
    const float* W_qup  = (const float*)d_in[17];
    const float* W_quq  = (const float*)d_in[18];
    const float* W_p    = (const float*)d_in[19];
    const float* b_p    = (const float*)d_in[20];
    const float* W_q    = (const float*)d_in[21];
    const float* b_q    = (const float*)d_in[22];
    const float* W_qu   = (const float*)d_in[23];
    const float* b_qu   = (const float*)d_in[24];
    float* out = (float*)d_out;

    float *pA, *pB, *qA, *qB, *quA, *quB, *selfp, *selfq, *selfqu;
    float *rsp, *rsq, *coefp, *coefq, *vqd;
    __nv_bfloat16 *Yphi, *Yplo, *Yqhi, *Yqlo;
    cudaGetSymbolAddress((void**)&pA, g_pA);
    cudaGetSymbolAddress((void**)&pB, g_pB);
    cudaGetSymbolAddress((void**)&qA, g_qA);
    cudaGetSymbolAddress((void**)&qB, g_qB);
    cudaGetSymbolAddress((void**)&quA, g_quA);
    cudaGetSymbolAddress((void**)&quB, g_quB);
    cudaGetSymbolAddress((void**)&selfp, g_selfp);
    cudaGetSymbolAddress((void**)&selfq, g_selfq);
    cudaGetSymbolAddress((void**)&selfqu, g_selfqu);
    cudaGetSymbolAddress((void**)&rsp, g_rsp);
    cudaGetSymbolAddress((void**)&rsq, g_rsq);
    cudaGetSymbolAddress((void**)&coefp, g_coefp);
    cudaGetSymbolAddress((void**)&coefq, g_coefq);
    cudaGetSymbolAddress((void**)&vqd, g_vqd);
    cudaGetSymbolAddress((void**)&Yphi, g_Yphi);
    cudaGetSymbolAddress((void**)&Yplo, g_Yplo);
    cudaGetSymbolAddress((void**)&Yqhi, g_Yqhi);
    cudaGetSymbolAddress((void**)&Yqlo, g_Yqlo);

    // step-invariant mask coefficients
    summask_kernel<<<BB, 256>>>(pmask, qmask);
    coefp_kernel<<<dim3(PP/8, BB), 256>>>(ppg, pmask);
    coefq_kernel<<<dim3(QQ/8, BB), 256>>>(qqg, qmask);
    coefqu_kernel<<<1, 128>>>(qumask);

    const float* pc = p_in;  const float* qc = q_in;  const float* quc = qu_in;
    float* pn = pA;  float* qn = qA;  float* qun = quA;

    for (int step = 0; step < 2; step++) {
        zero_s_kernel<<<4, 256>>>();
        pw_kernel<<<(BB*PP + BB*QQ)/8, 256>>>(pc, qc, pmask, qmask, W_node, b_node);
        s_kernel<<<dim3(BB, 24), 256>>>(pc, qc);
        vec_kernel<<<dim3(BB, 3), 256>>>(W_qd, W_qup, W_quq);

        gemm_feat_kernel<<<dim3(BB*PP/64, DD/64), 256>>>(pc, W_self, selfp, BB*PP, DD, b_self);
        gemm_feat_kernel<<<dim3(BB*QQ/64, DD/64), 256>>>(qc, W_self, selfq, BB*QQ, DD, b_self);
        gemm_feat_kernel<<<dim3((BB*QNN + 63)/64, DD/64), 256>>>(quc, W_self, selfqu, BB*QNN, DD, b_self);
        gemm_feat_t_kernel<<<dim3(BB*PP/64, DD/64), 256>>>(pc, W_pp, PP, rsp, Yphi, Yplo);
        gemm_feat_t_kernel<<<dim3(BB*QQ/64, DD/64), 256>>>(qc, W_qq, QQ, rsq, Yqhi, Yqlo);

        adj_hmma_kernel<<<BB*(PP/64) + BB*(QQ/64), 256>>>(ppg, qqg, Yphi, Yplo, Yqhi, Yqlo,
                                                          selfp, selfq, coefp, coefq, vqd, pn, qn);
        qu_update_kernel<<<BB*QNN, DD>>>(qun);

        pc = pn; qc = qn; quc = qun;
        pn = pB; qn = qB; qun = quB;
    }

    gemm_feat_kernel<<<dim3(BB*PP/64, HH/64), 256>>>(pc, W_p, out, BB*PP, HH, b_p);
    gemm_feat_kernel<<<dim3(BB*QQ/64, HH/64), 256>>>(qc, W_q, out + (size_t)BB*PP*HH, BB*QQ, HH, b_q);
    gemm_feat_kernel<<<dim3((BB*QNN + 63)/64, HH/64), 256>>>(quc, W_qu,
        out + (size_t)BB*PP*HH + (size_t)BB*QQ*HH, BB*QNN, HH, b_qu);
}

// round 5
// speedup vs baseline: 1.5880x; 1.1108x over previous
#include <cuda_runtime.h>
#include <cuda_bf16.h>
#include <math.h>
#include <stdint.h>

#define BB  4
#define PP  2048
#define QQ  1024
#define QNN 32
#define DD  256
#define HH  128

// ---------------- persistent scratch ----------------
__device__ float g_pA[BB*PP*DD];
__device__ float g_pB[BB*PP*DD];
__device__ float g_qA[BB*QQ*DD];
__device__ float g_qB[BB*QQ*DD];
__device__ float g_quA[BB*QNN*DD];
__device__ float g_quB[BB*QNN*DD];
__device__ float g_selfp[BB*PP*DD];
__device__ float g_selfq[BB*QQ*DD];
__device__ float g_selfqu[BB*QNN*DD];
__device__ __nv_bfloat16 g_Yphi[BB*DD*PP];
__device__ __nv_bfloat16 g_Yplo[BB*DD*PP];
__device__ __nv_bfloat16 g_Yqhi[BB*DD*QQ];
__device__ __nv_bfloat16 g_Yqlo[BB*DD*QQ];
// transposed hi/lo weights: [N,256] each; offsets below
__device__ __nv_bfloat16 g_Wth[294912];
__device__ __nv_bfloat16 g_Wtl[294912];
#define OFF_SELF 0
#define OFF_PPW  65536
#define OFF_QQW  131072
#define OFF_PW   196608
#define OFF_QW   229376
#define OFF_QUW  262144
__device__ float g_rsp[BB*PP];
__device__ float g_rsq[BB*QQ];
__device__ float g_coefp[BB*PP];
__device__ float g_coefq[BB*QQ];
__device__ float g_coefqu[BB*QNN];
__device__ float g_sp[BB*DD];
__device__ float g_sq[BB*DD];
__device__ float g_vqd[BB*DD];
__device__ float g_vqup[BB*DD];
__device__ float g_vquq[BB*DD];
__device__ float g_summ[2*BB];

// ---------------- small kernels ----------------
__global__ void zero_s_kernel() {
    int i = blockIdx.x * blockDim.x + threadIdx.x;
    if (i < BB*DD) { g_sp[i] = 0.f; g_sq[i] = 0.f; }
}

__global__ void summask_kernel(const int* __restrict__ pm, const int* __restrict__ qm) {
    int b = blockIdx.x, tid = threadIdx.x;
    __shared__ float red[256];
    float s = 0.f;
    for (int i = tid; i < PP; i += 256) s += (float)pm[b*PP + i];
    red[tid] = s; __syncthreads();
    for (int o = 128; o; o >>= 1) { if (tid < o) red[tid] += red[tid + o]; __syncthreads(); }
    if (tid == 0) g_summ[b] = red[0];
    __syncthreads();
    s = 0.f;
    for (int i = tid; i < QQ; i += 256) s += (float)qm[b*QQ + i];
    red[tid] = s; __syncthreads();
    for (int o = 128; o; o >>= 1) { if (tid < o) red[tid] += red[tid + o]; __syncthreads(); }
    if (tid == 0) g_summ[BB + b] = red[0];
}

__global__ void coefp_kernel(const int* __restrict__ G, const int* __restrict__ pm) {
    int b = blockIdx.y;
    __shared__ float spm[PP];
    int tid = threadIdx.x;
    for (int i = tid; i < PP; i += 256) spm[i] = (float)pm[b*PP + i];
    __syncthreads();
    int warp = tid >> 5, lane = tid & 31;
    int row = blockIdx.x * 8 + warp;
    const int* g = G + ((size_t)b*PP + row) * PP;
    float s = 0.f;
    for (int j = lane; j < PP; j += 32) s += spm[j] * (float)g[j];
    for (int o = 16; o; o >>= 1) s += __shfl_xor_sync(0xffffffffu, s, o);
    if (lane == 0)
        g_coefp[b*PP + row] = pm[b*PP + row] ? 1.f / fmaxf(s, 1.f) : 0.f;
}

__global__ void coefq_kernel(const int* __restrict__ G, const int* __restrict__ qm) {
    int b = blockIdx.y;
    __shared__ float sqm[QQ];
    int tid = threadIdx.x;
    for (int i = tid; i < QQ; i += 256) sqm[i] = (float)qm[b*QQ + i];
    __syncthreads();
    int warp = tid >> 5, lane = tid & 31;
    int row = blockIdx.x * 8 + warp;
    const int* g = G + ((size_t)b*QQ + row) * QQ;
    float s = 0.f;
    for (int j = lane; j < QQ; j += 32) s += sqm[j] * (float)g[j];
    for (int o = 16; o; o >>= 1) s += __shfl_xor_sync(0xffffffffu, s, o);
    if (lane == 0)
        g_coefq[b*QQ + row] = qm[b*QQ + row] ? 1.f / fmaxf(g_summ[b] + s, 1.f) : 0.f;
}

__global__ void coefqu_kernel(const int* __restrict__ qum) {
    int i = blockIdx.x * blockDim.x + threadIdx.x;
    if (i >= BB*QNN) return;
    int b = i / QNN;
    float t = g_summ[b] + g_summ[BB + b];
    g_coefqu[i] = qum[i] ? 1.f / fmaxf(t, 1.f) : 0.f;
}

__global__ void pw_kernel(const float* __restrict__ pcur, const float* __restrict__ qcur,
                          const int* __restrict__ pmask, const int* __restrict__ qmask,
                          const float* __restrict__ Wn, const float* __restrict__ bn) {
    __shared__ float w[DD];
    int tid = threadIdx.x;
    for (int k = tid; k < DD; k += 256) w[k] = Wn[k];
    __syncthreads();
    int warp = tid >> 5, lane = tid & 31;
    int row = blockIdx.x * 8 + warp;
    const float* node; const int* mask; float* out; int idx;
    const int NP = BB*PP;
    if (row < NP) { node = pcur + (size_t)row*DD; mask = pmask; idx = row; out = g_rsp; }
    else {
        int r = row - NP;
        if (r >= BB*QQ) return;
        node = qcur + (size_t)r*DD; mask = qmask; idx = r; out = g_rsq;
    }
    float s = 0.f;
    for (int k = lane; k < DD; k += 32) s += node[k] * w[k];
    for (int o = 16; o; o >>= 1) s += __shfl_xor_sync(0xffffffffu, s, o);
    if (lane == 0) {
        float sig = 1.f / (1.f + expf(-(s + bn[0])));
        out[idx] = mask[idx] ? sig : 0.f;
    }
}

__global__ void s_kernel(const float* __restrict__ pcur, const float* __restrict__ qcur) {
    int b = blockIdx.x;
    int chunk = blockIdx.y;
    int tid = threadIdx.x;
    float acc = 0.f;
    if (chunk < 16) {
        int i0 = chunk * 128;
        for (int i = 0; i < 128; i++) {
            float w = g_rsp[b*PP + i0 + i];
            if (w != 0.f) acc += w * pcur[((size_t)(b*PP + i0 + i))*DD + tid];
        }
        atomicAdd(&g_sp[b*DD + tid], acc);
    } else {
        int i0 = (chunk - 16) * 128;
        for (int i = 0; i < 128; i++) {
            float w = g_rsq[b*QQ + i0 + i];
            if (w != 0.f) acc += w * qcur[((size_t)(b*QQ + i0 + i))*DD + tid];
        }
        atomicAdd(&g_sq[b*DD + tid], acc);
    }
}

__global__ void vec_kernel(const float* __restrict__ Wqd, const float* __restrict__ Wqup,
                           const float* __restrict__ Wquq) {
    int b = blockIdx.x, sel = blockIdx.y, tid = threadIdx.x;
    __shared__ float sh[DD];
    const float* s = (sel == 2) ? g_sq : g_sp;
    const float* W = (sel == 0) ? Wqd : (sel == 1) ? Wqup : Wquq;
    float* out = (sel == 0) ? g_vqd : (sel == 1) ? g_vqup : g_vquq;
    sh[tid] = s[b*DD + tid];
    __syncthreads();
    float acc = 0.f;
    #pragma unroll 8
    for (int k = 0; k < DD; k++) acc += sh[k] * W[(size_t)k*DD + tid];
    out[b*DD + tid] = acc;
}

__global__ void qu_update_kernel(float* __restrict__ qunxt) {
    int r = blockIdx.x;
    int d = threadIdx.x;
    int b = r / QNN;
    float v = g_selfqu[(size_t)r*DD + d] + g_coefqu[r] * (g_vqup[b*DD + d] + g_vquq[b*DD + d]);
    qunxt[(size_t)r*DD + d] = fmaxf(v, 0.f);
}

// ---------------- weight transpose + hi/lo split (once per call) ----------------
// W[K=256, N] fp32 -> Wt hi/lo [N, 256] bf16
__global__ void wsplit_kernel(const float* __restrict__ W, int N,
                              __nv_bfloat16* __restrict__ Wth, __nv_bfloat16* __restrict__ Wtl) {
    __shared__ float T[32][33];
    int nb = blockIdx.x * 32, kb = blockIdx.y * 32;
    int tx = threadIdx.x, ty = threadIdx.y;  // 32 x 8
    #pragma unroll
    for (int r = 0; r < 32; r += 8)
        T[ty + r][tx] = W[(size_t)(kb + ty + r) * N + nb + tx];
    __syncthreads();
    #pragma unroll
    for (int r = 0; r < 32; r += 8) {
        int n = nb + ty + r, k = kb + tx;
        float v = T[tx][ty + r];
        __nv_bfloat16 h = __float2bfloat16(v);
        Wth[(size_t)n * 256 + k] = h;
        Wtl[(size_t)n * 256 + k] = __float2bfloat16(v - __bfloat162float(h));
    }
}

// ---------------- mma.sync helpers ----------------
__device__ __forceinline__ void mma_bf16(float c[4], uint32_t a0, uint32_t a1,
                                         uint32_t a2, uint32_t a3,
                                         uint32_t b0, uint32_t b1) {
    asm volatile(
        "mma.sync.aligned.m16n8k16.row.col.f32.bf16.bf16.f32 "
        "{%0,%1,%2,%3}, {%4,%5,%6,%7}, {%8,%9}, {%0,%1,%2,%3};"
        : "+f"(c[0]), "+f"(c[1]), "+f"(c[2]), "+f"(c[3])
        : "r"(a0), "r"(a1), "r"(a2), "r"(a3), "r"(b0), "r"(b1));
}

__device__ __forceinline__ void split_pack2(float x, float y, uint32_t& h, uint32_t& l) {
    __nv_bfloat16 hx = __float2bfloat16(x), hy = __float2bfloat16(y);
    float rx = x - __bfloat162float(hx), ry = y - __bfloat162float(hy);
    __nv_bfloat16 lx = __float2bfloat16(rx), ly = __float2bfloat16(ry);
    h = (uint32_t)__bfloat16_as_ushort(hy) << 16 | __bfloat16_as_ushort(hx);
    l = (uint32_t)__bfloat16_as_ushort(ly) << 16 | __bfloat16_as_ushort(lx);
}

// ---------------- HMMA feature GEMM: C[M,N] = A[M,256] @ Wt^T ----------------
// 3-product hi/lo split. CTA tile 128x128, K chunk 32, 8 warps (4M x 2N).
// Epilogue: Cout? C+bias : Yt hi/lo transposed write (rowscale applied).
#define KC2 32
#define KCP2 40

__global__ __launch_bounds__(256)
void gemm_mma_kernel(const float* __restrict__ A,
                     const __nv_bfloat16* __restrict__ Wth,
                     const __nv_bfloat16* __restrict__ Wtl,
                     int N, float* __restrict__ Cout, const float* __restrict__ bias,
                     const float* __restrict__ rowscale,
                     __nv_bfloat16* __restrict__ Yhi, __nv_bfloat16* __restrict__ Ylo,
                     int NNbatch) {
    __shared__ __nv_bfloat16 Ah[128 * KCP2];
    __shared__ __nv_bfloat16 Al[128 * KCP2];
    __shared__ __nv_bfloat16 Wh[128 * KCP2];
    __shared__ __nv_bfloat16 Wl[128 * KCP2];

    int bm = blockIdx.x * 128, bn = blockIdx.y * 128;
    int tid = threadIdx.x, wid = tid >> 5, lane = tid & 31;
    int wm = wid >> 1, wn = wid & 1;

    float c[2][8][4];
    #pragma unroll
    for (int mt = 0; mt < 2; mt++)
        #pragma unroll
        for (int nt = 0; nt < 8; nt++)
            #pragma unroll
            for (int r = 0; r < 4; r++) c[mt][nt][r] = 0.f;

    for (int ch = 0; ch < 8; ch++) {
        int k0 = ch * KC2;
        // A: [128 x 32] fp32 -> hi/lo bf16
        #pragma unroll
        for (int it = 0; it < 4; it++) {
            int u = tid + it * 256;            // 0..1023 float4-units
            int row = u >> 3, c4 = u & 7;
            float4 v = *(const float4*)(A + (size_t)(bm + row) * DD + k0 + c4 * 4);
            uint32_t h0, l0, h1, l1;
            split_pack2(v.x, v.y, h0, l0);
            split_pack2(v.z, v.w, h1, l1);
            *(uint2*)(Ah + row * KCP2 + c4 * 4) = make_uint2(h0, h1);
            *(uint2*)(Al + row * KCP2 + c4 * 4) = make_uint2(l0, l1);
        }
        // W: [128 x 32] bf16 hi/lo (pre-transposed [N,256])
        #pragma unroll
        for (int it = 0; it < 2; it++) {
            int u = tid + it * 256;            // 0..511 uint4-units
            int n = u >> 2, c8 = u & 3;
            size_t src = (size_t)(bn + n) * 256 + k0 + c8 * 8;
            *(uint4*)(Wh + n * KCP2 + c8 * 8) = *(const uint4*)(Wth + src);
            *(uint4*)(Wl + n * KCP2 + c8 * 8) = *(const uint4*)(Wtl + src);
        }
        __syncthreads();
        #pragma unroll
        for (int kt = 0; kt < 2; kt++) {
            int gk = kt * 16 + (lane & 3) * 2;
            int r0 = lane >> 2;
            uint32_t ah[2][4], al[2][4];
            #pragma unroll
            for (int mt = 0; mt < 2; mt++) {
                int mrow = wm * 32 + mt * 16 + r0;
                ah[mt][0] = *(const uint32_t*)(Ah + mrow * KCP2 + gk);
                ah[mt][1] = *(const uint32_t*)(Ah + (mrow + 8) * KCP2 + gk);
                ah[mt][2] = *(const uint32_t*)(Ah + mrow * KCP2 + gk + 8);
                ah[mt][3] = *(const uint32_t*)(Ah + (mrow + 8) * KCP2 + gk + 8);
                al[mt][0] = *(const uint32_t*)(Al + mrow * KCP2 + gk);
                al[mt][1] = *(const uint32_t*)(Al + (mrow + 8) * KCP2 + gk);
                al[mt][2] = *(const uint32_t*)(Al + mrow * KCP2 + gk + 8);
                al[mt][3] = *(const uint32_t*)(Al + (mrow + 8) * KCP2 + gk + 8);
            }
            #pragma unroll
            for (int nt = 0; nt < 8; nt++) {
                int n = wn * 64 + nt * 8 + r0;
                uint32_t wh0 = *(const uint32_t*)(Wh + n * KCP2 + gk);
                uint32_t wh1 = *(const uint32_t*)(Wh + n * KCP2 + gk + 8);
                uint32_t wl0 = *(const uint32_t*)(Wl + n * KCP2 + gk);
                uint32_t wl1 = *(const uint32_t*)(Wl + n * KCP2 + gk + 8);
                #pragma unroll
                for (int mt = 0; mt < 2; mt++) {
                    mma_bf16(c[mt][nt], ah[mt][0], ah[mt][1], ah[mt][2], ah[mt][3], wh0, wh1);
                    mma_bf16(c[mt][nt], al[mt][0], al[mt][1], al[mt][2], al[mt][3], wh0, wh1);
                    mma_bf16(c[mt][nt], ah[mt][0], ah[mt][1], ah[mt][2], ah[mt][3], wl0, wl1);
                }
            }
        }
        __syncthreads();
    }

    // epilogue
    if (Cout) {
        #pragma unroll
        for (int mt = 0; mt < 2; mt++)
            #pragma unroll
            for (int h = 0; h < 2; h++) {
                int row = bm + wm * 32 + mt * 16 + (lane >> 2) + h * 8;
                float* orow = Cout + (size_t)row * N;
                #pragma unroll
                for (int nt = 0; nt < 8; nt++) {
                    int col = bn + wn * 64 + nt * 8 + (lane & 3) * 2;
                    float2 o;
                    o.x = c[mt][nt][h * 2 + 0] + bias[col];
                    o.y = c[mt][nt][h * 2 + 1] + bias[col + 1];
                    *(float2*)(orow + col) = o;
                }
            }
    } else {
        #pragma unroll
        for (int mt = 0; mt < 2; mt++)
            #pragma unroll
            for (int h = 0; h < 2; h++) {
                int gr = bm + wm * 32 + mt * 16 + (lane >> 2) + h * 8;
                float rs = rowscale[gr];
                int b = gr / NNbatch;
                int i = gr - b * NNbatch;
                #pragma unroll
                for (int nt = 0; nt < 8; nt++) {
                    int col = bn + wn * 64 + nt * 8 + (lane & 3) * 2;
                    size_t base = ((size_t)b * DD + col) * NNbatch + i;
                    float v0 = c[mt][nt][h * 2 + 0] * rs;
                    float v1 = c[mt][nt][h * 2 + 1] * rs;
                    __nv_bfloat16 h0 = __float2bfloat16(v0);
                    __nv_bfloat16 h1 = __float2bfloat16(v1);
                    Yhi[base] = h0;
                    Yhi[base + NNbatch] = h1;
                    Ylo[base] = __float2bfloat16(v0 - __bfloat162float(h0));
                    Ylo[base + NNbatch] = __float2bfloat16(v1 - __bfloat162float(h1));
                }
            }
    }
}

// ---------------- HMMA adjacency aggregation (unchanged, validated) ----------------
#define KC 32
#define KCP 40

__global__ __launch_bounds__(256)
void adj_hmma_kernel(const int* __restrict__ Gp, const int* __restrict__ Gq,
                     const __nv_bfloat16* __restrict__ Yphi, const __nv_bfloat16* __restrict__ Yplo,
                     const __nv_bfloat16* __restrict__ Yqhi, const __nv_bfloat16* __restrict__ Yqlo,
                     const float* __restrict__ selfp, const float* __restrict__ selfq,
                     const float* __restrict__ coefp, const float* __restrict__ coefq,
                     const float* __restrict__ vqd,
                     float* __restrict__ Op, float* __restrict__ Oq) {
    __shared__ __nv_bfloat16 As[64 * KCP];
    __shared__ __nv_bfloat16 Bh[256 * KCP];
    __shared__ __nv_bfloat16 Bl[256 * KCP];

    int bx = blockIdx.x;
    const int* G; const __nv_bfloat16 *Yh, *Yl; const float *S, *coef, *ev;
    float* O; int NN, b, mtile;
    if (bx < BB * (PP/64)) {
        b = bx >> 5; mtile = bx & 31; NN = PP;
        G = Gp + (size_t)b*PP*PP;
        Yh = Yphi + (size_t)b*DD*PP;  Yl = Yplo + (size_t)b*DD*PP;
        S = selfp + (size_t)b*PP*DD;  coef = coefp + b*PP;
        ev = nullptr;                 O = Op + (size_t)b*PP*DD;
    } else {
        int i2 = bx - BB * (PP/64);
        b = i2 >> 4; mtile = i2 & 15; NN = QQ;
        G = Gq + (size_t)b*QQ*QQ;
        Yh = Yqhi + (size_t)b*DD*QQ;  Yl = Yqlo + (size_t)b*DD*QQ;
        S = selfq + (size_t)b*QQ*DD;  coef = coefq + b*QQ;
        ev = vqd + b*DD;              O = Oq + (size_t)b*QQ*DD;
    }
    int bm = mtile * 64;
    int tid = threadIdx.x, wid = tid >> 5, lane = tid & 31;
    int wm = wid >> 2;
    int wn = wid & 3;

    float c[2][8][4];
    #pragma unroll
    for (int mt = 0; mt < 2; mt++)
        #pragma unroll
        for (int nt = 0; nt < 8; nt++)
            #pragma unroll
            for (int r = 0; r < 4; r++) c[mt][nt][r] = 0.f;

    const int nchunks = NN / KC;
    for (int ch = 0; ch < nchunks; ch++) {
        int k0 = ch * KC;
        const int* gsrc = G + (size_t)bm * NN + k0;
        #pragma unroll
        for (int it = 0; it < 2; it++) {
            int idx = tid + it * 256;
            int row = idx >> 3, c4 = idx & 7;
            uint4 v = *(const uint4*)(gsrc + (size_t)row * NN + c4 * 4);
            uint32_t lo32 = (v.x ? 0x3F80u : 0u) | ((v.y ? 0x3F80u : 0u) << 16);
            uint32_t hi32 = (v.z ? 0x3F80u : 0u) | ((v.w ? 0x3F80u : 0u) << 16);
            *(uint2*)(As + row * KCP + c4 * 4) = make_uint2(lo32, hi32);
        }
        #pragma unroll
        for (int it = 0; it < 4; it++) {
            int idx = tid + it * 256;
            int d = idx >> 2, c8 = idx & 3;
            size_t src = (size_t)d * NN + k0 + c8 * 8;
            *(uint4*)(Bh + d * KCP + c8 * 8) = *(const uint4*)(Yh + src);
            *(uint4*)(Bl + d * KCP + c8 * 8) = *(const uint4*)(Yl + src);
        }
        __syncthreads();
        #pragma unroll
        for (int kt = 0; kt < 2; kt++) {
            int gk = kt * 16 + (lane & 3) * 2;
            int r0 = lane >> 2;
            uint32_t a[2][4];
            #pragma unroll
            for (int mt = 0; mt < 2; mt++) {
                int mrow = wm * 32 + mt * 16 + r0;
                a[mt][0] = *(const uint32_t*)(As + mrow * KCP + gk);
                a[mt][1] = *(const uint32_t*)(As + (mrow + 8) * KCP + gk);
                a[mt][2] = *(const uint32_t*)(As + mrow * KCP + gk + 8);
                a[mt][3] = *(const uint32_t*)(As + (mrow + 8) * KCP + gk + 8);
            }
            #pragma unroll
            for (int nt = 0; nt < 8; nt++) {
                int n = wn * 64 + nt * 8 + r0;
                uint32_t bh0 = *(const uint32_t*)(Bh + n * KCP + gk);
                uint32_t bh1 = *(const uint32_t*)(Bh + n * KCP + gk + 8);
                uint32_t bl0 = *(const uint32_t*)(Bl + n * KCP + gk);
                uint32_t bl1 = *(const uint32_t*)(Bl + n * KCP + gk + 8);
                mma_bf16(c[0][nt], a[0][0], a[0][1], a[0][2], a[0][3], bh0, bh1);
                mma_bf16(c[1][nt], a[1][0], a[1][1], a[1][2], a[1][3], bh0, bh1);
                mma_bf16(c[0][nt], a[0][0], a[0][1], a[0][2], a[0][3], bl0, bl1);
                mma_bf16(c[1][nt], a[1][0], a[1][1], a[1][2], a[1][3], bl0, bl1);
            }
        }
        __syncthreads();
    }

    #pragma unroll
    for (int mt = 0; mt < 2; mt++) {
        #pragma unroll
        for (int h = 0; h < 2; h++) {
            int row = bm + wm * 32 + mt * 16 + (lane >> 2) + h * 8;
            float cf = coef[row];
            const float* srow = S + (size_t)row * DD;
            float* orow = O + (size_t)row * DD;
            #pragma unroll
            for (int nt = 0; nt < 8; nt++) {
                int col = wn * 64 + nt * 8 + (lane & 3) * 2;
                float v0 = c[mt][nt][h * 2 + 0];
                float v1 = c[mt][nt][h * 2 + 1];
                if (ev) { v0 += ev[col]; v1 += ev[col + 1]; }
                float2 s2 = *(const float2*)(srow + col);
                float2 o;
                o.x = fmaxf(s2.x + cf * v0, 0.f);
                o.y = fmaxf(s2.y + cf * v1, 0.f);
                *(float2*)(orow + col) = o;
            }
        }
    }
}

// ---------------- launch ----------------
extern "C" void kernel_launch(void* const* d_in, const int* in_sizes, int n_in,
                              void* d_out, int out_size) {
    const float* p_in   = (const float*)d_in[0];
    const float* q_in   = (const float*)d_in[1];
    const float* qu_in  = (const float*)d_in[2];
    const int*   pmask  = (const int*)d_in[3];
    const int*   qmask  = (const int*)d_in[4];
    const int*   qumask = (const int*)d_in[5];
    const int*   ppg    = (const int*)d_in[6];
    const int*   qqg    = (const int*)d_in[7];
    const float* W_node = (const float*)d_in[10];
    const float* b_node = (const float*)d_in[11];
    const float* W_self = (const float*)d_in[12];
    const float* b_self = (const float*)d_in[13];
    const float* W_pp   = (const float*)d_in[14];
    const float* W_qd   = (const float*)d_in[15];
    const float* W_qq   = (const float*)d_in[16];
    const float* W_qup  = (const float*)d_in[17];
    const float* W_quq  = (const float*)d_in[18];
    const float* W_p    = (const float*)d_in[19];
    const float* b_p    = (const float*)d_in[20];
    const float* W_q    = (const float*)d_in[21];
    const float* b_q    = (const float*)d_in[22];
    const float* W_qu   = (const float*)d_in[23];
    const float* b_qu   = (const float*)d_in[24];
    float* out = (float*)d_out;

    float *pA, *pB, *qA, *qB, *quA, *quB, *selfp, *selfq, *selfqu;
    float *rsp, *rsq, *coefp, *coefq, *vqd;
    __nv_bfloat16 *Yphi, *Yplo, *Yqhi, *Yqlo, *Wth, *Wtl;
    cudaGetSymbolAddress((void**)&pA, g_pA);
    cudaGetSymbolAddress((void**)&pB, g_pB);
    cudaGetSymbolAddress((void**)&qA, g_qA);
    cudaGetSymbolAddress((void**)&qB, g_qB);
    cudaGetSymbolAddress((void**)&quA, g_quA);
    cudaGetSymbolAddress((void**)&quB, g_quB);
    cudaGetSymbolAddress((void**)&selfp, g_selfp);
    cudaGetSymbolAddress((void**)&selfq, g_selfq);
    cudaGetSymbolAddress((void**)&selfqu, g_selfqu);
    cudaGetSymbolAddress((void**)&rsp, g_rsp);
    cudaGetSymbolAddress((void**)&rsq, g_rsq);
    cudaGetSymbolAddress((void**)&coefp, g_coefp);
    cudaGetSymbolAddress((void**)&coefq, g_coefq);
    cudaGetSymbolAddress((void**)&vqd, g_vqd);
    cudaGetSymbolAddress((void**)&Yphi, g_Yphi);
    cudaGetSymbolAddress((void**)&Yplo, g_Yplo);
    cudaGetSymbolAddress((void**)&Yqhi, g_Yqhi);
    cudaGetSymbolAddress((void**)&Yqlo, g_Yqlo);
    cudaGetSymbolAddress((void**)&Wth, g_Wth);
    cudaGetSymbolAddress((void**)&Wtl, g_Wtl);

    // one-time (per call) weight transpose + split
    wsplit_kernel<<<dim3(8, 8), dim3(32, 8)>>>(W_self, 256, Wth + OFF_SELF, Wtl + OFF_SELF);
    wsplit_kernel<<<dim3(8, 8), dim3(32, 8)>>>(W_pp,   256, Wth + OFF_PPW,  Wtl + OFF_PPW);
    wsplit_kernel<<<dim3(8, 8), dim3(32, 8)>>>(W_qq,   256, Wth + OFF_QQW,  Wtl + OFF_QQW);
    wsplit_kernel<<<dim3(4, 8), dim3(32, 8)>>>(W_p,    128, Wth + OFF_PW,   Wtl + OFF_PW);
    wsplit_kernel<<<dim3(4, 8), dim3(32, 8)>>>(W_q,    128, Wth + OFF_QW,   Wtl + OFF_QW);
    wsplit_kernel<<<dim3(4, 8), dim3(32, 8)>>>(W_qu,   128, Wth + OFF_QUW,  Wtl + OFF_QUW);

    // step-invariant mask coefficients
    summask_kernel<<<BB, 256>>>(pmask, qmask);
    coefp_kernel<<<dim3(PP/8, BB), 256>>>(ppg, pmask);
    coefq_kernel<<<dim3(QQ/8, BB), 256>>>(qqg, qmask);
    coefqu_kernel<<<1, 128>>>(qumask);

    const float* pc = p_in;  const float* qc = q_in;  const float* quc = qu_in;
    float* pn = pA;  float* qn = qA;  float* qun = quA;

    for (int step = 0; step < 2; step++) {
        zero_s_kernel<<<4, 256>>>();
        pw_kernel<<<(BB*PP + BB*QQ)/8, 256>>>(pc, qc, pmask, qmask, W_node, b_node);
        s_kernel<<<dim3(BB, 24), 256>>>(pc, qc);
        vec_kernel<<<dim3(BB, 3), 256>>>(W_qd, W_qup, W_quq);

        // self projections (fp32 out + bias)
        gemm_mma_kernel<<<dim3(BB*PP/128, 2), 256>>>(pc, Wth + OFF_SELF, Wtl + OFF_SELF,
            DD, selfp, b_self, nullptr, nullptr, nullptr, 0);
        gemm_mma_kernel<<<dim3(BB*QQ/128, 2), 256>>>(qc, Wth + OFF_SELF, Wtl + OFF_SELF,
            DD, selfq, b_self, nullptr, nullptr, nullptr, 0);
        gemm_mma_kernel<<<dim3(1, 2), 256>>>(quc, Wth + OFF_SELF, Wtl + OFF_SELF,
            DD, selfqu, b_self, nullptr, nullptr, nullptr, 0);
        // weighted features, transposed hi/lo output
        gemm_mma_kernel<<<dim3(BB*PP/128, 2), 256>>>(pc, Wth + OFF_PPW, Wtl + OFF_PPW,
            DD, nullptr, nullptr, rsp, Yphi, Yplo, PP);
        gemm_mma_kernel<<<dim3(BB*QQ/128, 2), 256>>>(qc, Wth + OFF_QQW, Wtl + OFF_QQW,
            DD, nullptr, nullptr, rsq, Yqhi, Yqlo, QQ);

        adj_hmma_kernel<<<BB*(PP/64) + BB*(QQ/64), 256>>>(ppg, qqg, Yphi, Yplo, Yqhi, Yqlo,
                                                          selfp, selfq, coefp, coefq, vqd, pn, qn);
        qu_update_kernel<<<BB*QNN, DD>>>(qun);

        pc = pn; qc = qn; quc = qun;
        pn = pB; qn = qB; qun = quB;
    }

    // output projections
    gemm_mma_kernel<<<dim3(BB*PP/128, 1), 256>>>(pc, Wth + OFF_PW, Wtl + OFF_PW,
        HH, out, b_p, nullptr, nullptr, nullptr, 0);
    gemm_mma_kernel<<<dim3(BB*QQ/128, 1), 256>>>(qc, Wth + OFF_QW, Wtl + OFF_QW,
        HH, out + (size_t)BB*PP*HH, b_q, nullptr, nullptr, nullptr, 0);
    gemm_mma_kernel<<<dim3(1, 1), 256>>>(quc, Wth + OFF_QUW, Wtl + OFF_QUW,
        HH, out + (size_t)BB*PP*HH + (size_t)BB*QQ*HH, b_qu, nullptr, nullptr, nullptr, 0);
}

// round 6
// speedup vs baseline: 1.9812x; 1.2476x over previous
#include <cuda_runtime.h>
#include <cuda_bf16.h>
#include <math.h>
#include <stdint.h>

#define BB  4
#define PP  2048
#define QQ  1024
#define QNN 32
#define DD  256
#define HH  128

// ---------------- persistent scratch ----------------
__device__ float g_pA[BB*PP*DD];
__device__ float g_pB[BB*PP*DD];
__device__ float g_qA[BB*QQ*DD];
__device__ float g_qB[BB*QQ*DD];
__device__ float g_quA[BB*QNN*DD];
__device__ float g_quB[BB*QNN*DD];
__device__ float g_selfp[BB*PP*DD];
__device__ float g_selfq[BB*QQ*DD];
__device__ float g_selfqu[BB*QNN*DD];
__device__ __nv_bfloat16 g_Yphi[BB*DD*PP];
__device__ __nv_bfloat16 g_Yplo[BB*DD*PP];
__device__ __nv_bfloat16 g_Yqhi[BB*DD*QQ];
__device__ __nv_bfloat16 g_Yqlo[BB*DD*QQ];
__device__ __nv_bfloat16 g_Gpbf[(size_t)BB*PP*PP];
__device__ __nv_bfloat16 g_Gqbf[(size_t)BB*QQ*QQ];
// presplit node features (hi/lo bf16, [row, 256])
__device__ __nv_bfloat16 g_Aphi[BB*PP*DD];
__device__ __nv_bfloat16 g_Aplo[BB*PP*DD];
__device__ __nv_bfloat16 g_Aqhi[BB*QQ*DD];
__device__ __nv_bfloat16 g_Aqlo[BB*QQ*DD];
__device__ __nv_bfloat16 g_Aquhi[BB*QNN*DD];
__device__ __nv_bfloat16 g_Aqulo[BB*QNN*DD];
// transposed hi/lo weights: [N,256] each
__device__ __nv_bfloat16 g_Wth[294912];
__device__ __nv_bfloat16 g_Wtl[294912];
#define OFF_SELF 0
#define OFF_PPW  65536
#define OFF_QQW  131072
#define OFF_PW   196608
#define OFF_QW   229376
#define OFF_QUW  262144
__device__ float g_rsp[BB*PP];
__device__ float g_rsq[BB*QQ];
__device__ float g_coefp[BB*PP];
__device__ float g_coefq[BB*QQ];
__device__ float g_coefqu[BB*QNN];
__device__ float g_sp[BB*DD];
__device__ float g_sq[BB*DD];
__device__ float g_vqd[BB*DD];
__device__ float g_vqup[BB*DD];
__device__ float g_vquq[BB*DD];
__device__ float g_summ[2*BB];

// ---------------- cp.async helpers ----------------
#define CPA(dst, src) asm volatile("cp.async.cg.shared.global [%0], [%1], 16;" :: "r"(dst), "l"(src) : "memory")
#define CPC() asm volatile("cp.async.commit_group;" ::: "memory")
#define CPW1() asm volatile("cp.async.wait_group 1;" ::: "memory")
#define CPW0() asm volatile("cp.async.wait_group 0;" ::: "memory")

// ---------------- small kernels ----------------
__global__ void zero_s_kernel() {
    int i = blockIdx.x * blockDim.x + threadIdx.x;
    if (i < BB*DD) { g_sp[i] = 0.f; g_sq[i] = 0.f; }
}

__global__ void summask_kernel(const int* __restrict__ pm, const int* __restrict__ qm) {
    int b = blockIdx.x, tid = threadIdx.x;
    __shared__ float red[256];
    float s = 0.f;
    for (int i = tid; i < PP; i += 256) s += (float)pm[b*PP + i];
    red[tid] = s; __syncthreads();
    for (int o = 128; o; o >>= 1) { if (tid < o) red[tid] += red[tid + o]; __syncthreads(); }
    if (tid == 0) g_summ[b] = red[0];
    __syncthreads();
    s = 0.f;
    for (int i = tid; i < QQ; i += 256) s += (float)qm[b*QQ + i];
    red[tid] = s; __syncthreads();
    for (int o = 128; o; o >>= 1) { if (tid < o) red[tid] += red[tid + o]; __syncthreads(); }
    if (tid == 0) g_summ[BB + b] = red[0];
}

__global__ void coefp_kernel(const int* __restrict__ G, const int* __restrict__ pm) {
    int b = blockIdx.y;
    __shared__ float spm[PP];
    int tid = threadIdx.x;
    for (int i = tid; i < PP; i += 256) spm[i] = (float)pm[b*PP + i];
    __syncthreads();
    int warp = tid >> 5, lane = tid & 31;
    int row = blockIdx.x * 8 + warp;
    const int* g = G + ((size_t)b*PP + row) * PP;
    float s = 0.f;
    for (int j = lane; j < PP; j += 32) s += spm[j] * (float)g[j];
    for (int o = 16; o; o >>= 1) s += __shfl_xor_sync(0xffffffffu, s, o);
    if (lane == 0)
        g_coefp[b*PP + row] = pm[b*PP + row] ? 1.f / fmaxf(s, 1.f) : 0.f;
}

__global__ void coefq_kernel(const int* __restrict__ G, const int* __restrict__ qm) {
    int b = blockIdx.y;
    __shared__ float sqm[QQ];
    int tid = threadIdx.x;
    for (int i = tid; i < QQ; i += 256) sqm[i] = (float)qm[b*QQ + i];
    __syncthreads();
    int warp = tid >> 5, lane = tid & 31;
    int row = blockIdx.x * 8 + warp;
    const int* g = G + ((size_t)b*QQ + row) * QQ;
    float s = 0.f;
    for (int j = lane; j < QQ; j += 32) s += sqm[j] * (float)g[j];
    for (int o = 16; o; o >>= 1) s += __shfl_xor_sync(0xffffffffu, s, o);
    if (lane == 0)
        g_coefq[b*QQ + row] = qm[b*QQ + row] ? 1.f / fmaxf(g_summ[b] + s, 1.f) : 0.f;
}

__global__ void coefqu_kernel(const int* __restrict__ qum) {
    int i = blockIdx.x * blockDim.x + threadIdx.x;
    if (i >= BB*QNN) return;
    int b = i / QNN;
    float t = g_summ[b] + g_summ[BB + b];
    g_coefqu[i] = qum[i] ? 1.f / fmaxf(t, 1.f) : 0.f;
}

// fused: node weights (sigmoid gate) + masked weighted feature sum s
__global__ void pws_kernel(const float* __restrict__ pcur, const float* __restrict__ qcur,
                           const int* __restrict__ pmask, const int* __restrict__ qmask,
                           const float* __restrict__ Wn, const float* __restrict__ bn) {
    int b = blockIdx.x, chunk = blockIdx.y;
    int tid = threadIdx.x, wid = tid >> 5, lane = tid & 31;
    const float* node; const int* mask; float* rsout; float* sout; int rowbase;
    if (chunk < 16) {
        node = pcur + (size_t)b*PP*DD; mask = pmask + b*PP;
        rsout = g_rsp + b*PP; sout = g_sp + b*DD; rowbase = chunk * 128;
    } else {
        node = qcur + (size_t)b*QQ*DD; mask = qmask + b*QQ;
        rsout = g_rsq + b*QQ; sout = g_sq + b*DD; rowbase = (chunk - 16) * 128;
    }
    __shared__ float wsh[DD];
    __shared__ float wrow[128];
    for (int k = tid; k < DD; k += 256) wsh[k] = Wn[k];
    __syncthreads();
    float bv = bn[0];
    #pragma unroll
    for (int r = 0; r < 16; r++) {
        int lrow = wid * 16 + r;
        const float* nrow = node + (size_t)(rowbase + lrow) * DD;
        float s = 0.f;
        #pragma unroll
        for (int k = lane; k < DD; k += 32) s += nrow[k] * wsh[k];
        #pragma unroll
        for (int o = 16; o; o >>= 1) s += __shfl_xor_sync(0xffffffffu, s, o);
        if (lane == 0) {
            float sig = 1.f / (1.f + expf(-(s + bv)));
            float w = mask[rowbase + lrow] ? sig : 0.f;
            wrow[lrow] = w;
            rsout[rowbase + lrow] = w;
        }
    }
    __syncthreads();
    float acc = 0.f;
    #pragma unroll 4
    for (int i = 0; i < 128; i++) {
        float w = wrow[i];
        if (w != 0.f) acc += w * node[(size_t)(rowbase + i) * DD + tid];
    }
    atomicAdd(&sout[tid], acc);
}

__global__ void vec_kernel(const float* __restrict__ Wqd, const float* __restrict__ Wqup,
                           const float* __restrict__ Wquq) {
    int b = blockIdx.x, sel = blockIdx.y, tid = threadIdx.x;
    __shared__ float sh[DD];
    const float* s = (sel == 2) ? g_sq : g_sp;
    const float* W = (sel == 0) ? Wqd : (sel == 1) ? Wqup : Wquq;
    float* out = (sel == 0) ? g_vqd : (sel == 1) ? g_vqup : g_vquq;
    sh[tid] = s[b*DD + tid];
    __syncthreads();
    float acc = 0.f;
    #pragma unroll 8
    for (int k = 0; k < DD; k++) acc += sh[k] * W[(size_t)k*DD + tid];
    out[b*DD + tid] = acc;
}

__global__ void qu_update_kernel(float* __restrict__ qunxt) {
    int r = blockIdx.x;
    int d = threadIdx.x;
    int b = r / QNN;
    float v = g_selfqu[(size_t)r*DD + d] + g_coefqu[r] * (g_vqup[b*DD + d] + g_vquq[b*DD + d]);
    qunxt[(size_t)r*DD + d] = fmaxf(v, 0.f);
}

// ---------------- prep kernels ----------------
// binary int graph -> bf16 {0,1} (step-invariant; run once)
__global__ void g2bf_kernel(const int* __restrict__ Gp, const int* __restrict__ Gq) {
    size_t i = ((size_t)blockIdx.x * 256 + threadIdx.x) * 8;
    const size_t NPel = (size_t)BB*PP*PP;
    const int* src; __nv_bfloat16* dst;
    if (i < NPel) { src = Gp + i; dst = g_Gpbf + i; }
    else { size_t j = i - NPel; src = Gq + j; dst = g_Gqbf + j; }
    int4 a = *(const int4*)src;
    int4 b = *(const int4*)(src + 4);
    uint32_t r0 = (a.x ? 0x3F80u : 0u) | ((a.y ? 0x3F80u : 0u) << 16);
    uint32_t r1 = (a.z ? 0x3F80u : 0u) | ((a.w ? 0x3F80u : 0u) << 16);
    uint32_t r2 = (b.x ? 0x3F80u : 0u) | ((b.y ? 0x3F80u : 0u) << 16);
    uint32_t r3 = (b.z ? 0x3F80u : 0u) | ((b.w ? 0x3F80u : 0u) << 16);
    *(uint4*)dst = make_uint4(r0, r1, r2, r3);
}

__device__ __forceinline__ void split_pack2(float x, float y, uint32_t& h, uint32_t& l) {
    __nv_bfloat16 hx = __float2bfloat16(x), hy = __float2bfloat16(y);
    float rx = x - __bfloat162float(hx), ry = y - __bfloat162float(hy);
    __nv_bfloat16 lx = __float2bfloat16(rx), ly = __float2bfloat16(ry);
    h = (uint32_t)__bfloat16_as_ushort(hy) << 16 | __bfloat16_as_ushort(hx);
    l = (uint32_t)__bfloat16_as_ushort(ly) << 16 | __bfloat16_as_ushort(lx);
}

// fp32 [M,256] -> hi/lo bf16 [M,256]
__global__ void asplit_kernel(const float* __restrict__ A,
                              __nv_bfloat16* __restrict__ Ahi, __nv_bfloat16* __restrict__ Alo) {
    size_t i4 = ((size_t)blockIdx.x * 256 + threadIdx.x) * 4;
    float4 v = *(const float4*)(A + i4);
    uint32_t h0, l0, h1, l1;
    split_pack2(v.x, v.y, h0, l0);
    split_pack2(v.z, v.w, h1, l1);
    *(uint2*)(Ahi + i4) = make_uint2(h0, h1);
    *(uint2*)(Alo + i4) = make_uint2(l0, l1);
}

// W[K=256, N] fp32 -> Wt hi/lo [N, 256] bf16
__global__ void wsplit_kernel(const float* __restrict__ W, int N,
                              __nv_bfloat16* __restrict__ Wth, __nv_bfloat16* __restrict__ Wtl) {
    __shared__ float T[32][33];
    int nb = blockIdx.x * 32, kb = blockIdx.y * 32;
    int tx = threadIdx.x, ty = threadIdx.y;  // 32 x 8
    #pragma unroll
    for (int r = 0; r < 32; r += 8)
        T[ty + r][tx] = W[(size_t)(kb + ty + r) * N + nb + tx];
    __syncthreads();
    #pragma unroll
    for (int r = 0; r < 32; r += 8) {
        int n = nb + ty + r, k = kb + tx;
        float v = T[tx][ty + r];
        __nv_bfloat16 h = __float2bfloat16(v);
        Wth[(size_t)n * 256 + k] = h;
        Wtl[(size_t)n * 256 + k] = __float2bfloat16(v - __bfloat162float(h));
    }
}

// ---------------- mma helper ----------------
__device__ __forceinline__ void mma_bf16(float c[4], uint32_t a0, uint32_t a1,
                                         uint32_t a2, uint32_t a3,
                                         uint32_t b0, uint32_t b1) {
    asm volatile(
        "mma.sync.aligned.m16n8k16.row.col.f32.bf16.bf16.f32 "
        "{%0,%1,%2,%3}, {%4,%5,%6,%7}, {%8,%9}, {%0,%1,%2,%3};"
        : "+f"(c[0]), "+f"(c[1]), "+f"(c[2]), "+f"(c[3])
        : "r"(a0), "r"(a1), "r"(a2), "r"(a3), "r"(b0), "r"(b1));
}

// ---------------- HMMA feature GEMM (presplit A) ----------------
#define KC2 32
#define KCP2 40

__global__ __launch_bounds__(256)
void gemm_mma_kernel(const __nv_bfloat16* __restrict__ Ahi, const __nv_bfloat16* __restrict__ Alo,
                     const __nv_bfloat16* __restrict__ Wth, const __nv_bfloat16* __restrict__ Wtl,
                     int N, float* __restrict__ Cout, const float* __restrict__ bias,
                     const float* __restrict__ rowscale,
                     __nv_bfloat16* __restrict__ Yhi, __nv_bfloat16* __restrict__ Ylo,
                     int NNbatch) {
    __shared__ __nv_bfloat16 Ah[128 * KCP2];
    __shared__ __nv_bfloat16 Al[128 * KCP2];
    __shared__ __nv_bfloat16 Wh[128 * KCP2];
    __shared__ __nv_bfloat16 Wl[128 * KCP2];

    int bm = blockIdx.x * 128, bn = blockIdx.y * 128;
    int tid = threadIdx.x, wid = tid >> 5, lane = tid & 31;
    int wm = wid >> 1, wn = wid & 1;

    float c[2][8][4];
    #pragma unroll
    for (int mt = 0; mt < 2; mt++)
        #pragma unroll
        for (int nt = 0; nt < 8; nt++)
            #pragma unroll
            for (int r = 0; r < 4; r++) c[mt][nt][r] = 0.f;

    for (int ch = 0; ch < 8; ch++) {
        int k0 = ch * KC2;
        #pragma unroll
        for (int it = 0; it < 2; it++) {
            int u = tid + it * 256;            // 0..511
            int row = u >> 2, c8 = u & 3;
            size_t src = (size_t)(bm + row) * DD + k0 + c8 * 8;
            *(uint4*)(Ah + row * KCP2 + c8 * 8) = *(const uint4*)(Ahi + src);
            *(uint4*)(Al + row * KCP2 + c8 * 8) = *(const uint4*)(Alo + src);
        }
        #pragma unroll
        for (int it = 0; it < 2; it++) {
            int u = tid + it * 256;
            int n = u >> 2, c8 = u & 3;
            size_t src = (size_t)(bn + n) * 256 + k0 + c8 * 8;
            *(uint4*)(Wh + n * KCP2 + c8 * 8) = *(const uint4*)(Wth + src);
            *(uint4*)(Wl + n * KCP2 + c8 * 8) = *(const uint4*)(Wtl + src);
        }
        __syncthreads();
        #pragma unroll
        for (int kt = 0; kt < 2; kt++) {
            int gk = kt * 16 + (lane & 3) * 2;
            int r0 = lane >> 2;
            uint32_t ah[2][4], al[2][4];
            #pragma unroll
            for (int mt = 0; mt < 2; mt++) {
                int mrow = wm * 32 + mt * 16 + r0;
                ah[mt][0] = *(const uint32_t*)(Ah + mrow * KCP2 + gk);
                ah[mt][1] = *(const uint32_t*)(Ah + (mrow + 8) * KCP2 + gk);
                ah[mt][2] = *(const uint32_t*)(Ah + mrow * KCP2 + gk + 8);
                ah[mt][3] = *(const uint32_t*)(Ah + (mrow + 8) * KCP2 + gk + 8);
                al[mt][0] = *(const uint32_t*)(Al + mrow * KCP2 + gk);
                al[mt][1] = *(const uint32_t*)(Al + (mrow + 8) * KCP2 + gk);
                al[mt][2] = *(const uint32_t*)(Al + mrow * KCP2 + gk + 8);
                al[mt][3] = *(const uint32_t*)(Al + (mrow + 8) * KCP2 + gk + 8);
            }
            #pragma unroll
            for (int nt = 0; nt < 8; nt++) {
                int n = wn * 64 + nt * 8 + r0;
                uint32_t wh0 = *(const uint32_t*)(Wh + n * KCP2 + gk);
                uint32_t wh1 = *(const uint32_t*)(Wh + n * KCP2 + gk + 8);
                uint32_t wl0 = *(const uint32_t*)(Wl + n * KCP2 + gk);
                uint32_t wl1 = *(const uint32_t*)(Wl + n * KCP2 + gk + 8);
                #pragma unroll
                for (int mt = 0; mt < 2; mt++) {
                    mma_bf16(c[mt][nt], ah[mt][0], ah[mt][1], ah[mt][2], ah[mt][3], wh0, wh1);
                    mma_bf16(c[mt][nt], al[mt][0], al[mt][1], al[mt][2], al[mt][3], wh0, wh1);
                    mma_bf16(c[mt][nt], ah[mt][0], ah[mt][1], ah[mt][2], ah[mt][3], wl0, wl1);
                }
            }
        }
        __syncthreads();
    }

    if (Cout) {
        #pragma unroll
        for (int mt = 0; mt < 2; mt++)
            #pragma unroll
            for (int h = 0; h < 2; h++) {
                int row = bm + wm * 32 + mt * 16 + (lane >> 2) + h * 8;
                float* orow = Cout + (size_t)row * N;
                #pragma unroll
                for (int nt = 0; nt < 8; nt++) {
                    int col = bn + wn * 64 + nt * 8 + (lane & 3) * 2;
                    float2 o;
                    o.x = c[mt][nt][h * 2 + 0] + bias[col];
                    o.y = c[mt][nt][h * 2 + 1] + bias[col + 1];
                    *(float2*)(orow + col) = o;
                }
            }
    } else {
        #pragma unroll
        for (int mt = 0; mt < 2; mt++)
            #pragma unroll
            for (int h = 0; h < 2; h++) {
                int gr = bm + wm * 32 + mt * 16 + (lane >> 2) + h * 8;
                float rs = rowscale[gr];
                int b = gr / NNbatch;
                int i = gr - b * NNbatch;
                #pragma unroll
                for (int nt = 0; nt < 8; nt++) {
                    int col = bn + wn * 64 + nt * 8 + (lane & 3) * 2;
                    size_t base = ((size_t)b * DD + col) * NNbatch + i;
                    float v0 = c[mt][nt][h * 2 + 0] * rs;
                    float v1 = c[mt][nt][h * 2 + 1] * rs;
                    __nv_bfloat16 h0 = __float2bfloat16(v0);
                    __nv_bfloat16 h1 = __float2bfloat16(v1);
                    Yhi[base] = h0;
                    Yhi[base + NNbatch] = h1;
                    Ylo[base] = __float2bfloat16(v0 - __bfloat162float(h0));
                    Ylo[base + NNbatch] = __float2bfloat16(v1 - __bfloat162float(h1));
                }
            }
    }
}

// ---------------- pipelined HMMA adjacency aggregation ----------------
// dynamic smem: As[2][64*40], Bh[2][256*40], Bl[2][256*40] bf16 = 92160 B
#define KC 32
#define KCP 40
#define ADJ_SMEM 92160
#define AS_BYTES 5120
#define BH_BYTES 20480

__global__ __launch_bounds__(256)
void adj_hmma_kernel(const __nv_bfloat16* __restrict__ Yphi, const __nv_bfloat16* __restrict__ Yplo,
                     const __nv_bfloat16* __restrict__ Yqhi, const __nv_bfloat16* __restrict__ Yqlo,
                     const float* __restrict__ selfp, const float* __restrict__ selfq,
                     const float* __restrict__ coefp, const float* __restrict__ coefq,
                     const float* __restrict__ vqd,
                     float* __restrict__ Op, float* __restrict__ Oq) {
    extern __shared__ __align__(16) char dsm[];
    uint32_t smemBase = (uint32_t)__cvta_generic_to_shared(dsm);

    int bx = blockIdx.x;
    const __nv_bfloat16 *Gbf, *Yh, *Yl; const float *S, *coef, *ev;
    float* O; int NN, b, mtile;
    if (bx < BB * (PP/64)) {
        b = bx >> 5; mtile = bx & 31; NN = PP;
        Gbf = g_Gpbf + (size_t)b*PP*PP;
        Yh = Yphi + (size_t)b*DD*PP;  Yl = Yplo + (size_t)b*DD*PP;
        S = selfp + (size_t)b*PP*DD;  coef = coefp + b*PP;
        ev = nullptr;                 O = Op + (size_t)b*PP*DD;
    } else {
        int i2 = bx - BB * (PP/64);
        b = i2 >> 4; mtile = i2 & 15; NN = QQ;
        Gbf = g_Gqbf + (size_t)b*QQ*QQ;
        Yh = Yqhi + (size_t)b*DD*QQ;  Yl = Yqlo + (size_t)b*DD*QQ;
        S = selfq + (size_t)b*QQ*DD;  coef = coefq + b*QQ;
        ev = vqd + b*DD;              O = Oq + (size_t)b*QQ*DD;
    }
    int bm = mtile * 64;
    int tid = threadIdx.x, wid = tid >> 5, lane = tid & 31;
    int wm = wid >> 2, wn = wid & 3;

    float c[2][8][4];
    #pragma unroll
    for (int mt = 0; mt < 2; mt++)
        #pragma unroll
        for (int nt = 0; nt < 8; nt++)
            #pragma unroll
            for (int r = 0; r < 4; r++) c[mt][nt][r] = 0.f;

    // per-thread cp.async assignments
    int arow = tid >> 2, ac8 = tid & 3;  // A: 64 rows x 4 chunks

    auto issue = [&](int k0, int bufi) {
        uint32_t asb = smemBase + bufi * AS_BYTES;
        CPA(asb + arow * 80 + ac8 * 16, Gbf + (size_t)(bm + arow) * NN + k0 + ac8 * 8);
        uint32_t bhb = smemBase + 2 * AS_BYTES + bufi * BH_BYTES;
        uint32_t blb = smemBase + 2 * AS_BYTES + 2 * BH_BYTES + bufi * BH_BYTES;
        #pragma unroll
        for (int it = 0; it < 4; it++) {
            int idx = tid + it * 256;
            int d = idx >> 2, c8 = idx & 3;
            size_t src = (size_t)d * NN + k0 + c8 * 8;
            CPA(bhb + d * 80 + c8 * 16, Yh + src);
            CPA(blb + d * 80 + c8 * 16, Yl + src);
        }
    };

    const int nchunks = NN / KC;
    issue(0, 0);
    CPC();
    int buf = 0;
    for (int ch = 0; ch < nchunks; ch++) {
        bool hn = (ch + 1 < nchunks);
        if (hn) { issue((ch + 1) * KC, buf ^ 1); CPC(); }
        if (hn) { CPW1(); } else { CPW0(); }
        __syncthreads();

        const __nv_bfloat16* As = (const __nv_bfloat16*)(dsm + buf * AS_BYTES);
        const __nv_bfloat16* Bh = (const __nv_bfloat16*)(dsm + 2 * AS_BYTES + buf * BH_BYTES);
        const __nv_bfloat16* Bl = (const __nv_bfloat16*)(dsm + 2 * AS_BYTES + 2 * BH_BYTES + buf * BH_BYTES);

        #pragma unroll
        for (int kt = 0; kt < 2; kt++) {
            int gk = kt * 16 + (lane & 3) * 2;
            int r0 = lane >> 2;
            uint32_t a[2][4];
            #pragma unroll
            for (int mt = 0; mt < 2; mt++) {
                int mrow = wm * 32 + mt * 16 + r0;
                a[mt][0] = *(const uint32_t*)(As + mrow * KCP + gk);
                a[mt][1] = *(const uint32_t*)(As + (mrow + 8) * KCP + gk);
                a[mt][2] = *(const uint32_t*)(As + mrow * KCP + gk + 8);
                a[mt][3] = *(const uint32_t*)(As + (mrow + 8) * KCP + gk + 8);
            }
            #pragma unroll
            for (int nt = 0; nt < 8; nt++) {
                int n = wn * 64 + nt * 8 + r0;
                uint32_t bh0 = *(const uint32_t*)(Bh + n * KCP + gk);
                uint32_t bh1 = *(const uint32_t*)(Bh + n * KCP + gk + 8);
                uint32_t bl0 = *(const uint32_t*)(Bl + n * KCP + gk);
                uint32_t bl1 = *(const uint32_t*)(Bl + n * KCP + gk + 8);
                mma_bf16(c[0][nt], a[0][0], a[0][1], a[0][2], a[0][3], bh0, bh1);
                mma_bf16(c[1][nt], a[1][0], a[1][1], a[1][2], a[1][3], bh0, bh1);
                mma_bf16(c[0][nt], a[0][0], a[0][1], a[0][2], a[0][3], bl0, bl1);
                mma_bf16(c[1][nt], a[1][0], a[1][1], a[1][2], a[1][3], bl0, bl1);
            }
        }
        __syncthreads();
        buf ^= 1;
    }

    #pragma unroll
    for (int mt = 0; mt < 2; mt++) {
        #pragma unroll
        for (int h = 0; h < 2; h++) {
            int row = bm + wm * 32 + mt * 16 + (lane >> 2) + h * 8;
            float cf = coef[row];
            const float* srow = S + (size_t)row * DD;
            float* orow = O + (size_t)row * DD;
            #pragma unroll
            for (int nt = 0; nt < 8; nt++) {
                int col = wn * 64 + nt * 8 + (lane & 3) * 2;
                float v0 = c[mt][nt][h * 2 + 0];
                float v1 = c[mt][nt][h * 2 + 1];
                if (ev) { v0 += ev[col]; v1 += ev[col + 1]; }
                float2 s2 = *(const float2*)(srow + col);
                float2 o;
                o.x = fmaxf(s2.x + cf * v0, 0.f);
                o.y = fmaxf(s2.y + cf * v1, 0.f);
                *(float2*)(orow + col) = o;
            }
        }
    }
}

// ---------------- launch ----------------
extern "C" void kernel_launch(void* const* d_in, const int* in_sizes, int n_in,
                              void* d_out, int out_size) {
    const float* p_in   = (const float*)d_in[0];
    const float* q_in   = (const float*)d_in[1];
    const float* qu_in  = (const float*)d_in[2];
    const int*   pmask  = (const int*)d_in[3];
    const int*   qmask  = (const int*)d_in[4];
    const int*   qumask = (const int*)d_in[5];
    const int*   ppg    = (const int*)d_in[6];
    const int*   qqg    = (const int*)d_in[7];
    const float* W_node = (const float*)d_in[10];
    const float* b_node = (const float*)d_in[11];
    const float* W_self = (const float*)d_in[12];
    const float* b_self = (const float*)d_in[13];
    const float* W_pp   = (const float*)d_in[14];
    const float* W_qd   = (const float*)d_in[15];
    const float* W_qq   = (const float*)d_in[16];
    const float* W_qup  = (const float*)d_in[17];
    const float* W_quq  = (const float*)d_in[18];
    const float* W_p    = (const float*)d_in[19];
    const float* b_p    = (const float*)d_in[20];
    const float* W_q    = (const float*)d_in[21];
    const float* b_q    = (const float*)d_in[22];
    const float* W_qu   = (const float*)d_in[23];
    const float* b_qu   = (const float*)d_in[24];
    float* out = (float*)d_out;

    float *pA, *pB, *qA, *qB, *quA, *quB, *selfp, *selfq, *selfqu;
    float *rsp, *rsq, *coefp, *coefq, *vqd;
    __nv_bfloat16 *Yphi, *Yplo, *Yqhi, *Yqlo, *Wth, *Wtl;
    __nv_bfloat16 *Aphi, *Aplo, *Aqhi, *Aqlo, *Aquhi, *Aqulo;
    cudaGetSymbolAddress((void**)&pA, g_pA);
    cudaGetSymbolAddress((void**)&pB, g_pB);
    cudaGetSymbolAddress((void**)&qA, g_qA);
    cudaGetSymbolAddress((void**)&qB, g_qB);
    cudaGetSymbolAddress((void**)&quA, g_quA);
    cudaGetSymbolAddress((void**)&quB, g_quB);
    cudaGetSymbolAddress((void**)&selfp, g_selfp);
    cudaGetSymbolAddress((void**)&selfq, g_selfq);
    cudaGetSymbolAddress((void**)&selfqu, g_selfqu);
    cudaGetSymbolAddress((void**)&rsp, g_rsp);
    cudaGetSymbolAddress((void**)&rsq, g_rsq);
    cudaGetSymbolAddress((void**)&coefp, g_coefp);
    cudaGetSymbolAddress((void**)&coefq, g_coefq);
    cudaGetSymbolAddress((void**)&vqd, g_vqd);
    cudaGetSymbolAddress((void**)&Yphi, g_Yphi);
    cudaGetSymbolAddress((void**)&Yplo, g_Yplo);
    cudaGetSymbolAddress((void**)&Yqhi, g_Yqhi);
    cudaGetSymbolAddress((void**)&Yqlo, g_Yqlo);
    cudaGetSymbolAddress((void**)&Wth, g_Wth);
    cudaGetSymbolAddress((void**)&Wtl, g_Wtl);
    cudaGetSymbolAddress((void**)&Aphi, g_Aphi);
    cudaGetSymbolAddress((void**)&Aplo, g_Aplo);
    cudaGetSymbolAddress((void**)&Aqhi, g_Aqhi);
    cudaGetSymbolAddress((void**)&Aqlo, g_Aqlo);
    cudaGetSymbolAddress((void**)&Aquhi, g_Aquhi);
    cudaGetSymbolAddress((void**)&Aqulo, g_Aqulo);

    cudaFuncSetAttribute(adj_hmma_kernel, cudaFuncAttributeMaxDynamicSharedMemorySize, ADJ_SMEM);

    // preamble: graph -> bf16, weight transpose+split, mask coefficients
    g2bf_kernel<<<10240, 256>>>(ppg, qqg);
    wsplit_kernel<<<dim3(8, 8), dim3(32, 8)>>>(W_self, 256, Wth + OFF_SELF, Wtl + OFF_SELF);
    wsplit_kernel<<<dim3(8, 8), dim3(32, 8)>>>(W_pp,   256, Wth + OFF_PPW,  Wtl + OFF_PPW);
    wsplit_kernel<<<dim3(8, 8), dim3(32, 8)>>>(W_qq,   256, Wth + OFF_QQW,  Wtl + OFF_QQW);
    wsplit_kernel<<<dim3(4, 8), dim3(32, 8)>>>(W_p,    128, Wth + OFF_PW,   Wtl + OFF_PW);
    wsplit_kernel<<<dim3(4, 8), dim3(32, 8)>>>(W_q,    128, Wth + OFF_QW,   Wtl + OFF_QW);
    wsplit_kernel<<<dim3(4, 8), dim3(32, 8)>>>(W_qu,   128, Wth + OFF_QUW,  Wtl + OFF_QUW);
    summask_kernel<<<BB, 256>>>(pmask, qmask);
    coefp_kernel<<<dim3(PP/8, BB), 256>>>(ppg, pmask);
    coefq_kernel<<<dim3(QQ/8, BB), 256>>>(qqg, qmask);
    coefqu_kernel<<<1, 128>>>(qumask);

    const float* pc = p_in;  const float* qc = q_in;  const float* quc = qu_in;
    float* pn = pA;  float* qn = qA;  float* qun = quA;

    for (int step = 0; step < 2; step++) {
        zero_s_kernel<<<4, 256>>>();
        pws_kernel<<<dim3(BB, 24), 256>>>(pc, qc, pmask, qmask, W_node, b_node);
        vec_kernel<<<dim3(BB, 3), 256>>>(W_qd, W_qup, W_quq);

        asplit_kernel<<<2048, 256>>>(pc, Aphi, Aplo);
        asplit_kernel<<<1024, 256>>>(qc, Aqhi, Aqlo);
        asplit_kernel<<<32, 256>>>(quc, Aquhi, Aqulo);

        gemm_mma_kernel<<<dim3(BB*PP/128, 2), 256>>>(Aphi, Aplo, Wth + OFF_SELF, Wtl + OFF_SELF,
            DD, selfp, b_self, nullptr, nullptr, nullptr, 0);
        gemm_mma_kernel<<<dim3(BB*QQ/128, 2), 256>>>(Aqhi, Aqlo, Wth + OFF_SELF, Wtl + OFF_SELF,
            DD, selfq, b_self, nullptr, nullptr, nullptr, 0);
        gemm_mma_kernel<<<dim3(1, 2), 256>>>(Aquhi, Aqulo, Wth + OFF_SELF, Wtl + OFF_SELF,
            DD, selfqu, b_self, nullptr, nullptr, nullptr, 0);
        gemm_mma_kernel<<<dim3(BB*PP/128, 2), 256>>>(Aphi, Aplo, Wth + OFF_PPW, Wtl + OFF_PPW,
            DD, nullptr, nullptr, rsp, Yphi, Yplo, PP);
        gemm_mma_kernel<<<dim3(BB*QQ/128, 2), 256>>>(Aqhi, Aqlo, Wth + OFF_QQW, Wtl + OFF_QQW,
            DD, nullptr, nullptr, rsq, Yqhi, Yqlo, QQ);

        adj_hmma_kernel<<<BB*(PP/64) + BB*(QQ/64), 256, ADJ_SMEM>>>(
            Yphi, Yplo, Yqhi, Yqlo, selfp, selfq, coefp, coefq, vqd, pn, qn);
        qu_update_kernel<<<BB*QNN, DD>>>(qun);

        pc = pn; qc = qn; quc = qun;
        pn = pB; qn = qB; qun = quB;
    }

    // output projections (presplit final states, then HMMA)
    asplit_kernel<<<2048, 256>>>(pc, Aphi, Aplo);
    asplit_kernel<<<1024, 256>>>(qc, Aqhi, Aqlo);
    asplit_kernel<<<32, 256>>>(quc, Aquhi, Aqulo);
    gemm_mma_kernel<<<dim3(BB*PP/128, 1), 256>>>(Aphi, Aplo, Wth + OFF_PW, Wtl + OFF_PW,
        HH, out, b_p, nullptr, nullptr, nullptr, 0);
    gemm_mma_kernel<<<dim3(BB*QQ/128, 1), 256>>>(Aqhi, Aqlo, Wth + OFF_QW, Wtl + OFF_QW,
        HH, out + (size_t)BB*PP*HH, b_q, nullptr, nullptr, nullptr, 0);
    gemm_mma_kernel<<<dim3(1, 1), 256>>>(Aquhi, Aqulo, Wth + OFF_QUW, Wtl + OFF_QUW,
        HH, out + (size_t)BB*PP*HH + (size_t)BB*QQ*HH, b_qu, nullptr, nullptr, nullptr, 0);
}

// round 8
// speedup vs baseline: 2.3626x; 1.1925x over previous
#include <cuda_runtime.h>
#include <cuda_bf16.h>
#include <math.h>
#include <stdint.h>

#define BB  4
#define PP  2048
#define QQ  1024
#define QNN 32
#define DD  256
#define HH  128

// ---------------- persistent scratch ----------------
__device__ float g_pA[BB*PP*DD];
__device__ float g_pB[BB*PP*DD];
__device__ float g_qA[BB*QQ*DD];
__device__ float g_qB[BB*QQ*DD];
__device__ float g_quA[BB*QNN*DD];
__device__ float g_quB[BB*QNN*DD];
__device__ float g_selfp[BB*PP*DD];
__device__ float g_selfq[BB*QQ*DD];
__device__ float g_selfqu[BB*QNN*DD];
__device__ __nv_bfloat16 g_Yphi[BB*DD*PP];
__device__ __nv_bfloat16 g_Yplo[BB*DD*PP];
__device__ __nv_bfloat16 g_Yqhi[BB*DD*QQ];
__device__ __nv_bfloat16 g_Yqlo[BB*DD*QQ];
__device__ __nv_bfloat16 g_Gpbf[(size_t)BB*PP*PP];
__device__ __nv_bfloat16 g_Gqbf[(size_t)BB*QQ*QQ];
__device__ __nv_bfloat16 g_Aphi[BB*PP*DD];
__device__ __nv_bfloat16 g_Aplo[BB*PP*DD];
__device__ __nv_bfloat16 g_Aqhi[BB*QQ*DD];
__device__ __nv_bfloat16 g_Aqlo[BB*QQ*DD];
__device__ __nv_bfloat16 g_Aquhi[BB*QNN*DD];
__device__ __nv_bfloat16 g_Aqulo[BB*QNN*DD];
__device__ __nv_bfloat16 g_Wth[294912];
__device__ __nv_bfloat16 g_Wtl[294912];
#define OFF_SELF 0
#define OFF_PPW  65536
#define OFF_QQW  131072
#define OFF_PW   196608
#define OFF_QW   229376
#define OFF_QUW  262144
__device__ float g_rsp[BB*PP];
__device__ float g_rsq[BB*QQ];
__device__ float g_coefp[BB*PP];
__device__ float g_coefq[BB*QQ];
__device__ float g_coefqu[BB*QNN];
__device__ float g_sppart[BB*16*DD];
__device__ float g_sqpart[BB*8*DD];
__device__ float g_vqd[BB*DD];
__device__ float g_vqup[BB*DD];
__device__ float g_vquq[BB*DD];
__device__ float g_summ[2*BB];

// ---------------- asm helpers ----------------
#define CPA(dst, src) asm volatile("cp.async.cg.shared.global [%0], [%1], 16;" :: "r"(dst), "l"(src) : "memory")
#define CPC() asm volatile("cp.async.commit_group;" ::: "memory")
#define CPW1() asm volatile("cp.async.wait_group 1;" ::: "memory")
#define CPW0() asm volatile("cp.async.wait_group 0;" ::: "memory")
#define LDSM4(r0, r1, r2, r3, addr) \
    asm volatile("ldmatrix.sync.aligned.m8n8.x4.shared.b16 {%0,%1,%2,%3}, [%4];" \
        : "=r"(r0), "=r"(r1), "=r"(r2), "=r"(r3) : "r"(addr))

__device__ __forceinline__ void mma_bf16(float c[4], uint32_t a0, uint32_t a1,
                                         uint32_t a2, uint32_t a3,
                                         uint32_t b0, uint32_t b1) {
    asm volatile(
        "mma.sync.aligned.m16n8k16.row.col.f32.bf16.bf16.f32 "
        "{%0,%1,%2,%3}, {%4,%5,%6,%7}, {%8,%9}, {%0,%1,%2,%3};"
        : "+f"(c[0]), "+f"(c[1]), "+f"(c[2]), "+f"(c[3])
        : "r"(a0), "r"(a1), "r"(a2), "r"(a3), "r"(b0), "r"(b1));
}

// ---------------- small kernels ----------------
__global__ void summask_kernel(const int* __restrict__ pm, const int* __restrict__ qm) {
    int b = blockIdx.x, tid = threadIdx.x;
    __shared__ float red[256];
    float s = 0.f;
    for (int i = tid; i < PP; i += 256) s += (float)pm[b*PP + i];
    red[tid] = s; __syncthreads();
    for (int o = 128; o; o >>= 1) { if (tid < o) red[tid] += red[tid + o]; __syncthreads(); }
    if (tid == 0) g_summ[b] = red[0];
    __syncthreads();
    s = 0.f;
    for (int i = tid; i < QQ; i += 256) s += (float)qm[b*QQ + i];
    red[tid] = s; __syncthreads();
    for (int o = 128; o; o >>= 1) { if (tid < o) red[tid] += red[tid + o]; __syncthreads(); }
    if (tid == 0) g_summ[BB + b] = red[0];
}

// fused: G int -> bf16 + masked row-degree -> coef (p graph)
__global__ void gcoefp_kernel(const int* __restrict__ G, const int* __restrict__ pm) {
    int b = blockIdx.y;
    __shared__ float spm[PP];
    int tid = threadIdx.x;
    for (int i = tid; i < PP; i += 256) spm[i] = (float)pm[b*PP + i];
    __syncthreads();
    int warp = tid >> 5, lane = tid & 31;
    int row = blockIdx.x * 8 + warp;
    const int* g = G + ((size_t)b*PP + row) * PP;
    __nv_bfloat16* go = g_Gpbf + ((size_t)b*PP + row) * PP;
    float s = 0.f;
    for (int j = lane * 4; j < PP; j += 128) {
        int4 v = *(const int4*)(g + j);
        uint32_t r0 = (v.x ? 0x3F80u : 0u) | ((v.y ? 0x3F80u : 0u) << 16);
        uint32_t r1 = (v.z ? 0x3F80u : 0u) | ((v.w ? 0x3F80u : 0u) << 16);
        *(uint2*)(go + j) = make_uint2(r0, r1);
        s += spm[j] * (float)v.x + spm[j+1] * (float)v.y
           + spm[j+2] * (float)v.z + spm[j+3] * (float)v.w;
    }
    #pragma unroll
    for (int o = 16; o; o >>= 1) s += __shfl_xor_sync(0xffffffffu, s, o);
    if (lane == 0)
        g_coefp[b*PP + row] = pm[b*PP + row] ? 1.f / fmaxf(s, 1.f) : 0.f;
}

__global__ void gcoefq_kernel(const int* __restrict__ G, const int* __restrict__ qm) {
    int b = blockIdx.y;
    __shared__ float sqm[QQ];
    int tid = threadIdx.x;
    for (int i = tid; i < QQ; i += 256) sqm[i] = (float)qm[b*QQ + i];
    __syncthreads();
    int warp = tid >> 5, lane = tid & 31;
    int row = blockIdx.x * 8 + warp;
    const int* g = G + ((size_t)b*QQ + row) * QQ;
    __nv_bfloat16* go = g_Gqbf + ((size_t)b*QQ + row) * QQ;
    float s = 0.f;
    for (int j = lane * 4; j < QQ; j += 128) {
        int4 v = *(const int4*)(g + j);
        uint32_t r0 = (v.x ? 0x3F80u : 0u) | ((v.y ? 0x3F80u : 0u) << 16);
        uint32_t r1 = (v.z ? 0x3F80u : 0u) | ((v.w ? 0x3F80u : 0u) << 16);
        *(uint2*)(go + j) = make_uint2(r0, r1);
        s += sqm[j] * (float)v.x + sqm[j+1] * (float)v.y
           + sqm[j+2] * (float)v.z + sqm[j+3] * (float)v.w;
    }
    #pragma unroll
    for (int o = 16; o; o >>= 1) s += __shfl_xor_sync(0xffffffffu, s, o);
    if (lane == 0)
        g_coefq[b*QQ + row] = qm[b*QQ + row] ? 1.f / fmaxf(g_summ[b] + s, 1.f) : 0.f;
}

__global__ void coefqu_kernel(const int* __restrict__ qum) {
    int i = blockIdx.x * blockDim.x + threadIdx.x;
    if (i >= BB*QNN) return;
    int b = i / QNN;
    float t = g_summ[b] + g_summ[BB + b];
    g_coefqu[i] = qum[i] ? 1.f / fmaxf(t, 1.f) : 0.f;
}

// fused: node gate weights + partial weighted feature sums (no atomics)
__global__ void pws_kernel(const float* __restrict__ pcur, const float* __restrict__ qcur,
                           const int* __restrict__ pmask, const int* __restrict__ qmask,
                           const float* __restrict__ Wn, const float* __restrict__ bn) {
    int b = blockIdx.x, chunk = blockIdx.y;
    int tid = threadIdx.x, wid = tid >> 5, lane = tid & 31;
    const float* node; const int* mask; float* rsout; float* sout; int rowbase;
    if (chunk < 16) {
        node = pcur + (size_t)b*PP*DD; mask = pmask + b*PP;
        rsout = g_rsp + b*PP; sout = g_sppart + (b*16 + chunk)*DD; rowbase = chunk * 128;
    } else {
        node = qcur + (size_t)b*QQ*DD; mask = qmask + b*QQ;
        rsout = g_rsq + b*QQ; sout = g_sqpart + (b*8 + (chunk - 16))*DD; rowbase = (chunk - 16) * 128;
    }
    __shared__ float wsh[DD];
    __shared__ float wrow[128];
    for (int k = tid; k < DD; k += 256) wsh[k] = Wn[k];
    __syncthreads();
    float bv = bn[0];
    #pragma unroll
    for (int r = 0; r < 16; r++) {
        int lrow = wid * 16 + r;
        const float* nrow = node + (size_t)(rowbase + lrow) * DD;
        float s = 0.f;
        #pragma unroll
        for (int k = lane; k < DD; k += 32) s += nrow[k] * wsh[k];
        #pragma unroll
        for (int o = 16; o; o >>= 1) s += __shfl_xor_sync(0xffffffffu, s, o);
        if (lane == 0) {
            float sig = 1.f / (1.f + expf(-(s + bv)));
            float w = mask[rowbase + lrow] ? sig : 0.f;
            wrow[lrow] = w;
            rsout[rowbase + lrow] = w;
        }
    }
    __syncthreads();
    float acc = 0.f;
    #pragma unroll 4
    for (int i = 0; i < 128; i++) {
        float w = wrow[i];
        if (w != 0.f) acc += w * node[(size_t)(rowbase + i) * DD + tid];
    }
    sout[tid] = acc;
}

__global__ void vec_kernel(const float* __restrict__ Wqd, const float* __restrict__ Wqup,
                           const float* __restrict__ Wquq) {
    int b = blockIdx.x, sel = blockIdx.y, tid = threadIdx.x;
    __shared__ float sh[DD];
    const float* W = (sel == 0) ? Wqd : (sel == 1) ? Wqup : Wquq;
    float* out = (sel == 0) ? g_vqd : (sel == 1) ? g_vqup : g_vquq;
    float sv = 0.f;
    if (sel < 2) {
        #pragma unroll
        for (int c = 0; c < 16; c++) sv += g_sppart[(b*16 + c)*DD + tid];
    } else {
        #pragma unroll
        for (int c = 0; c < 8; c++) sv += g_sqpart[(b*8 + c)*DD + tid];
    }
    sh[tid] = sv;
    __syncthreads();
    float acc = 0.f;
    #pragma unroll 8
    for (int k = 0; k < DD; k++) acc += sh[k] * W[(size_t)k*DD + tid];
    out[b*DD + tid] = acc;
}

__global__ void qu_update_kernel(float* __restrict__ qunxt) {
    int r = blockIdx.x;
    int d = threadIdx.x;
    int b = r / QNN;
    float v = g_selfqu[(size_t)r*DD + d] + g_coefqu[r] * (g_vqup[b*DD + d] + g_vquq[b*DD + d]);
    qunxt[(size_t)r*DD + d] = fmaxf(v, 0.f);
}

// ---------------- split/prep ----------------
__device__ __forceinline__ void split_pack2(float x, float y, uint32_t& h, uint32_t& l) {
    __nv_bfloat16 hx = __float2bfloat16(x), hy = __float2bfloat16(y);
    float rx = x - __bfloat162float(hx), ry = y - __bfloat162float(hy);
    __nv_bfloat16 lx = __float2bfloat16(rx), ly = __float2bfloat16(ry);
    h = (uint32_t)__bfloat16_as_ushort(hy) << 16 | __bfloat16_as_ushort(hx);
    l = (uint32_t)__bfloat16_as_ushort(ly) << 16 | __bfloat16_as_ushort(lx);
}

// all three node arrays -> hi/lo bf16, one launch
__global__ void asplit_all_kernel(const float* __restrict__ P, const float* __restrict__ Q,
                                  const float* __restrict__ QU) {
    int bx = blockIdx.x;
    const float* A; __nv_bfloat16 *Ahi, *Alo; int lb;
    if (bx < 2048) { A = P; Ahi = g_Aphi; Alo = g_Aplo; lb = bx; }
    else if (bx < 3072) { A = Q; Ahi = g_Aqhi; Alo = g_Aqlo; lb = bx - 2048; }
    else { A = QU; Ahi = g_Aquhi; Alo = g_Aqulo; lb = bx - 3072; }
    size_t i4 = ((size_t)lb * 256 + threadIdx.x) * 4;
    float4 v = *(const float4*)(A + i4);
    uint32_t h0, l0, h1, l1;
    split_pack2(v.x, v.y, h0, l0);
    split_pack2(v.z, v.w, h1, l1);
    *(uint2*)(Ahi + i4) = make_uint2(h0, h1);
    *(uint2*)(Alo + i4) = make_uint2(l0, l1);
}

// all six weights: transpose + hi/lo split, one launch
__global__ void wsplit_all_kernel(const float* __restrict__ W_self, const float* __restrict__ W_pp,
                                  const float* __restrict__ W_qq, const float* __restrict__ W_p,
                                  const float* __restrict__ W_q, const float* __restrict__ W_qu) {
    int z = blockIdx.z;
    const float* W; int N; int off;
    switch (z) {
        case 0: W = W_self; N = 256; off = OFF_SELF; break;
        case 1: W = W_pp;   N = 256; off = OFF_PPW;  break;
        case 2: W = W_qq;   N = 256; off = OFF_QQW;  break;
        case 3: W = W_p;    N = 128; off = OFF_PW;   break;
        case 4: W = W_q;    N = 128; off = OFF_QW;   break;
        default: W = W_qu;  N = 128; off = OFF_QUW;  break;
    }
    int nb = blockIdx.x * 32;
    if (nb >= N) return;
    int kb = blockIdx.y * 32;
    __shared__ float T[32][33];
    int tx = threadIdx.x, ty = threadIdx.y;  // 32 x 8
    #pragma unroll
    for (int r = 0; r < 32; r += 8)
        T[ty + r][tx] = W[(size_t)(kb + ty + r) * N + nb + tx];
    __syncthreads();
    __nv_bfloat16* Wth = g_Wth + off;
    __nv_bfloat16* Wtl = g_Wtl + off;
    #pragma unroll
    for (int r = 0; r < 32; r += 8) {
        int n = nb + ty + r, k = kb + tx;
        float v = T[tx][ty + r];
        __nv_bfloat16 h = __float2bfloat16(v);
        Wth[(size_t)n * 256 + k] = h;
        Wtl[(size_t)n * 256 + k] = __float2bfloat16(v - __bfloat162float(h));
    }
}

// ---------------- shared GEMM mainloop (ldmatrix + 3-product hi/lo) ----------------
#define KCP2 40

__device__ __forceinline__ void gemm_mainloop(
        const __nv_bfloat16* __restrict__ Ahi, const __nv_bfloat16* __restrict__ Alo,
        const __nv_bfloat16* __restrict__ Wth, const __nv_bfloat16* __restrict__ Wtl,
        int bm, int bn, float c[2][8][4], char* smem) {
    __nv_bfloat16* Ah = (__nv_bfloat16*)smem;
    __nv_bfloat16* Al = (__nv_bfloat16*)(smem + 10240);
    __nv_bfloat16* Wh = (__nv_bfloat16*)(smem + 20480);
    __nv_bfloat16* Wl = (__nv_bfloat16*)(smem + 30720);
    uint32_t sb = (uint32_t)__cvta_generic_to_shared(smem);

    int tid = threadIdx.x, wid = tid >> 5, lane = tid & 31;
    int wm = wid >> 1, wn = wid & 1;
    int m8 = lane >> 3, r8 = lane & 7;
    int rowoff = r8 + ((m8 & 1) ? 8 : 0);
    int koff8 = (m8 >= 2) ? 8 : 0;

    for (int ch = 0; ch < 8; ch++) {
        int k0 = ch * 32;
        #pragma unroll
        for (int it = 0; it < 2; it++) {
            int u = tid + it * 256;
            int row = u >> 2, c8 = u & 3;
            size_t src = (size_t)(bm + row) * DD + k0 + c8 * 8;
            *(uint4*)(Ah + row * KCP2 + c8 * 8) = *(const uint4*)(Ahi + src);
            *(uint4*)(Al + row * KCP2 + c8 * 8) = *(const uint4*)(Alo + src);
        }
        #pragma unroll
        for (int it = 0; it < 2; it++) {
            int u = tid + it * 256;
            int n = u >> 2, c8 = u & 3;
            size_t src = (size_t)(bn + n) * 256 + k0 + c8 * 8;
            *(uint4*)(Wh + n * KCP2 + c8 * 8) = *(const uint4*)(Wth + src);
            *(uint4*)(Wl + n * KCP2 + c8 * 8) = *(const uint4*)(Wtl + src);
        }
        __syncthreads();
        #pragma unroll
        for (int kt = 0; kt < 2; kt++) {
            int kcol = kt * 16 + koff8;
            uint32_t ah[2][4], al[2][4];
            #pragma unroll
            for (int mt = 0; mt < 2; mt++) {
                uint32_t aoff = (uint32_t)((wm*32 + mt*16 + rowoff) * KCP2 + kcol) * 2;
                LDSM4(ah[mt][0], ah[mt][1], ah[mt][2], ah[mt][3], sb + aoff);
                LDSM4(al[mt][0], al[mt][1], al[mt][2], al[mt][3], sb + 10240 + aoff);
            }
            #pragma unroll
            for (int j = 0; j < 4; j++) {
                uint32_t woff = (uint32_t)((wn*64 + j*16 + rowoff) * KCP2 + kcol) * 2;
                uint32_t wh0, wh1, wh2, wh3, wl0, wl1, wl2, wl3;
                LDSM4(wh0, wh1, wh2, wh3, sb + 20480 + woff);
                LDSM4(wl0, wl1, wl2, wl3, sb + 30720 + woff);
                #pragma unroll
                for (int mt = 0; mt < 2; mt++) {
                    mma_bf16(c[mt][2*j],   ah[mt][0], ah[mt][1], ah[mt][2], ah[mt][3], wh0, wh2);
                    mma_bf16(c[mt][2*j],   al[mt][0], al[mt][1], al[mt][2], al[mt][3], wh0, wh2);
                    mma_bf16(c[mt][2*j],   ah[mt][0], ah[mt][1], ah[mt][2], ah[mt][3], wl0, wl2);
                    mma_bf16(c[mt][2*j+1], ah[mt][0], ah[mt][1], ah[mt][2], ah[mt][3], wh1, wh3);
                    mma_bf16(c[mt][2*j+1], al[mt][0], al[mt][1], al[mt][2], al[mt][3], wh1, wh3);
                    mma_bf16(c[mt][2*j+1], ah[mt][0], ah[mt][1], ah[mt][2], ah[mt][3], wl1, wl3);
                }
            }
        }
        __syncthreads();
    }
}

// step-phase GEMM: by<2 -> self(C+bias), by>=2 -> Y transposed hi/lo
__global__ __launch_bounds__(256)
void gemm_step_kernel(const __nv_bfloat16* __restrict__ Ahi, const __nv_bfloat16* __restrict__ Alo,
                      const __nv_bfloat16* __restrict__ WthS, const __nv_bfloat16* __restrict__ WtlS,
                      const __nv_bfloat16* __restrict__ WthY, const __nv_bfloat16* __restrict__ WtlY,
                      float* __restrict__ Cself, const float* __restrict__ bias,
                      const float* __restrict__ rowscale,
                      __nv_bfloat16* __restrict__ Yhi, __nv_bfloat16* __restrict__ Ylo,
                      int NNbatch) {
    __shared__ char smem[40960];
    int by = blockIdx.y;
    int mode = by >> 1;
    int bm = blockIdx.x * 128, bn = (by & 1) * 128;
    const __nv_bfloat16* Wth = mode ? WthY : WthS;
    const __nv_bfloat16* Wtl = mode ? WtlY : WtlS;

    float c[2][8][4];
    #pragma unroll
    for (int mt = 0; mt < 2; mt++)
        #pragma unroll
        for (int nt = 0; nt < 8; nt++)
            #pragma unroll
            for (int r = 0; r < 4; r++) c[mt][nt][r] = 0.f;

    gemm_mainloop(Ahi, Alo, Wth, Wtl, bm, bn, c, smem);

    int tid = threadIdx.x, wid = tid >> 5, lane = tid & 31;
    int wm = wid >> 1, wn = wid & 1;
    if (mode == 0) {
        #pragma unroll
        for (int mt = 0; mt < 2; mt++)
            #pragma unroll
            for (int h = 0; h < 2; h++) {
                int row = bm + wm * 32 + mt * 16 + (lane >> 2) + h * 8;
                float* orow = Cself + (size_t)row * DD;
                #pragma unroll
                for (int nt = 0; nt < 8; nt++) {
                    int col = bn + wn * 64 + nt * 8 + (lane & 3) * 2;
                    float2 o;
                    o.x = c[mt][nt][h * 2 + 0] + bias[col];
                    o.y = c[mt][nt][h * 2 + 1] + bias[col + 1];
                    *(float2*)(orow + col) = o;
                }
            }
    } else {
        #pragma unroll
        for (int mt = 0; mt < 2; mt++)
            #pragma unroll
            for (int h = 0; h < 2; h++) {
                int gr = bm + wm * 32 + mt * 16 + (lane >> 2) + h * 8;
                float rs = rowscale[gr];
                int b = gr / NNbatch;
                int i = gr - b * NNbatch;
                #pragma unroll
                for (int nt = 0; nt < 8; nt++) {
                    int col = bn + wn * 64 + nt * 8 + (lane & 3) * 2;
                    size_t base = ((size_t)b * DD + col) * NNbatch + i;
                    float v0 = c[mt][nt][h * 2 + 0] * rs;
                    float v1 = c[mt][nt][h * 2 + 1] * rs;
                    __nv_bfloat16 h0 = __float2bfloat16(v0);
                    __nv_bfloat16 h1 = __float2bfloat16(v1);
                    Yhi[base] = h0;
                    Yhi[base + NNbatch] = h1;
                    Ylo[base] = __float2bfloat16(v0 - __bfloat162float(h0));
                    Ylo[base + NNbatch] = __float2bfloat16(v1 - __bfloat162float(h1));
                }
            }
    }
}

// merged output projections: blocks [0,64) p, [64,96) q, 96 qu; N = HH
__global__ __launch_bounds__(256)
void gemm_out_kernel(const float* __restrict__ b_p, const float* __restrict__ b_q,
                     const float* __restrict__ b_qu, float* __restrict__ out) {
    __shared__ char smem[40960];
    int bx = blockIdx.x;
    const __nv_bfloat16 *Ahi, *Alo, *Wth, *Wtl; const float* bias; float* O; int bm;
    if (bx < 64) {
        Ahi = g_Aphi; Alo = g_Aplo; Wth = g_Wth + OFF_PW; Wtl = g_Wtl + OFF_PW;
        bias = b_p; O = out; bm = bx * 128;
    } else if (bx < 96) {
        Ahi = g_Aqhi; Alo = g_Aqlo; Wth = g_Wth + OFF_QW; Wtl = g_Wtl + OFF_QW;
        bias = b_q; O = out + (size_t)BB*PP*HH; bm = (bx - 64) * 128;
    } else {
        Ahi = g_Aquhi; Alo = g_Aqulo; Wth = g_Wth + OFF_QUW; Wtl = g_Wtl + OFF_QUW;
        bias = b_qu; O = out + (size_t)BB*PP*HH + (size_t)BB*QQ*HH; bm = 0;
    }
    float c[2][8][4];
    #pragma unroll
    for (int mt = 0; mt < 2; mt++)
        #pragma unroll
        for (int nt = 0; nt < 8; nt++)
            #pragma unroll
            for (int r = 0; r < 4; r++) c[mt][nt][r] = 0.f;

    gemm_mainloop(Ahi, Alo, Wth, Wtl, bm, 0, c, smem);

    int tid = threadIdx.x, wid = tid >> 5, lane = tid & 31;
    int wm = wid >> 1, wn = wid & 1;
    // wn==0 covers cols 0..63, wn==1 covers cols 64..127 (all valid for N=HH=128)
    #pragma unroll
    for (int mt = 0; mt < 2; mt++)
        #pragma unroll
        for (int h = 0; h < 2; h++) {
            int row = bm + wm * 32 + mt * 16 + (lane >> 2) + h * 8;
            float* orow = O + (size_t)row * HH;
            #pragma unroll
            for (int nt = 0; nt < 8; nt++) {
                int col = wn * 64 + nt * 8 + (lane & 3) * 2;
                float2 o;
                o.x = c[mt][nt][h * 2 + 0] + bias[col];
                o.y = c[mt][nt][h * 2 + 1] + bias[col + 1];
                *(float2*)(orow + col) = o;
            }
        }
}

// ---------------- pipelined HMMA adjacency aggregation (ldmatrix) ----------------
#define KC 32
#define KCP 40
#define ADJ_SMEM 92160
#define AS_BYTES 5120
#define BH_BYTES 20480

__global__ __launch_bounds__(256)
void adj_hmma_kernel(const __nv_bfloat16* __restrict__ Yphi, const __nv_bfloat16* __restrict__ Yplo,
                     const __nv_bfloat16* __restrict__ Yqhi, const __nv_bfloat16* __restrict__ Yqlo,
                     const float* __restrict__ selfp, const float* __restrict__ selfq,
                     const float* __restrict__ coefp, const float* __restrict__ coefq,
                     const float* __restrict__ vqd,
                     float* __restrict__ Op, float* __restrict__ Oq) {
    extern __shared__ __align__(16) char dsm[];
    uint32_t smemBase = (uint32_t)__cvta_generic_to_shared(dsm);

    int bx = blockIdx.x;
    const __nv_bfloat16 *Gbf, *Yh, *Yl; const float *S, *coef, *ev;
    float* O; int NN, b, mtile;
    if (bx < BB * (PP/64)) {
        b = bx >> 5; mtile = bx & 31; NN = PP;
        Gbf = g_Gpbf + (size_t)b*PP*PP;
        Yh = Yphi + (size_t)b*DD*PP;  Yl = Yplo + (size_t)b*DD*PP;
        S = selfp + (size_t)b*PP*DD;  coef = coefp + b*PP;
        ev = nullptr;                 O = Op + (size_t)b*PP*DD;
    } else {
        int i2 = bx - BB * (PP/64);
        b = i2 >> 4; mtile = i2 & 15; NN = QQ;
        Gbf = g_Gqbf + (size_t)b*QQ*QQ;
        Yh = Yqhi + (size_t)b*DD*QQ;  Yl = Yqlo + (size_t)b*DD*QQ;
        S = selfq + (size_t)b*QQ*DD;  coef = coefq + b*QQ;
        ev = vqd + b*DD;              O = Oq + (size_t)b*QQ*DD;
    }
    int bm = mtile * 64;
    int tid = threadIdx.x, wid = tid >> 5, lane = tid & 31;
    int wm = wid >> 2, wn = wid & 3;
    int m8 = lane >> 3, r8 = lane & 7;
    int rowoff = r8 + ((m8 & 1) ? 8 : 0);
    int koff8 = (m8 >= 2) ? 8 : 0;

    float c[2][8][4];
    #pragma unroll
    for (int mt = 0; mt < 2; mt++)
        #pragma unroll
        for (int nt = 0; nt < 8; nt++)
            #pragma unroll
            for (int r = 0; r < 4; r++) c[mt][nt][r] = 0.f;

    int arow = tid >> 2, ac8 = tid & 3;

    auto issue = [&](int k0, int bufi) {
        uint32_t asb = smemBase + bufi * AS_BYTES;
        CPA(asb + arow * 80 + ac8 * 16, Gbf + (size_t)(bm + arow) * NN + k0 + ac8 * 8);
        uint32_t bhb = smemBase + 2 * AS_BYTES + bufi * BH_BYTES;
        uint32_t blb = smemBase + 2 * AS_BYTES + 2 * BH_BYTES + bufi * BH_BYTES;
        #pragma unroll
        for (int it = 0; it < 4; it++) {
            int idx = tid + it * 256;
            int d = idx >> 2, c8 = idx & 3;
            size_t src = (size_t)d * NN + k0 + c8 * 8;
            CPA(bhb + d * 80 + c8 * 16, Yh + src);
            CPA(blb + d * 80 + c8 * 16, Yl + src);
        }
    };

    const int nchunks = NN / KC;
    issue(0, 0);
    CPC();
    int buf = 0;
    for (int ch = 0; ch < nchunks; ch++) {
        bool hn = (ch + 1 < nchunks);
        if (hn) { issue((ch + 1) * KC, buf ^ 1); CPC(); }
        if (hn) { CPW1(); } else { CPW0(); }
        __syncthreads();

        uint32_t asB = smemBase + buf * AS_BYTES;
        uint32_t bhB = smemBase + 2 * AS_BYTES + buf * BH_BYTES;
        uint32_t blB = smemBase + 2 * AS_BYTES + 2 * BH_BYTES + buf * BH_BYTES;

        #pragma unroll
        for (int kt = 0; kt < 2; kt++) {
            int kcol = kt * 16 + koff8;
            uint32_t a[2][4];
            #pragma unroll
            for (int mt = 0; mt < 2; mt++) {
                uint32_t aoff = (uint32_t)((wm*32 + mt*16 + rowoff) * KCP + kcol) * 2;
                LDSM4(a[mt][0], a[mt][1], a[mt][2], a[mt][3], asB + aoff);
            }
            #pragma unroll
            for (int j = 0; j < 4; j++) {
                uint32_t boff = (uint32_t)((wn*64 + j*16 + rowoff) * KCP + kcol) * 2;
                uint32_t bh0, bh1, bh2, bh3, bl0, bl1, bl2, bl3;
                LDSM4(bh0, bh1, bh2, bh3, bhB + boff);
                LDSM4(bl0, bl1, bl2, bl3, blB + boff);
                mma_bf16(c[0][2*j],   a[0][0], a[0][1], a[0][2], a[0][3], bh0, bh2);
                mma_bf16(c[1][2*j],   a[1][0], a[1][1], a[1][2], a[1][3], bh0, bh2);
                mma_bf16(c[0][2*j],   a[0][0], a[0][1], a[0][2], a[0][3], bl0, bl2);
                mma_bf16(c[1][2*j],   a[1][0], a[1][1], a[1][2], a[1][3], bl0, bl2);
                mma_bf16(c[0][2*j+1], a[0][0], a[0][1], a[0][2], a[0][3], bh1, bh3);
                mma_bf16(c[1][2*j+1], a[1][0], a[1][1], a[1][2], a[1][3], bh1, bh3);
                mma_bf16(c[0][2*j+1], a[0][0], a[0][1], a[0][2], a[0][3], bl1, bl3);
                mma_bf16(c[1][2*j+1], a[1][0], a[1][1], a[1][2], a[1][3], bl1, bl3);
            }
        }
        __syncthreads();
        buf ^= 1;
    }

    #pragma unroll
    for (int mt = 0; mt < 2; mt++) {
        #pragma unroll
        for (int h = 0; h < 2; h++) {
            int row = bm + wm * 32 + mt * 16 + (lane >> 2) + h * 8;
            float cf = coef[row];
            const float* srow = S + (size_t)row * DD;
            float* orow = O + (size_t)row * DD;
            #pragma unroll
            for (int nt = 0; nt < 8; nt++) {
                int col = wn * 64 + nt * 8 + (lane & 3) * 2;
                float v0 = c[mt][nt][h * 2 + 0];
                float v1 = c[mt][nt][h * 2 + 1];
                if (ev) { v0 += ev[col]; v1 += ev[col + 1]; }
                float2 s2 = *(const float2*)(srow + col);
                float2 o;
                o.x = fmaxf(s2.x + cf * v0, 0.f);
                o.y = fmaxf(s2.y + cf * v1, 0.f);
                *(float2*)(orow + col) = o;
            }
        }
    }
}

// ---------------- launch ----------------
extern "C" void kernel_launch(void* const* d_in, const int* in_sizes, int n_in,
                              void* d_out, int out_size) {
    const float* p_in   = (const float*)d_in[0];
    const float* q_in   = (const float*)d_in[1];
    const float* qu_in  = (const float*)d_in[2];
    const int*   pmask  = (const int*)d_in[3];
    const int*   qmask  = (const int*)d_in[4];
    const int*   qumask = (const int*)d_in[5];
    const int*   ppg    = (const int*)d_in[6];
    const int*   qqg    = (const int*)d_in[7];
    const float* W_node = (const float*)d_in[10];
    const float* b_node = (const float*)d_in[11];
    const float* W_self = (const float*)d_in[12];
    const float* b_self = (const float*)d_in[13];
    const float* W_pp   = (const float*)d_in[14];
    const float* W_qd   = (const float*)d_in[15];
    const float* W_qq   = (const float*)d_in[16];
    const float* W_qup  = (const float*)d_in[17];
    const float* W_quq  = (const float*)d_in[18];
    const float* W_p    = (const float*)d_in[19];
    const float* b_p    = (const float*)d_in[20];
    const float* W_q    = (const float*)d_in[21];
    const float* b_q    = (const float*)d_in[22];
    const float* W_qu   = (const float*)d_in[23];
    const float* b_qu   = (const float*)d_in[24];
    float* out = (float*)d_out;

    float *pA, *pB, *qA, *qB, *quA, *quB, *selfp, *selfq, *selfqu;
    float *rsp, *rsq, *coefp, *coefq, *vqd;
    __nv_bfloat16 *Yphi, *Yplo, *Yqhi, *Yqlo, *Wth, *Wtl;
    __nv_bfloat16 *Aphi, *Aplo, *Aqhi, *Aqlo, *Aquhi, *Aqulo;
    cudaGetSymbolAddress((void**)&pA, g_pA);
    cudaGetSymbolAddress((void**)&pB, g_pB);
    cudaGetSymbolAddress((void**)&qA, g_qA);
    cudaGetSymbolAddress((void**)&qB, g_qB);
    cudaGetSymbolAddress((void**)&quA, g_quA);
    cudaGetSymbolAddress((void**)&quB, g_quB);
    cudaGetSymbolAddress((void**)&selfp, g_selfp);
    cudaGetSymbolAddress((void**)&selfq, g_selfq);
    cudaGetSymbolAddress((void**)&selfqu, g_selfqu);
    cudaGetSymbolAddress((void**)&rsp, g_rsp);
    cudaGetSymbolAddress((void**)&rsq, g_rsq);
    cudaGetSymbolAddress((void**)&coefp, g_coefp);
    cudaGetSymbolAddress((void**)&coefq, g_coefq);
    cudaGetSymbolAddress((void**)&vqd, g_vqd);
    cudaGetSymbolAddress((void**)&Yphi, g_Yphi);
    cudaGetSymbolAddress((void**)&Yplo, g_Yplo);
    cudaGetSymbolAddress((void**)&Yqhi, g_Yqhi);
    cudaGetSymbolAddress((void**)&Yqlo, g_Yqlo);
    cudaGetSymbolAddress((void**)&Wth, g_Wth);
    cudaGetSymbolAddress((void**)&Wtl, g_Wtl);
    cudaGetSymbolAddress((void**)&Aphi, g_Aphi);
    cudaGetSymbolAddress((void**)&Aplo, g_Aplo);
    cudaGetSymbolAddress((void**)&Aqhi, g_Aqhi);
    cudaGetSymbolAddress((void**)&Aqlo, g_Aqlo);
    cudaGetSymbolAddress((void**)&Aquhi, g_Aquhi);
    cudaGetSymbolAddress((void**)&Aqulo, g_Aqulo);

    cudaFuncSetAttribute(adj_hmma_kernel, cudaFuncAttributeMaxDynamicSharedMemorySize, ADJ_SMEM);

    // prep: mask sums, fused G->bf16+coef, weight splits
    summask_kernel<<<BB, 256>>>(pmask, qmask);
    gcoefp_kernel<<<dim3(PP/8, BB), 256>>>(ppg, pmask);
    gcoefq_kernel<<<dim3(QQ/8, BB), 256>>>(qqg, qmask);
    coefqu_kernel<<<1, 128>>>(qumask);
    wsplit_all_kernel<<<dim3(8, 8, 6), dim3(32, 8)>>>(W_self, W_pp, W_qq, W_p, W_q, W_qu);

    const float* pc = p_in;  const float* qc = q_in;  const float* quc = qu_in;
    float* pn = pA;  float* qn = qA;  float* qun = quA;

    for (int step = 0; step < 2; step++) {
        pws_kernel<<<dim3(BB, 24), 256>>>(pc, qc, pmask, qmask, W_node, b_node);
        vec_kernel<<<dim3(BB, 3), 256>>>(W_qd, W_qup, W_quq);
        asplit_all_kernel<<<3104, 256>>>(pc, qc, quc);

        gemm_step_kernel<<<dim3(BB*PP/128, 4), 256>>>(Aphi, Aplo,
            Wth + OFF_SELF, Wtl + OFF_SELF, Wth + OFF_PPW, Wtl + OFF_PPW,
            selfp, b_self, rsp, Yphi, Yplo, PP);
        gemm_step_kernel<<<dim3(BB*QQ/128, 4), 256>>>(Aqhi, Aqlo,
            Wth + OFF_SELF, Wtl + OFF_SELF, Wth + OFF_QQW, Wtl + OFF_QQW,
            selfq, b_self, rsq, Yqhi, Yqlo, QQ);
        gemm_step_kernel<<<dim3(1, 2), 256>>>(Aquhi, Aqulo,
            Wth + OFF_SELF, Wtl + OFF_SELF, Wth + OFF_SELF, Wtl + OFF_SELF,
            selfqu, b_self, nullptr, nullptr, nullptr, 0);

        adj_hmma_kernel<<<BB*(PP/64) + BB*(QQ/64), 256, ADJ_SMEM>>>(
            Yphi, Yplo, Yqhi, Yqlo, selfp, selfq, coefp, coefq, vqd, pn, qn);
        qu_update_kernel<<<BB*QNN, DD>>>(qun);

        pc = pn; qc = qn; quc = qun;
        pn = pB; qn = qB; qun = quB;
    }

    // output projections
    asplit_all_kernel<<<3104, 256>>>(pc, qc, quc);
    gemm_out_kernel<<<97, 256>>>(b_p, b_q, b_qu, out);
}

// round 9
// speedup vs baseline: 3.1052x; 1.3143x over previous
#include <cuda_runtime.h>
#include <cuda_bf16.h>
#include <math.h>
#include <stdint.h>

#define BB  4
#define PP  2048
#define QQ  1024
#define QNN 32
#define DD  256
#define HH  128

// ---------------- persistent scratch ----------------
__device__ float g_pA[BB*PP*DD];
__device__ float g_pB[BB*PP*DD];
__device__ float g_qA[BB*QQ*DD];
__device__ float g_qB[BB*QQ*DD];
__device__ float g_quA[BB*QNN*DD];
__device__ float g_quB[BB*QNN*DD];
__device__ float g_selfp[BB*PP*DD];
__device__ float g_selfq[BB*QQ*DD];
__device__ float g_selfqu[BB*QNN*DD];
__device__ __nv_bfloat16 g_Yphi[BB*DD*PP];
__device__ __nv_bfloat16 g_Yplo[BB*DD*PP];
__device__ __nv_bfloat16 g_Yqhi[BB*DD*QQ];
__device__ __nv_bfloat16 g_Yqlo[BB*DD*QQ];
__device__ __nv_bfloat16 g_Gpbf[(size_t)BB*PP*PP];
__device__ __nv_bfloat16 g_Gqbf[(size_t)BB*QQ*QQ];
__device__ __nv_bfloat16 g_Aphi[BB*PP*DD];
__device__ __nv_bfloat16 g_Aplo[BB*PP*DD];
__device__ __nv_bfloat16 g_Aqhi[BB*QQ*DD];
__device__ __nv_bfloat16 g_Aqlo[BB*QQ*DD];
__device__ __nv_bfloat16 g_Aquhi[BB*QNN*DD];
__device__ __nv_bfloat16 g_Aqulo[BB*QNN*DD];
__device__ __nv_bfloat16 g_Wth[294912];
__device__ __nv_bfloat16 g_Wtl[294912];
#define OFF_SELF 0
#define OFF_PPW  65536
#define OFF_QQW  131072
#define OFF_PW   196608
#define OFF_QW   229376
#define OFF_QUW  262144
__device__ float g_rsp[BB*PP];
__device__ float g_rsq[BB*QQ];
__device__ float g_coefp[BB*PP];
__device__ float g_coefq[BB*QQ];
__device__ float g_coefqu[BB*QNN];
__device__ float g_sppart[BB*16*DD];
__device__ float g_sqpart[BB*8*DD];
__device__ float g_vqd[BB*DD];
__device__ float g_vqup[BB*DD];
__device__ float g_vquq[BB*DD];

// ---------------- asm helpers ----------------
#define CPA(dst, src) asm volatile("cp.async.cg.shared.global [%0], [%1], 16;" :: "r"(dst), "l"(src) : "memory")
#define CPC() asm volatile("cp.async.commit_group;" ::: "memory")
#define CPW1() asm volatile("cp.async.wait_group 1;" ::: "memory")
#define CPW0() asm volatile("cp.async.wait_group 0;" ::: "memory")
#define LDSM4(r0, r1, r2, r3, addr) \
    asm volatile("ldmatrix.sync.aligned.m8n8.x4.shared.b16 {%0,%1,%2,%3}, [%4];" \
        : "=r"(r0), "=r"(r1), "=r"(r2), "=r"(r3) : "r"(addr))

__device__ __forceinline__ void mma_bf16(float c[4], uint32_t a0, uint32_t a1,
                                         uint32_t a2, uint32_t a3,
                                         uint32_t b0, uint32_t b1) {
    asm volatile(
        "mma.sync.aligned.m16n8k16.row.col.f32.bf16.bf16.f32 "
        "{%0,%1,%2,%3}, {%4,%5,%6,%7}, {%8,%9}, {%0,%1,%2,%3};"
        : "+f"(c[0]), "+f"(c[1]), "+f"(c[2]), "+f"(c[3])
        : "r"(a0), "r"(a1), "r"(a2), "r"(a3), "r"(b0), "r"(b1));
}

__device__ __forceinline__ void split_pack2(float x, float y, uint32_t& h, uint32_t& l) {
    __nv_bfloat16 hx = __float2bfloat16(x), hy = __float2bfloat16(y);
    float rx = x - __bfloat162float(hx), ry = y - __bfloat162float(hy);
    __nv_bfloat16 lx = __float2bfloat16(rx), ly = __float2bfloat16(ry);
    h = (uint32_t)__bfloat16_as_ushort(hy) << 16 | __bfloat16_as_ushort(hx);
    l = (uint32_t)__bfloat16_as_ushort(ly) << 16 | __bfloat16_as_ushort(lx);
}

// ---------------- PREP über-kernel ----------------
// [0,1024)  gcoefp: G_p int->bf16 + coef_p
// [1024,1536) gcoefq: G_q int->bf16 + coef_q (recomputes sum_pm per block)
// 1536      coefqu (recomputes sums)
// [1537,1921) wsplit (6 weights)
__global__ __launch_bounds__(256)
void prep_kernel(const int* __restrict__ Gp, const int* __restrict__ Gq,
                 const int* __restrict__ pm, const int* __restrict__ qm,
                 const int* __restrict__ qum,
                 const float* __restrict__ W_self, const float* __restrict__ W_pp,
                 const float* __restrict__ W_qq, const float* __restrict__ W_p,
                 const float* __restrict__ W_q, const float* __restrict__ W_qu) {
    __shared__ float shp[2112];
    int bx = blockIdx.x, tid = threadIdx.x;
    if (bx < 1024) {
        int b = bx >> 8, xtile = bx & 255;
        for (int i = tid; i < PP; i += 256) shp[i] = (float)pm[b*PP + i];
        __syncthreads();
        int warp = tid >> 5, lane = tid & 31;
        int row = xtile * 8 + warp;
        const int* g = Gp + ((size_t)b*PP + row) * PP;
        __nv_bfloat16* go = g_Gpbf + ((size_t)b*PP + row) * PP;
        float s = 0.f;
        for (int j = lane * 4; j < PP; j += 128) {
            int4 v = *(const int4*)(g + j);
            uint32_t r0 = (v.x ? 0x3F80u : 0u) | ((v.y ? 0x3F80u : 0u) << 16);
            uint32_t r1 = (v.z ? 0x3F80u : 0u) | ((v.w ? 0x3F80u : 0u) << 16);
            *(uint2*)(go + j) = make_uint2(r0, r1);
            s += shp[j] * (float)v.x + shp[j+1] * (float)v.y
               + shp[j+2] * (float)v.z + shp[j+3] * (float)v.w;
        }
        #pragma unroll
        for (int o = 16; o; o >>= 1) s += __shfl_xor_sync(0xffffffffu, s, o);
        if (lane == 0)
            g_coefp[b*PP + row] = pm[b*PP + row] ? 1.f / fmaxf(s, 1.f) : 0.f;
    } else if (bx < 1536) {
        int i2 = bx - 1024;
        int b = i2 >> 7, xtile = i2 & 127;
        // block-local sum of pm[b]
        float ps = 0.f;
        for (int i = tid; i < PP; i += 256) ps += (float)pm[b*PP + i];
        for (int i = tid; i < QQ; i += 256) shp[i] = (float)qm[b*QQ + i];
        shp[1024 + tid] = ps;
        __syncthreads();
        if (tid < 128) shp[1024 + tid] += shp[1024 + tid + 128];
        __syncthreads();
        if (tid < 64) shp[1024 + tid] += shp[1024 + tid + 64];
        __syncthreads();
        if (tid < 32) {
            float v = shp[1024 + tid] + shp[1024 + tid + 32];
            #pragma unroll
            for (int o = 16; o; o >>= 1) v += __shfl_xor_sync(0xffffffffu, v, o);
            if (tid == 0) shp[2048] = v;
        }
        __syncthreads();
        float psum = shp[2048];
        int warp = tid >> 5, lane = tid & 31;
        int row = xtile * 8 + warp;
        const int* g = Gq + ((size_t)b*QQ + row) * QQ;
        __nv_bfloat16* go = g_Gqbf + ((size_t)b*QQ + row) * QQ;
        float s = 0.f;
        for (int j = lane * 4; j < QQ; j += 128) {
            int4 v = *(const int4*)(g + j);
            uint32_t r0 = (v.x ? 0x3F80u : 0u) | ((v.y ? 0x3F80u : 0u) << 16);
            uint32_t r1 = (v.z ? 0x3F80u : 0u) | ((v.w ? 0x3F80u : 0u) << 16);
            *(uint2*)(go + j) = make_uint2(r0, r1);
            s += shp[j] * (float)v.x + shp[j+1] * (float)v.y
               + shp[j+2] * (float)v.z + shp[j+3] * (float)v.w;
        }
        #pragma unroll
        for (int o = 16; o; o >>= 1) s += __shfl_xor_sync(0xffffffffu, s, o);
        if (lane == 0)
            g_coefq[b*QQ + row] = qm[b*QQ + row] ? 1.f / fmaxf(psum + s, 1.f) : 0.f;
    } else if (bx == 1536) {
        // coefqu: recompute sums per b
        for (int b = 0; b < BB; b++) {
            float s = 0.f;
            for (int i = tid; i < PP; i += 256) s += (float)pm[b*PP + i];
            for (int i = tid; i < QQ; i += 256) s += (float)qm[b*QQ + i];
            shp[tid] = s;
            __syncthreads();
            for (int o = 128; o; o >>= 1) { if (tid < o) shp[tid] += shp[tid + o]; __syncthreads(); }
            if (tid == 0) shp[1024 + b] = shp[0];
            __syncthreads();
        }
        if (tid < BB*QNN) {
            int b = tid / QNN;
            g_coefqu[tid] = qum[tid] ? 1.f / fmaxf(shp[1024 + b], 1.f) : 0.f;
        }
    } else {
        // wsplit: 384 blocks
        int w = bx - 1537;
        int z = w / 64, ww = w % 64;
        const float* W; int N; int off;
        switch (z) {
            case 0: W = W_self; N = 256; off = OFF_SELF; break;
            case 1: W = W_pp;   N = 256; off = OFF_PPW;  break;
            case 2: W = W_qq;   N = 256; off = OFF_QQW;  break;
            case 3: W = W_p;    N = 128; off = OFF_PW;   break;
            case 4: W = W_q;    N = 128; off = OFF_QW;   break;
            default: W = W_qu;  N = 128; off = OFF_QUW;  break;
        }
        int nb = (ww & 7) * 32, kb = (ww >> 3) * 32;
        if (nb >= N) return;
        int tx = tid & 31, ty = tid >> 5;
        #pragma unroll
        for (int r = 0; r < 32; r += 8)
            shp[(ty + r) * 33 + tx] = W[(size_t)(kb + ty + r) * N + nb + tx];
        __syncthreads();
        __nv_bfloat16* Wth = g_Wth + off;
        __nv_bfloat16* Wtl = g_Wtl + off;
        #pragma unroll
        for (int r = 0; r < 32; r += 8) {
            int n = nb + ty + r, k = kb + tx;
            float v = shp[tx * 33 + ty + r];
            __nv_bfloat16 h = __float2bfloat16(v);
            Wth[(size_t)n * 256 + k] = h;
            Wtl[(size_t)n * 256 + k] = __float2bfloat16(v - __bfloat162float(h));
        }
    }
}

// ---------------- asplit body + standalone ----------------
__device__ __forceinline__ void asplit_body(int lb, const float* __restrict__ P,
                                            const float* __restrict__ Q,
                                            const float* __restrict__ QU) {
    const float* A; __nv_bfloat16 *Ahi, *Alo; int l2;
    if (lb < 2048) { A = P; Ahi = g_Aphi; Alo = g_Aplo; l2 = lb; }
    else if (lb < 3072) { A = Q; Ahi = g_Aqhi; Alo = g_Aqlo; l2 = lb - 2048; }
    else { A = QU; Ahi = g_Aquhi; Alo = g_Aqulo; l2 = lb - 3072; }
    size_t i4 = ((size_t)l2 * 256 + threadIdx.x) * 4;
    float4 v = *(const float4*)(A + i4);
    uint32_t h0, l0, h1, l1;
    split_pack2(v.x, v.y, h0, l0);
    split_pack2(v.z, v.w, h1, l1);
    *(uint2*)(Ahi + i4) = make_uint2(h0, h1);
    *(uint2*)(Alo + i4) = make_uint2(l0, l1);
}

__global__ void asplit_all_kernel(const float* __restrict__ P, const float* __restrict__ Q,
                                  const float* __restrict__ QU) {
    asplit_body(blockIdx.x, P, Q, QU);
}

// ---------------- step-pre über-kernel: pws + asplit ----------------
__global__ __launch_bounds__(256)
void steppre_kernel(const float* __restrict__ pcur, const float* __restrict__ qcur,
                    const float* __restrict__ qucur,
                    const int* __restrict__ pmask, const int* __restrict__ qmask,
                    const float* __restrict__ Wn, const float* __restrict__ bn) {
    int bx = blockIdx.x;
    if (bx >= 96) { asplit_body(bx - 96, pcur, qcur, qucur); return; }
    int b = bx / 24, chunk = bx % 24;
    int tid = threadIdx.x, wid = tid >> 5, lane = tid & 31;
    const float* node; const int* mask; float* rsout; float* sout; int rowbase;
    if (chunk < 16) {
        node = pcur + (size_t)b*PP*DD; mask = pmask + b*PP;
        rsout = g_rsp + b*PP; sout = g_sppart + (b*16 + chunk)*DD; rowbase = chunk * 128;
    } else {
        node = qcur + (size_t)b*QQ*DD; mask = qmask + b*QQ;
        rsout = g_rsq + b*QQ; sout = g_sqpart + (b*8 + (chunk - 16))*DD; rowbase = (chunk - 16) * 128;
    }
    __shared__ float wsh[DD];
    __shared__ float wrow[128];
    for (int k = tid; k < DD; k += 256) wsh[k] = Wn[k];
    __syncthreads();
    float bv = bn[0];
    #pragma unroll
    for (int r = 0; r < 16; r++) {
        int lrow = wid * 16 + r;
        const float* nrow = node + (size_t)(rowbase + lrow) * DD;
        float s = 0.f;
        #pragma unroll
        for (int k = lane; k < DD; k += 32) s += nrow[k] * wsh[k];
        #pragma unroll
        for (int o = 16; o; o >>= 1) s += __shfl_xor_sync(0xffffffffu, s, o);
        if (lane == 0) {
            float sig = 1.f / (1.f + expf(-(s + bv)));
            float w = mask[rowbase + lrow] ? sig : 0.f;
            wrow[lrow] = w;
            rsout[rowbase + lrow] = w;
        }
    }
    __syncthreads();
    float acc = 0.f;
    #pragma unroll 4
    for (int i = 0; i < 128; i++) {
        float w = wrow[i];
        if (w != 0.f) acc += w * node[(size_t)(rowbase + i) * DD + tid];
    }
    sout[tid] = acc;
}

// ---------------- shared GEMM mainloop (ldmatrix + 3-product hi/lo) ----------------
#define KCP2 40

__device__ __forceinline__ void gemm_mainloop(
        const __nv_bfloat16* __restrict__ Ahi, const __nv_bfloat16* __restrict__ Alo,
        const __nv_bfloat16* __restrict__ Wth, const __nv_bfloat16* __restrict__ Wtl,
        int bm, int bn, float c[2][8][4], char* smem) {
    __nv_bfloat16* Ah = (__nv_bfloat16*)smem;
    __nv_bfloat16* Al = (__nv_bfloat16*)(smem + 10240);
    __nv_bfloat16* Wh = (__nv_bfloat16*)(smem + 20480);
    __nv_bfloat16* Wl = (__nv_bfloat16*)(smem + 30720);
    uint32_t sb = (uint32_t)__cvta_generic_to_shared(smem);

    int tid = threadIdx.x, wid = tid >> 5, lane = tid & 31;
    int wm = wid >> 1, wn = wid & 1;
    int m8 = lane >> 3, r8 = lane & 7;
    int rowoff = r8 + ((m8 & 1) ? 8 : 0);
    int koff8 = (m8 >= 2) ? 8 : 0;

    for (int ch = 0; ch < 8; ch++) {
        int k0 = ch * 32;
        #pragma unroll
        for (int it = 0; it < 2; it++) {
            int u = tid + it * 256;
            int row = u >> 2, c8 = u & 3;
            size_t src = (size_t)(bm + row) * DD + k0 + c8 * 8;
            *(uint4*)(Ah + row * KCP2 + c8 * 8) = *(const uint4*)(Ahi + src);
            *(uint4*)(Al + row * KCP2 + c8 * 8) = *(const uint4*)(Alo + src);
        }
        #pragma unroll
        for (int it = 0; it < 2; it++) {
            int u = tid + it * 256;
            int n = u >> 2, c8 = u & 3;
            size_t src = (size_t)(bn + n) * 256 + k0 + c8 * 8;
            *(uint4*)(Wh + n * KCP2 + c8 * 8) = *(const uint4*)(Wth + src);
            *(uint4*)(Wl + n * KCP2 + c8 * 8) = *(const uint4*)(Wtl + src);
        }
        __syncthreads();
        #pragma unroll
        for (int kt = 0; kt < 2; kt++) {
            int kcol = kt * 16 + koff8;
            uint32_t ah[2][4], al[2][4];
            #pragma unroll
            for (int mt = 0; mt < 2; mt++) {
                uint32_t aoff = (uint32_t)((wm*32 + mt*16 + rowoff) * KCP2 + kcol) * 2;
                LDSM4(ah[mt][0], ah[mt][1], ah[mt][2], ah[mt][3], sb + aoff);
                LDSM4(al[mt][0], al[mt][1], al[mt][2], al[mt][3], sb + 10240 + aoff);
            }
            #pragma unroll
            for (int j = 0; j < 4; j++) {
                uint32_t woff = (uint32_t)((wn*64 + j*16 + rowoff) * KCP2 + kcol) * 2;
                uint32_t wh0, wh1, wh2, wh3, wl0, wl1, wl2, wl3;
                LDSM4(wh0, wh1, wh2, wh3, sb + 20480 + woff);
                LDSM4(wl0, wl1, wl2, wl3, sb + 30720 + woff);
                #pragma unroll
                for (int mt = 0; mt < 2; mt++) {
                    mma_bf16(c[mt][2*j],   ah[mt][0], ah[mt][1], ah[mt][2], ah[mt][3], wh0, wh2);
                    mma_bf16(c[mt][2*j],   al[mt][0], al[mt][1], al[mt][2], al[mt][3], wh0, wh2);
                    mma_bf16(c[mt][2*j],   ah[mt][0], ah[mt][1], ah[mt][2], ah[mt][3], wl0, wl2);
                    mma_bf16(c[mt][2*j+1], ah[mt][0], ah[mt][1], ah[mt][2], ah[mt][3], wh1, wh3);
                    mma_bf16(c[mt][2*j+1], al[mt][0], al[mt][1], al[mt][2], al[mt][3], wh1, wh3);
                    mma_bf16(c[mt][2*j+1], ah[mt][0], ah[mt][1], ah[mt][2], ah[mt][3], wl1, wl3);
                }
            }
        }
        __syncthreads();
    }
}

__device__ __forceinline__ void gemm_epi_self(float c[2][8][4], float* Cself,
                                              const float* bias, int bm, int bn, int N) {
    int tid = threadIdx.x, wid = tid >> 5, lane = tid & 31;
    int wm = wid >> 1, wn = wid & 1;
    #pragma unroll
    for (int mt = 0; mt < 2; mt++)
        #pragma unroll
        for (int h = 0; h < 2; h++) {
            int row = bm + wm * 32 + mt * 16 + (lane >> 2) + h * 8;
            float* orow = Cself + (size_t)row * N;
            #pragma unroll
            for (int nt = 0; nt < 8; nt++) {
                int col = bn + wn * 64 + nt * 8 + (lane & 3) * 2;
                float2 o;
                o.x = c[mt][nt][h * 2 + 0] + bias[col];
                o.y = c[mt][nt][h * 2 + 1] + bias[col + 1];
                *(float2*)(orow + col) = o;
            }
        }
}

// step-phase GEMM + vec über-kernel
// [0,256) p: bmi=idx&63, by=idx>>6 | [256,384) q | {384,385} qu | [386,398) vec
__global__ __launch_bounds__(256)
void gemm_all_kernel(const float* __restrict__ b_self,
                     const float* __restrict__ Wqd, const float* __restrict__ Wqup,
                     const float* __restrict__ Wquq) {
    __shared__ char smem[40960];
    int idx = blockIdx.x;
    if (idx >= 386) {
        // vec: s partial reduce + GEMV
        int v = idx - 386;
        int b = v & 3, sel = v >> 2, tid = threadIdx.x;
        float* sh = (float*)smem;
        const float* W = (sel == 0) ? Wqd : (sel == 1) ? Wqup : Wquq;
        float* out = (sel == 0) ? g_vqd : (sel == 1) ? g_vqup : g_vquq;
        float sv = 0.f;
        if (sel < 2) {
            #pragma unroll
            for (int cc = 0; cc < 16; cc++) sv += g_sppart[(b*16 + cc)*DD + tid];
        } else {
            #pragma unroll
            for (int cc = 0; cc < 8; cc++) sv += g_sqpart[(b*8 + cc)*DD + tid];
        }
        sh[tid] = sv;
        __syncthreads();
        float acc = 0.f;
        #pragma unroll 8
        for (int k = 0; k < DD; k++) acc += sh[k] * W[(size_t)k*DD + tid];
        out[b*DD + tid] = acc;
        return;
    }
    const __nv_bfloat16 *Ahi, *Alo, *WthS, *WtlS, *WthY, *WtlY;
    float* Cself; const float* rowscale;
    __nv_bfloat16 *Yhi, *Ylo; int NNbatch, bm, by;
    if (idx < 256) {
        by = idx >> 6; bm = (idx & 63) * 128;
        Ahi = g_Aphi; Alo = g_Aplo;
        WthY = g_Wth + OFF_PPW; WtlY = g_Wtl + OFF_PPW;
        Cself = g_selfp; rowscale = g_rsp; Yhi = g_Yphi; Ylo = g_Yplo; NNbatch = PP;
    } else if (idx < 384) {
        int i2 = idx - 256;
        by = i2 >> 5; bm = (i2 & 31) * 128;
        Ahi = g_Aqhi; Alo = g_Aqlo;
        WthY = g_Wth + OFF_QQW; WtlY = g_Wtl + OFF_QQW;
        Cself = g_selfq; rowscale = g_rsq; Yhi = g_Yqhi; Ylo = g_Yqlo; NNbatch = QQ;
    } else {
        by = idx - 384; bm = 0;
        Ahi = g_Aquhi; Alo = g_Aqulo;
        WthY = nullptr; WtlY = nullptr;
        Cself = g_selfqu; rowscale = nullptr; Yhi = nullptr; Ylo = nullptr; NNbatch = 0;
    }
    WthS = g_Wth + OFF_SELF; WtlS = g_Wtl + OFF_SELF;
    int mode = by >> 1;
    int bn = (by & 1) * 128;
    const __nv_bfloat16* Wth = mode ? WthY : WthS;
    const __nv_bfloat16* Wtl = mode ? WtlY : WtlS;

    float c[2][8][4];
    #pragma unroll
    for (int mt = 0; mt < 2; mt++)
        #pragma unroll
        for (int nt = 0; nt < 8; nt++)
            #pragma unroll
            for (int r = 0; r < 4; r++) c[mt][nt][r] = 0.f;

    gemm_mainloop(Ahi, Alo, Wth, Wtl, bm, bn, c, smem);

    int tid = threadIdx.x, wid = tid >> 5, lane = tid & 31;
    int wm = wid >> 1, wn = wid & 1;
    if (mode == 0) {
        gemm_epi_self(c, Cself, b_self, bm, bn, DD);
    } else {
        #pragma unroll
        for (int mt = 0; mt < 2; mt++)
            #pragma unroll
            for (int h = 0; h < 2; h++) {
                int gr = bm + wm * 32 + mt * 16 + (lane >> 2) + h * 8;
                float rs = rowscale[gr];
                int b = gr / NNbatch;
                int i = gr - b * NNbatch;
                #pragma unroll
                for (int nt = 0; nt < 8; nt++) {
                    int col = bn + wn * 64 + nt * 8 + (lane & 3) * 2;
                    size_t base = ((size_t)b * DD + col) * NNbatch + i;
                    float v0 = c[mt][nt][h * 2 + 0] * rs;
                    float v1 = c[mt][nt][h * 2 + 1] * rs;
                    __nv_bfloat16 h0 = __float2bfloat16(v0);
                    __nv_bfloat16 h1 = __float2bfloat16(v1);
                    Yhi[base] = h0;
                    Yhi[base + NNbatch] = h1;
                    Ylo[base] = __float2bfloat16(v0 - __bfloat162float(h0));
                    Ylo[base + NNbatch] = __float2bfloat16(v1 - __bfloat162float(h1));
                }
            }
    }
}

// merged output projections: [0,64) p, [64,96) q, 96 qu
__global__ __launch_bounds__(256)
void gemm_out_kernel(const float* __restrict__ b_p, const float* __restrict__ b_q,
                     const float* __restrict__ b_qu, float* __restrict__ out) {
    __shared__ char smem[40960];
    int bx = blockIdx.x;
    const __nv_bfloat16 *Ahi, *Alo, *Wth, *Wtl; const float* bias; float* O; int bm;
    if (bx < 64) {
        Ahi = g_Aphi; Alo = g_Aplo; Wth = g_Wth + OFF_PW; Wtl = g_Wtl + OFF_PW;
        bias = b_p; O = out; bm = bx * 128;
    } else if (bx < 96) {
        Ahi = g_Aqhi; Alo = g_Aqlo; Wth = g_Wth + OFF_QW; Wtl = g_Wtl + OFF_QW;
        bias = b_q; O = out + (size_t)BB*PP*HH; bm = (bx - 64) * 128;
    } else {
        Ahi = g_Aquhi; Alo = g_Aqulo; Wth = g_Wth + OFF_QUW; Wtl = g_Wtl + OFF_QUW;
        bias = b_qu; O = out + (size_t)BB*PP*HH + (size_t)BB*QQ*HH; bm = 0;
    }
    float c[2][8][4];
    #pragma unroll
    for (int mt = 0; mt < 2; mt++)
        #pragma unroll
        for (int nt = 0; nt < 8; nt++)
            #pragma unroll
            for (int r = 0; r < 4; r++) c[mt][nt][r] = 0.f;

    gemm_mainloop(Ahi, Alo, Wth, Wtl, bm, 0, c, smem);
    gemm_epi_self(c, O, bias, bm, 0, HH);
}

// ---------------- adjacency (N=128 split, 2 CTAs/SM) + qu_update ----------------
// [0,256) p-adj | [256,384) q-adj | [384,512) qu_update
#define KC 32
#define KCP 40
#define AS_B 5120
#define BH_B 10240
#define ADJ_SMEM (2*AS_B + 4*BH_B)   // 51200

__global__ __launch_bounds__(256, 2)
void adjq_kernel(const float* __restrict__ selfp, const float* __restrict__ selfq,
                 float* __restrict__ Op, float* __restrict__ Oq,
                 float* __restrict__ qunxt) {
    extern __shared__ __align__(16) char dsm[];
    int bx = blockIdx.x;
    int tid = threadIdx.x;
    if (bx >= 384) {
        // qu_update
        int r = bx - 384;
        int b = r / QNN;
        float v = g_selfqu[(size_t)r*DD + tid] + g_coefqu[r] * (g_vqup[b*DD + tid] + g_vquq[b*DD + tid]);
        qunxt[(size_t)r*DD + tid] = fmaxf(v, 0.f);
        return;
    }
    uint32_t smemBase = (uint32_t)__cvta_generic_to_shared(dsm);

    const __nv_bfloat16 *Gbf, *Yh, *Yl; const float *S, *coef, *ev;
    float* O; int NN, b, mtile, nhalf;
    if (bx < 256) {
        nhalf = bx & 1;
        int rest = bx >> 1;         // 0..127
        b = rest >> 5; mtile = rest & 31; NN = PP;
        Gbf = g_Gpbf + (size_t)b*PP*PP;
        Yh = g_Yphi + (size_t)b*DD*PP;  Yl = g_Yplo + (size_t)b*DD*PP;
        S = selfp + (size_t)b*PP*DD;    coef = g_coefp + b*PP;
        ev = nullptr;                   O = Op + (size_t)b*PP*DD;
    } else {
        int i2 = bx - 256;
        nhalf = i2 & 1;
        int rest = i2 >> 1;         // 0..63
        b = rest >> 4; mtile = rest & 15; NN = QQ;
        Gbf = g_Gqbf + (size_t)b*QQ*QQ;
        Yh = g_Yqhi + (size_t)b*DD*QQ;  Yl = g_Yqlo + (size_t)b*DD*QQ;
        S = selfq + (size_t)b*QQ*DD;    coef = g_coefq + b*QQ;
        ev = g_vqd + b*DD;              O = Oq + (size_t)b*QQ*DD;
    }
    int bm = mtile * 64, bn = nhalf * 128;
    int wid = tid >> 5, lane = tid & 31;
    int wm = wid >> 2, wn = wid & 3;
    int m8 = lane >> 3, r8 = lane & 7;
    int rowoff = r8 + ((m8 & 1) ? 8 : 0);
    int koff8 = (m8 >= 2) ? 8 : 0;

    float c[2][4][4];
    #pragma unroll
    for (int mt = 0; mt < 2; mt++)
        #pragma unroll
        for (int nt = 0; nt < 4; nt++)
            #pragma unroll
            for (int r = 0; r < 4; r++) c[mt][nt][r] = 0.f;

    int arow = tid >> 2, ac8 = tid & 3;

    auto issue = [&](int k0, int bufi) {
        uint32_t asb = smemBase + bufi * AS_B;
        CPA(asb + arow * 80 + ac8 * 16, Gbf + (size_t)(bm + arow) * NN + k0 + ac8 * 8);
        uint32_t bhb = smemBase + 2 * AS_B + bufi * BH_B;
        uint32_t blb = smemBase + 2 * AS_B + 2 * BH_B + bufi * BH_B;
        #pragma unroll
        for (int it = 0; it < 2; it++) {
            int idx = tid + it * 256;
            int d = idx >> 2, c8 = idx & 3;
            size_t src = (size_t)(bn + d) * NN + k0 + c8 * 8;
            CPA(bhb + d * 80 + c8 * 16, Yh + src);
            CPA(blb + d * 80 + c8 * 16, Yl + src);
        }
    };

    const int nchunks = NN / KC;
    issue(0, 0);
    CPC();
    int buf = 0;
    for (int ch = 0; ch < nchunks; ch++) {
        bool hn = (ch + 1 < nchunks);
        if (hn) { issue((ch + 1) * KC, buf ^ 1); CPC(); }
        if (hn) { CPW1(); } else { CPW0(); }
        __syncthreads();

        uint32_t asB = smemBase + buf * AS_B;
        uint32_t bhB = smemBase + 2 * AS_B + buf * BH_B;
        uint32_t blB = smemBase + 2 * AS_B + 2 * BH_B + buf * BH_B;

        #pragma unroll
        for (int kt = 0; kt < 2; kt++) {
            int kcol = kt * 16 + koff8;
            uint32_t a[2][4];
            #pragma unroll
            for (int mt = 0; mt < 2; mt++) {
                uint32_t aoff = (uint32_t)((wm*32 + mt*16 + rowoff) * KCP + kcol) * 2;
                LDSM4(a[mt][0], a[mt][1], a[mt][2], a[mt][3], asB + aoff);
            }
            #pragma unroll
            for (int j = 0; j < 2; j++) {
                uint32_t boff = (uint32_t)((wn*32 + j*16 + rowoff) * KCP + kcol) * 2;
                uint32_t bh0, bh1, bh2, bh3, bl0, bl1, bl2, bl3;
                LDSM4(bh0, bh1, bh2, bh3, bhB + boff);
                LDSM4(bl0, bl1, bl2, bl3, blB + boff);
                mma_bf16(c[0][2*j],   a[0][0], a[0][1], a[0][2], a[0][3], bh0, bh2);
                mma_bf16(c[1][2*j],   a[1][0], a[1][1], a[1][2], a[1][3], bh0, bh2);
                mma_bf16(c[0][2*j],   a[0][0], a[0][1], a[0][2], a[0][3], bl0, bl2);
                mma_bf16(c[1][2*j],   a[1][0], a[1][1], a[1][2], a[1][3], bl0, bl2);
                mma_bf16(c[0][2*j+1], a[0][0], a[0][1], a[0][2], a[0][3], bh1, bh3);
                mma_bf16(c[1][2*j+1], a[1][0], a[1][1], a[1][2], a[1][3], bh1, bh3);
                mma_bf16(c[0][2*j+1], a[0][0], a[0][1], a[0][2], a[0][3], bl1, bl3);
                mma_bf16(c[1][2*j+1], a[1][0], a[1][1], a[1][2], a[1][3], bl1, bl3);
            }
        }
        __syncthreads();
        buf ^= 1;
    }

    #pragma unroll
    for (int mt = 0; mt < 2; mt++) {
        #pragma unroll
        for (int h = 0; h < 2; h++) {
            int row = bm + wm * 32 + mt * 16 + (lane >> 2) + h * 8;
            float cf = coef[row];
            const float* srow = S + (size_t)row * DD;
            float* orow = O + (size_t)row * DD;
            #pragma unroll
            for (int nt = 0; nt < 4; nt++) {
                int col = bn + wn * 32 + (nt >> 1) * 16 + (nt & 1) * 8 + (lane & 3) * 2;
                float v0 = c[mt][nt][h * 2 + 0];
                float v1 = c[mt][nt][h * 2 + 1];
                if (ev) { v0 += ev[col]; v1 += ev[col + 1]; }
                float2 s2 = *(const float2*)(srow + col);
                float2 o;
                o.x = fmaxf(s2.x + cf * v0, 0.f);
                o.y = fmaxf(s2.y + cf * v1, 0.f);
                *(float2*)(orow + col) = o;
            }
        }
    }
}

// ---------------- launch ----------------
extern "C" void kernel_launch(void* const* d_in, const int* in_sizes, int n_in,
                              void* d_out, int out_size) {
    const float* p_in   = (const float*)d_in[0];
    const float* q_in   = (const float*)d_in[1];
    const float* qu_in  = (const float*)d_in[2];
    const int*   pmask  = (const int*)d_in[3];
    const int*   qmask  = (const int*)d_in[4];
    const int*   qumask = (const int*)d_in[5];
    const int*   ppg    = (const int*)d_in[6];
    const int*   qqg    = (const int*)d_in[7];
    const float* W_node = (const float*)d_in[10];
    const float* b_node = (const float*)d_in[11];
    const float* W_self = (const float*)d_in[12];
    const float* b_self = (const float*)d_in[13];
    const float* W_pp   = (const float*)d_in[14];
    const float* W_qd   = (const float*)d_in[15];
    const float* W_qq   = (const float*)d_in[16];
    const float* W_qup  = (const float*)d_in[17];
    const float* W_quq  = (const float*)d_in[18];
    const float* W_p    = (const float*)d_in[19];
    const float* b_p    = (const float*)d_in[20];
    const float* W_q    = (const float*)d_in[21];
    const float* b_q    = (const float*)d_in[22];
    const float* W_qu   = (const float*)d_in[23];
    const float* b_qu   = (const float*)d_in[24];
    float* out = (float*)d_out;

    float *pA, *pB, *qA, *qB, *quA, *quB, *selfp, *selfq;
    cudaGetSymbolAddress((void**)&pA, g_pA);
    cudaGetSymbolAddress((void**)&pB, g_pB);
    cudaGetSymbolAddress((void**)&qA, g_qA);
    cudaGetSymbolAddress((void**)&qB, g_qB);
    cudaGetSymbolAddress((void**)&quA, g_quA);
    cudaGetSymbolAddress((void**)&quB, g_quB);
    cudaGetSymbolAddress((void**)&selfp, g_selfp);
    cudaGetSymbolAddress((void**)&selfq, g_selfq);

    cudaFuncSetAttribute(adjq_kernel, cudaFuncAttributeMaxDynamicSharedMemorySize, ADJ_SMEM);

    prep_kernel<<<1921, 256>>>(ppg, qqg, pmask, qmask, qumask,
                               W_self, W_pp, W_qq, W_p, W_q, W_qu);

    const float* pc = p_in;  const float* qc = q_in;  const float* quc = qu_in;
    float* pn = pA;  float* qn = qA;  float* qun = quA;

    for (int step = 0; step < 2; step++) {
        steppre_kernel<<<3200, 256>>>(pc, qc, quc, pmask, qmask, W_node, b_node);
        gemm_all_kernel<<<398, 256>>>(b_self, W_qd, W_qup, W_quq);
        adjq_kernel<<<512, 256, ADJ_SMEM>>>(selfp, selfq, pn, qn, qun);
        pc = pn; qc = qn; quc = qun;
        pn = pB; qn = qB; qun = quB;
    }

    asplit_all_kernel<<<3104, 256>>>(pc, qc, quc);
    gemm_out_kernel<<<97, 256>>>(b_p, b_q, b_qu, out);
}

// round 10
// speedup vs baseline: 3.1844x; 1.0255x over previous
#include <cuda_runtime.h>
#include <cuda_bf16.h>
#include <math.h>
#include <stdint.h>

#define BB  4
#define PP  2048
#define QQ  1024
#define QNN 32
#define DD  256
#define HH  128

// ---------------- persistent scratch ----------------
__device__ float g_pA[BB*PP*DD];
__device__ float g_pB[BB*PP*DD];
__device__ float g_qA[BB*QQ*DD];
__device__ float g_qB[BB*QQ*DD];
__device__ float g_quA[BB*QNN*DD];
__device__ float g_quB[BB*QNN*DD];
__device__ float g_selfp[BB*PP*DD];
__device__ float g_selfq[BB*QQ*DD];
__device__ float g_selfqu[BB*QNN*DD];
__device__ __nv_bfloat16 g_Yphi[BB*DD*PP];
__device__ __nv_bfloat16 g_Yplo[BB*DD*PP];
__device__ __nv_bfloat16 g_Yqhi[BB*DD*QQ];
__device__ __nv_bfloat16 g_Yqlo[BB*DD*QQ];
__device__ __nv_bfloat16 g_Gpbf[(size_t)BB*PP*PP];
__device__ __nv_bfloat16 g_Gqbf[(size_t)BB*QQ*QQ];
__device__ __nv_bfloat16 g_Aphi[BB*PP*DD];
__device__ __nv_bfloat16 g_Aplo[BB*PP*DD];
__device__ __nv_bfloat16 g_Aqhi[BB*QQ*DD];
__device__ __nv_bfloat16 g_Aqlo[BB*QQ*DD];
__device__ __nv_bfloat16 g_Aquhi[BB*QNN*DD];
__device__ __nv_bfloat16 g_Aqulo[BB*QNN*DD];
__device__ __nv_bfloat16 g_Wth[294912];
__device__ __nv_bfloat16 g_Wtl[294912];
#define OFF_SELF 0
#define OFF_PPW  65536
#define OFF_QQW  131072
#define OFF_PW   196608
#define OFF_QW   229376
#define OFF_QUW  262144
__device__ float g_rsp[BB*PP];
__device__ float g_rsq[BB*QQ];
__device__ float g_coefp[BB*PP];
__device__ float g_coefq[BB*QQ];
__device__ float g_coefqu[BB*QNN];
__device__ float g_sppart[BB*16*DD];
__device__ float g_sqpart[BB*8*DD];
__device__ float g_vqd[BB*DD];
__device__ float g_vqup[BB*DD];
__device__ float g_vquq[BB*DD];

// ---------------- asm helpers ----------------
#define CPA(dst, src) asm volatile("cp.async.cg.shared.global [%0], [%1], 16;" :: "r"(dst), "l"(src) : "memory")
#define CPC() asm volatile("cp.async.commit_group;" ::: "memory")
#define CPW3() asm volatile("cp.async.wait_group 3;" ::: "memory")
#define CPW2() asm volatile("cp.async.wait_group 2;" ::: "memory")
#define CPW1() asm volatile("cp.async.wait_group 1;" ::: "memory")
#define CPW0() asm volatile("cp.async.wait_group 0;" ::: "memory")
#define LDSM4(r0, r1, r2, r3, addr) \
    asm volatile("ldmatrix.sync.aligned.m8n8.x4.shared.b16 {%0,%1,%2,%3}, [%4];" \
        : "=r"(r0), "=r"(r1), "=r"(r2), "=r"(r3) : "r"(addr))

__device__ __forceinline__ void mma_bf16(float c[4], uint32_t a0, uint32_t a1,
                                         uint32_t a2, uint32_t a3,
                                         uint32_t b0, uint32_t b1) {
    asm volatile(
        "mma.sync.aligned.m16n8k16.row.col.f32.bf16.bf16.f32 "
        "{%0,%1,%2,%3}, {%4,%5,%6,%7}, {%8,%9}, {%0,%1,%2,%3};"
        : "+f"(c[0]), "+f"(c[1]), "+f"(c[2]), "+f"(c[3])
        : "r"(a0), "r"(a1), "r"(a2), "r"(a3), "r"(b0), "r"(b1));
}

__device__ __forceinline__ void split_pack2(float x, float y, uint32_t& h, uint32_t& l) {
    __nv_bfloat16 hx = __float2bfloat16(x), hy = __float2bfloat16(y);
    float rx = x - __bfloat162float(hx), ry = y - __bfloat162float(hy);
    __nv_bfloat16 lx = __float2bfloat16(rx), ly = __float2bfloat16(ry);
    h = (uint32_t)__bfloat16_as_ushort(hy) << 16 | __bfloat16_as_ushort(hx);
    l = (uint32_t)__bfloat16_as_ushort(ly) << 16 | __bfloat16_as_ushort(lx);
}

// ---------------- PREP über-kernel ----------------
__global__ __launch_bounds__(256)
void prep_kernel(const int* __restrict__ Gp, const int* __restrict__ Gq,
                 const int* __restrict__ pm, const int* __restrict__ qm,
                 const int* __restrict__ qum,
                 const float* __restrict__ W_self, const float* __restrict__ W_pp,
                 const float* __restrict__ W_qq, const float* __restrict__ W_p,
                 const float* __restrict__ W_q, const float* __restrict__ W_qu) {
    __shared__ float shp[2112];
    int bx = blockIdx.x, tid = threadIdx.x;
    if (bx < 1024) {
        int b = bx >> 8, xtile = bx & 255;
        for (int i = tid; i < PP; i += 256) shp[i] = (float)pm[b*PP + i];
        __syncthreads();
        int warp = tid >> 5, lane = tid & 31;
        int row = xtile * 8 + warp;
        const int* g = Gp + ((size_t)b*PP + row) * PP;
        __nv_bfloat16* go = g_Gpbf + ((size_t)b*PP + row) * PP;
        float s = 0.f;
        for (int j = lane * 4; j < PP; j += 128) {
            int4 v = *(const int4*)(g + j);
            uint32_t r0 = (v.x ? 0x3F80u : 0u) | ((v.y ? 0x3F80u : 0u) << 16);
            uint32_t r1 = (v.z ? 0x3F80u : 0u) | ((v.w ? 0x3F80u : 0u) << 16);
            *(uint2*)(go + j) = make_uint2(r0, r1);
            s += shp[j] * (float)v.x + shp[j+1] * (float)v.y
               + shp[j+2] * (float)v.z + shp[j+3] * (float)v.w;
        }
        #pragma unroll
        for (int o = 16; o; o >>= 1) s += __shfl_xor_sync(0xffffffffu, s, o);
        if (lane == 0)
            g_coefp[b*PP + row] = pm[b*PP + row] ? 1.f / fmaxf(s, 1.f) : 0.f;
    } else if (bx < 1536) {
        int i2 = bx - 1024;
        int b = i2 >> 7, xtile = i2 & 127;
        float ps = 0.f;
        for (int i = tid; i < PP; i += 256) ps += (float)pm[b*PP + i];
        for (int i = tid; i < QQ; i += 256) shp[i] = (float)qm[b*QQ + i];
        shp[1024 + tid] = ps;
        __syncthreads();
        if (tid < 128) shp[1024 + tid] += shp[1024 + tid + 128];
        __syncthreads();
        if (tid < 64) shp[1024 + tid] += shp[1024 + tid + 64];
        __syncthreads();
        if (tid < 32) {
            float v = shp[1024 + tid] + shp[1024 + tid + 32];
            #pragma unroll
            for (int o = 16; o; o >>= 1) v += __shfl_xor_sync(0xffffffffu, v, o);
            if (tid == 0) shp[2048] = v;
        }
        __syncthreads();
        float psum = shp[2048];
        int warp = tid >> 5, lane = tid & 31;
        int row = xtile * 8 + warp;
        const int* g = Gq + ((size_t)b*QQ + row) * QQ;
        __nv_bfloat16* go = g_Gqbf + ((size_t)b*QQ + row) * QQ;
        float s = 0.f;
        for (int j = lane * 4; j < QQ; j += 128) {
            int4 v = *(const int4*)(g + j);
            uint32_t r0 = (v.x ? 0x3F80u : 0u) | ((v.y ? 0x3F80u : 0u) << 16);
            uint32_t r1 = (v.z ? 0x3F80u : 0u) | ((v.w ? 0x3F80u : 0u) << 16);
            *(uint2*)(go + j) = make_uint2(r0, r1);
            s += shp[j] * (float)v.x + shp[j+1] * (float)v.y
               + shp[j+2] * (float)v.z + shp[j+3] * (float)v.w;
        }
        #pragma unroll
        for (int o = 16; o; o >>= 1) s += __shfl_xor_sync(0xffffffffu, s, o);
        if (lane == 0)
            g_coefq[b*QQ + row] = qm[b*QQ + row] ? 1.f / fmaxf(psum + s, 1.f) : 0.f;
    } else if (bx == 1536) {
        for (int b = 0; b < BB; b++) {
            float s = 0.f;
            for (int i = tid; i < PP; i += 256) s += (float)pm[b*PP + i];
            for (int i = tid; i < QQ; i += 256) s += (float)qm[b*QQ + i];
            shp[tid] = s;
            __syncthreads();
            for (int o = 128; o; o >>= 1) { if (tid < o) shp[tid] += shp[tid + o]; __syncthreads(); }
            if (tid == 0) shp[1024 + b] = shp[0];
            __syncthreads();
        }
        if (tid < BB*QNN) {
            int b = tid / QNN;
            g_coefqu[tid] = qum[tid] ? 1.f / fmaxf(shp[1024 + b], 1.f) : 0.f;
        }
    } else {
        int w = bx - 1537;
        int z = w / 64, ww = w % 64;
        const float* W; int N; int off;
        switch (z) {
            case 0: W = W_self; N = 256; off = OFF_SELF; break;
            case 1: W = W_pp;   N = 256; off = OFF_PPW;  break;
            case 2: W = W_qq;   N = 256; off = OFF_QQW;  break;
            case 3: W = W_p;    N = 128; off = OFF_PW;   break;
            case 4: W = W_q;    N = 128; off = OFF_QW;   break;
            default: W = W_qu;  N = 128; off = OFF_QUW;  break;
        }
        int nb = (ww & 7) * 32, kb = (ww >> 3) * 32;
        if (nb >= N) return;
        int tx = tid & 31, ty = tid >> 5;
        #pragma unroll
        for (int r = 0; r < 32; r += 8)
            shp[(ty + r) * 33 + tx] = W[(size_t)(kb + ty + r) * N + nb + tx];
        __syncthreads();
        __nv_bfloat16* Wth = g_Wth + off;
        __nv_bfloat16* Wtl = g_Wtl + off;
        #pragma unroll
        for (int r = 0; r < 32; r += 8) {
            int n = nb + ty + r, k = kb + tx;
            float v = shp[tx * 33 + ty + r];
            __nv_bfloat16 h = __float2bfloat16(v);
            Wth[(size_t)n * 256 + k] = h;
            Wtl[(size_t)n * 256 + k] = __float2bfloat16(v - __bfloat162float(h));
        }
    }
}

// ---------------- asplit body + standalone ----------------
__device__ __forceinline__ void asplit_body(int lb, const float* __restrict__ P,
                                            const float* __restrict__ Q,
                                            const float* __restrict__ QU) {
    const float* A; __nv_bfloat16 *Ahi, *Alo; int l2;
    if (lb < 2048) { A = P; Ahi = g_Aphi; Alo = g_Aplo; l2 = lb; }
    else if (lb < 3072) { A = Q; Ahi = g_Aqhi; Alo = g_Aqlo; l2 = lb - 2048; }
    else { A = QU; Ahi = g_Aquhi; Alo = g_Aqulo; l2 = lb - 3072; }
    size_t i4 = ((size_t)l2 * 256 + threadIdx.x) * 4;
    float4 v = *(const float4*)(A + i4);
    uint32_t h0, l0, h1, l1;
    split_pack2(v.x, v.y, h0, l0);
    split_pack2(v.z, v.w, h1, l1);
    *(uint2*)(Ahi + i4) = make_uint2(h0, h1);
    *(uint2*)(Alo + i4) = make_uint2(l0, l1);
}

__global__ void asplit_all_kernel(const float* __restrict__ P, const float* __restrict__ Q,
                                  const float* __restrict__ QU) {
    asplit_body(blockIdx.x, P, Q, QU);
}

// ---------------- step-pre über-kernel: pws + asplit ----------------
__global__ __launch_bounds__(256)
void steppre_kernel(const float* __restrict__ pcur, const float* __restrict__ qcur,
                    const float* __restrict__ qucur,
                    const int* __restrict__ pmask, const int* __restrict__ qmask,
                    const float* __restrict__ Wn, const float* __restrict__ bn) {
    int bx = blockIdx.x;
    if (bx >= 96) { asplit_body(bx - 96, pcur, qcur, qucur); return; }
    int b = bx / 24, chunk = bx % 24;
    int tid = threadIdx.x, wid = tid >> 5, lane = tid & 31;
    const float* node; const int* mask; float* rsout; float* sout; int rowbase;
    if (chunk < 16) {
        node = pcur + (size_t)b*PP*DD; mask = pmask + b*PP;
        rsout = g_rsp + b*PP; sout = g_sppart + (b*16 + chunk)*DD; rowbase = chunk * 128;
    } else {
        node = qcur + (size_t)b*QQ*DD; mask = qmask + b*QQ;
        rsout = g_rsq + b*QQ; sout = g_sqpart + (b*8 + (chunk - 16))*DD; rowbase = (chunk - 16) * 128;
    }
    __shared__ float wsh[DD];
    __shared__ float wrow[128];
    for (int k = tid; k < DD; k += 256) wsh[k] = Wn[k];
    __syncthreads();
    float bv = bn[0];
    #pragma unroll
    for (int r = 0; r < 16; r++) {
        int lrow = wid * 16 + r;
        const float* nrow = node + (size_t)(rowbase + lrow) * DD;
        float s = 0.f;
        #pragma unroll
        for (int k = lane; k < DD; k += 32) s += nrow[k] * wsh[k];
        #pragma unroll
        for (int o = 16; o; o >>= 1) s += __shfl_xor_sync(0xffffffffu, s, o);
        if (lane == 0) {
            float sig = 1.f / (1.f + expf(-(s + bv)));
            float w = mask[rowbase + lrow] ? sig : 0.f;
            wrow[lrow] = w;
            rsout[rowbase + lrow] = w;
        }
    }
    __syncthreads();
    float acc = 0.f;
    #pragma unroll 4
    for (int i = 0; i < 128; i++) {
        float w = wrow[i];
        if (w != 0.f) acc += w * node[(size_t)(rowbase + i) * DD + tid];
    }
    sout[tid] = acc;
}

// ---------------- shared GEMM mainloop (ldmatrix + 3-product hi/lo) ----------------
#define KCP2 40

__device__ __forceinline__ void gemm_mainloop(
        const __nv_bfloat16* __restrict__ Ahi, const __nv_bfloat16* __restrict__ Alo,
        const __nv_bfloat16* __restrict__ Wth, const __nv_bfloat16* __restrict__ Wtl,
        int bm, int bn, float c[2][8][4], char* smem) {
    __nv_bfloat16* Ah = (__nv_bfloat16*)smem;
    __nv_bfloat16* Al = (__nv_bfloat16*)(smem + 10240);
    __nv_bfloat16* Wh = (__nv_bfloat16*)(smem + 20480);
    __nv_bfloat16* Wl = (__nv_bfloat16*)(smem + 30720);
    uint32_t sb = (uint32_t)__cvta_generic_to_shared(smem);

    int tid = threadIdx.x, wid = tid >> 5, lane = tid & 31;
    int wm = wid >> 1, wn = wid & 1;
    int m8 = lane >> 3, r8 = lane & 7;
    int rowoff = r8 + ((m8 & 1) ? 8 : 0);
    int koff8 = (m8 >= 2) ? 8 : 0;

    for (int ch = 0; ch < 8; ch++) {
        int k0 = ch * 32;
        #pragma unroll
        for (int it = 0; it < 2; it++) {
            int u = tid + it * 256;
            int row = u >> 2, c8 = u & 3;
            size_t src = (size_t)(bm + row) * DD + k0 + c8 * 8;
            *(uint4*)(Ah + row * KCP2 + c8 * 8) = *(const uint4*)(Ahi + src);
            *(uint4*)(Al + row * KCP2 + c8 * 8) = *(const uint4*)(Alo + src);
        }
        #pragma unroll
        for (int it = 0; it < 2; it++) {
            int u = tid + it * 256;
            int n = u >> 2, c8 = u & 3;
            size_t src = (size_t)(bn + n) * 256 + k0 + c8 * 8;
            *(uint4*)(Wh + n * KCP2 + c8 * 8) = *(const uint4*)(Wth + src);
            *(uint4*)(Wl + n * KCP2 + c8 * 8) = *(const uint4*)(Wtl + src);
        }
        __syncthreads();
        #pragma unroll
        for (int kt = 0; kt < 2; kt++) {
            int kcol = kt * 16 + koff8;
            uint32_t ah[2][4], al[2][4];
            #pragma unroll
            for (int mt = 0; mt < 2; mt++) {
                uint32_t aoff = (uint32_t)((wm*32 + mt*16 + rowoff) * KCP2 + kcol) * 2;
                LDSM4(ah[mt][0], ah[mt][1], ah[mt][2], ah[mt][3], sb + aoff);
                LDSM4(al[mt][0], al[mt][1], al[mt][2], al[mt][3], sb + 10240 + aoff);
            }
            #pragma unroll
            for (int j = 0; j < 4; j++) {
                uint32_t woff = (uint32_t)((wn*64 + j*16 + rowoff) * KCP2 + kcol) * 2;
                uint32_t wh0, wh1, wh2, wh3, wl0, wl1, wl2, wl3;
                LDSM4(wh0, wh1, wh2, wh3, sb + 20480 + woff);
                LDSM4(wl0, wl1, wl2, wl3, sb + 30720 + woff);
                #pragma unroll
                for (int mt = 0; mt < 2; mt++) {
                    mma_bf16(c[mt][2*j],   ah[mt][0], ah[mt][1], ah[mt][2], ah[mt][3], wh0, wh2);
                    mma_bf16(c[mt][2*j],   al[mt][0], al[mt][1], al[mt][2], al[mt][3], wh0, wh2);
                    mma_bf16(c[mt][2*j],   ah[mt][0], ah[mt][1], ah[mt][2], ah[mt][3], wl0, wl2);
                    mma_bf16(c[mt][2*j+1], ah[mt][0], ah[mt][1], ah[mt][2], ah[mt][3], wh1, wh3);
                    mma_bf16(c[mt][2*j+1], al[mt][0], al[mt][1], al[mt][2], al[mt][3], wh1, wh3);
                    mma_bf16(c[mt][2*j+1], ah[mt][0], ah[mt][1], ah[mt][2], ah[mt][3], wl1, wl3);
                }
            }
        }
        __syncthreads();
    }
}

__device__ __forceinline__ void gemm_epi_self(float c[2][8][4], float* Cself,
                                              const float* bias, int bm, int bn, int N) {
    int tid = threadIdx.x, wid = tid >> 5, lane = tid & 31;
    int wm = wid >> 1, wn = wid & 1;
    #pragma unroll
    for (int mt = 0; mt < 2; mt++)
        #pragma unroll
        for (int h = 0; h < 2; h++) {
            int row = bm + wm * 32 + mt * 16 + (lane >> 2) + h * 8;
            float* orow = Cself + (size_t)row * N;
            #pragma unroll
            for (int nt = 0; nt < 8; nt++) {
                int col = bn + wn * 64 + nt * 8 + (lane & 3) * 2;
                float2 o;
                o.x = c[mt][nt][h * 2 + 0] + bias[col];
                o.y = c[mt][nt][h * 2 + 1] + bias[col + 1];
                *(float2*)(orow + col) = o;
            }
        }
}

// step-phase GEMM + vec über-kernel
__global__ __launch_bounds__(256)
void gemm_all_kernel(const float* __restrict__ b_self,
                     const float* __restrict__ Wqd, const float* __restrict__ Wqup,
                     const float* __restrict__ Wquq) {
    __shared__ char smem[40960];
    int idx = blockIdx.x;
    if (idx >= 386) {
        int v = idx - 386;
        int b = v & 3, sel = v >> 2, tid = threadIdx.x;
        float* sh = (float*)smem;
        const float* W = (sel == 0) ? Wqd : (sel == 1) ? Wqup : Wquq;
        float* out = (sel == 0) ? g_vqd : (sel == 1) ? g_vqup : g_vquq;
        float sv = 0.f;
        if (sel < 2) {
            #pragma unroll
            for (int cc = 0; cc < 16; cc++) sv += g_sppart[(b*16 + cc)*DD + tid];
        } else {
            #pragma unroll
            for (int cc = 0; cc < 8; cc++) sv += g_sqpart[(b*8 + cc)*DD + tid];
        }
        sh[tid] = sv;
        __syncthreads();
        float acc = 0.f;
        #pragma unroll 8
        for (int k = 0; k < DD; k++) acc += sh[k] * W[(size_t)k*DD + tid];
        out[b*DD + tid] = acc;
        return;
    }
    const __nv_bfloat16 *Ahi, *Alo, *WthS, *WtlS, *WthY, *WtlY;
    float* Cself; const float* rowscale;
    __nv_bfloat16 *Yhi, *Ylo; int NNbatch, bm, by;
    if (idx < 256) {
        by = idx >> 6; bm = (idx & 63) * 128;
        Ahi = g_Aphi; Alo = g_Aplo;
        WthY = g_Wth + OFF_PPW; WtlY = g_Wtl + OFF_PPW;
        Cself = g_selfp; rowscale = g_rsp; Yhi = g_Yphi; Ylo = g_Yplo; NNbatch = PP;
    } else if (idx < 384) {
        int i2 = idx - 256;
        by = i2 >> 5; bm = (i2 & 31) * 128;
        Ahi = g_Aqhi; Alo = g_Aqlo;
        WthY = g_Wth + OFF_QQW; WtlY = g_Wtl + OFF_QQW;
        Cself = g_selfq; rowscale = g_rsq; Yhi = g_Yqhi; Ylo = g_Yqlo; NNbatch = QQ;
    } else {
        by = idx - 384; bm = 0;
        Ahi = g_Aquhi; Alo = g_Aqulo;
        WthY = nullptr; WtlY = nullptr;
        Cself = g_selfqu; rowscale = nullptr; Yhi = nullptr; Ylo = nullptr; NNbatch = 0;
    }
    WthS = g_Wth + OFF_SELF; WtlS = g_Wtl + OFF_SELF;
    int mode = by >> 1;
    int bn = (by & 1) * 128;
    const __nv_bfloat16* Wth = mode ? WthY : WthS;
    const __nv_bfloat16* Wtl = mode ? WtlY : WtlS;

    float c[2][8][4];
    #pragma unroll
    for (int mt = 0; mt < 2; mt++)
        #pragma unroll
        for (int nt = 0; nt < 8; nt++)
            #pragma unroll
            for (int r = 0; r < 4; r++) c[mt][nt][r] = 0.f;

    gemm_mainloop(Ahi, Alo, Wth, Wtl, bm, bn, c, smem);

    int tid = threadIdx.x, wid = tid >> 5, lane = tid & 31;
    int wm = wid >> 1, wn = wid & 1;
    if (mode == 0) {
        gemm_epi_self(c, Cself, b_self, bm, bn, DD);
    } else {
        #pragma unroll
        for (int mt = 0; mt < 2; mt++)
            #pragma unroll
            for (int h = 0; h < 2; h++) {
                int gr = bm + wm * 32 + mt * 16 + (lane >> 2) + h * 8;
                float rs = rowscale[gr];
                int b = gr / NNbatch;
                int i = gr - b * NNbatch;
                #pragma unroll
                for (int nt = 0; nt < 8; nt++) {
                    int col = bn + wn * 64 + nt * 8 + (lane & 3) * 2;
                    size_t base = ((size_t)b * DD + col) * NNbatch + i;
                    float v0 = c[mt][nt][h * 2 + 0] * rs;
                    float v1 = c[mt][nt][h * 2 + 1] * rs;
                    __nv_bfloat16 h0 = __float2bfloat16(v0);
                    __nv_bfloat16 h1 = __float2bfloat16(v1);
                    Yhi[base] = h0;
                    Yhi[base + NNbatch] = h1;
                    Ylo[base] = __float2bfloat16(v0 - __bfloat162float(h0));
                    Ylo[base + NNbatch] = __float2bfloat16(v1 - __bfloat162float(h1));
                }
            }
    }
}

// merged output projections: [0,64) p, [64,96) q, 96 qu
__global__ __launch_bounds__(256)
void gemm_out_kernel(const float* __restrict__ b_p, const float* __restrict__ b_q,
                     const float* __restrict__ b_qu, float* __restrict__ out) {
    __shared__ char smem[40960];
    int bx = blockIdx.x;
    const __nv_bfloat16 *Ahi, *Alo, *Wth, *Wtl; const float* bias; float* O; int bm;
    if (bx < 64) {
        Ahi = g_Aphi; Alo = g_Aplo; Wth = g_Wth + OFF_PW; Wtl = g_Wtl + OFF_PW;
        bias = b_p; O = out; bm = bx * 128;
    } else if (bx < 96) {
        Ahi = g_Aqhi; Alo = g_Aqlo; Wth = g_Wth + OFF_QW; Wtl = g_Wtl + OFF_QW;
        bias = b_q; O = out + (size_t)BB*PP*HH; bm = (bx - 64) * 128;
    } else {
        Ahi = g_Aquhi; Alo = g_Aqulo; Wth = g_Wth + OFF_QUW; Wtl = g_Wtl + OFF_QUW;
        bias = b_qu; O = out + (size_t)BB*PP*HH + (size_t)BB*QQ*HH; bm = 0;
    }
    float c[2][8][4];
    #pragma unroll
    for (int mt = 0; mt < 2; mt++)
        #pragma unroll
        for (int nt = 0; nt < 8; nt++)
            #pragma unroll
            for (int r = 0; r < 4; r++) c[mt][nt][r] = 0.f;

    gemm_mainloop(Ahi, Alo, Wth, Wtl, bm, 0, c, smem);
    gemm_epi_self(c, O, bias, bm, 0, HH);
}

// ---------------- adjacency: 4-stage cp.async pipeline + qu_update ----------------
// [0,256) p-adj | [256,384) q-adj | [384,512) qu_update
#define KC 32
#define KCP 40
#define AS_B 5120
#define BH_B 10240
#define ST_B (AS_B + 2*BH_B)       // 25600 per stage
#define ADJ_SMEM (4*ST_B)          // 102400

__global__ __launch_bounds__(256, 2)
void adjq_kernel(const float* __restrict__ selfp, const float* __restrict__ selfq,
                 float* __restrict__ Op, float* __restrict__ Oq,
                 float* __restrict__ qunxt) {
    extern __shared__ __align__(16) char dsm[];
    int bx = blockIdx.x;
    int tid = threadIdx.x;
    if (bx >= 384) {
        int r = bx - 384;
        int b = r / QNN;
        float v = g_selfqu[(size_t)r*DD + tid] + g_coefqu[r] * (g_vqup[b*DD + tid] + g_vquq[b*DD + tid]);
        qunxt[(size_t)r*DD + tid] = fmaxf(v, 0.f);
        return;
    }
    uint32_t smemBase = (uint32_t)__cvta_generic_to_shared(dsm);

    const __nv_bfloat16 *Gbf, *Yh, *Yl; const float *S, *coef, *ev;
    float* O; int NN, b, mtile, nhalf;
    if (bx < 256) {
        nhalf = bx & 1;
        int rest = bx >> 1;
        b = rest >> 5; mtile = rest & 31; NN = PP;
        Gbf = g_Gpbf + (size_t)b*PP*PP;
        Yh = g_Yphi + (size_t)b*DD*PP;  Yl = g_Yplo + (size_t)b*DD*PP;
        S = selfp + (size_t)b*PP*DD;    coef = g_coefp + b*PP;
        ev = nullptr;                   O = Op + (size_t)b*PP*DD;
    } else {
        int i2 = bx - 256;
        nhalf = i2 & 1;
        int rest = i2 >> 1;
        b = rest >> 4; mtile = rest & 15; NN = QQ;
        Gbf = g_Gqbf + (size_t)b*QQ*QQ;
        Yh = g_Yqhi + (size_t)b*DD*QQ;  Yl = g_Yqlo + (size_t)b*DD*QQ;
        S = selfq + (size_t)b*QQ*DD;    coef = g_coefq + b*QQ;
        ev = g_vqd + b*DD;              O = Oq + (size_t)b*QQ*DD;
    }
    int bm = mtile * 64, bn = nhalf * 128;
    int wid = tid >> 5, lane = tid & 31;
    int wm = wid >> 2, wn = wid & 3;
    int m8 = lane >> 3, r8 = lane & 7;
    int rowoff = r8 + ((m8 & 1) ? 8 : 0);
    int koff8 = (m8 >= 2) ? 8 : 0;

    float c[2][4][4];
    #pragma unroll
    for (int mt = 0; mt < 2; mt++)
        #pragma unroll
        for (int nt = 0; nt < 4; nt++)
            #pragma unroll
            for (int r = 0; r < 4; r++) c[mt][nt][r] = 0.f;

    int arow = tid >> 2, ac8 = tid & 3;

    auto issue = [&](int k0, int stage) {
        uint32_t asb = smemBase + stage * ST_B;
        CPA(asb + arow * 80 + ac8 * 16, Gbf + (size_t)(bm + arow) * NN + k0 + ac8 * 8);
        uint32_t bhb = asb + AS_B;
        uint32_t blb = bhb + BH_B;
        #pragma unroll
        for (int it = 0; it < 2; it++) {
            int idx = tid + it * 256;
            int d = idx >> 2, c8 = idx & 3;
            size_t src = (size_t)(bn + d) * NN + k0 + c8 * 8;
            CPA(bhb + d * 80 + c8 * 16, Yh + src);
            CPA(blb + d * 80 + c8 * 16, Yl + src);
        }
    };

    const int nchunks = NN / KC;
    // prologue: fill 3 stages
    #pragma unroll
    for (int s = 0; s < 3; s++) { issue(s * KC, s); CPC(); }

    for (int ch = 0; ch < nchunks; ch++) {
        int nx = ch + 3;
        if (nx < nchunks) { issue(nx * KC, nx & 3); CPC(); }
        int k = nchunks - ch - 1; if (k > 3) k = 3;
        if (k == 3) { CPW3(); } else if (k == 2) { CPW2(); } else if (k == 1) { CPW1(); } else { CPW0(); }
        __syncthreads();

        uint32_t stB = smemBase + (ch & 3) * ST_B;
        uint32_t asB = stB;
        uint32_t bhB = stB + AS_B;
        uint32_t blB = bhB + BH_B;

        #pragma unroll
        for (int kt = 0; kt < 2; kt++) {
            int kcol = kt * 16 + koff8;
            uint32_t a[2][4];
            #pragma unroll
            for (int mt = 0; mt < 2; mt++) {
                uint32_t aoff = (uint32_t)((wm*32 + mt*16 + rowoff) * KCP + kcol) * 2;
                LDSM4(a[mt][0], a[mt][1], a[mt][2], a[mt][3], asB + aoff);
            }
            #pragma unroll
            for (int j = 0; j < 2; j++) {
                uint32_t boff = (uint32_t)((wn*32 + j*16 + rowoff) * KCP + kcol) * 2;
                uint32_t bh0, bh1, bh2, bh3, bl0, bl1, bl2, bl3;
                LDSM4(bh0, bh1, bh2, bh3, bhB + boff);
                LDSM4(bl0, bl1, bl2, bl3, blB + boff);
                mma_bf16(c[0][2*j],   a[0][0], a[0][1], a[0][2], a[0][3], bh0, bh2);
                mma_bf16(c[1][2*j],   a[1][0], a[1][1], a[1][2], a[1][3], bh0, bh2);
                mma_bf16(c[0][2*j],   a[0][0], a[0][1], a[0][2], a[0][3], bl0, bl2);
                mma_bf16(c[1][2*j],   a[1][0], a[1][1], a[1][2], a[1][3], bl0, bl2);
                mma_bf16(c[0][2*j+1], a[0][0], a[0][1], a[0][2], a[0][3], bh1, bh3);
                mma_bf16(c[1][2*j+1], a[1][0], a[1][1], a[1][2], a[1][3], bh1, bh3);
                mma_bf16(c[0][2*j+1], a[0][0], a[0][1], a[0][2], a[0][3], bl1, bl3);
                mma_bf16(c[1][2*j+1], a[1][0], a[1][1], a[1][2], a[1][3], bl1, bl3);
            }
        }
        __syncthreads();
    }

    #pragma unroll
    for (int mt = 0; mt < 2; mt++) {
        #pragma unroll
        for (int h = 0; h < 2; h++) {
            int row = bm + wm * 32 + mt * 16 + (lane >> 2) + h * 8;
            float cf = coef[row];
            const float* srow = S + (size_t)row * DD;
            float* orow = O + (size_t)row * DD;
            #pragma unroll
            for (int nt = 0; nt < 4; nt++) {
                int col = bn + wn * 32 + (nt >> 1) * 16 + (nt & 1) * 8 + (lane & 3) * 2;
                float v0 = c[mt][nt][h * 2 + 0];
                float v1 = c[mt][nt][h * 2 + 1];
                if (ev) { v0 += ev[col]; v1 += ev[col + 1]; }
                float2 s2 = *(const float2*)(srow + col);
                float2 o;
                o.x = fmaxf(s2.x + cf * v0, 0.f);
                o.y = fmaxf(s2.y + cf * v1, 0.f);
                *(float2*)(orow + col) = o;
            }
        }
    }
}

// ---------------- launch ----------------
extern "C" void kernel_launch(void* const* d_in, const int* in_sizes, int n_in,
                              void* d_out, int out_size) {
    const float* p_in   = (const float*)d_in[0];
    const float* q_in   = (const float*)d_in[1];
    const float* qu_in  = (const float*)d_in[2];
    const int*   pmask  = (const int*)d_in[3];
    const int*   qmask  = (const int*)d_in[4];
    const int*   qumask = (const int*)d_in[5];
    const int*   ppg    = (const int*)d_in[6];
    const int*   qqg    = (const int*)d_in[7];
    const float* W_node = (const float*)d_in[10];
    const float* b_node = (const float*)d_in[11];
    const float* W_self = (const float*)d_in[12];
    const float* b_self = (const float*)d_in[13];
    const float* W_pp   = (const float*)d_in[14];
    const float* W_qd   = (const float*)d_in[15];
    const float* W_qq   = (const float*)d_in[16];
    const float* W_qup  = (const float*)d_in[17];
    const float* W_quq  = (const float*)d_in[18];
    const float* W_p    = (const float*)d_in[19];
    const float* b_p    = (const float*)d_in[20];
    const float* W_q    = (const float*)d_in[21];
    const float* b_q    = (const float*)d_in[22];
    const float* W_qu   = (const float*)d_in[23];
    const float* b_qu   = (const float*)d_in[24];
    float* out = (float*)d_out;

    float *pA, *pB, *qA, *qB, *quA, *quB, *selfp, *selfq;
    cudaGetSymbolAddress((void**)&pA, g_pA);
    cudaGetSymbolAddress((void**)&pB, g_pB);
    cudaGetSymbolAddress((void**)&qA, g_qA);
    cudaGetSymbolAddress((void**)&qB, g_qB);
    cudaGetSymbolAddress((void**)&quA, g_quA);
    cudaGetSymbolAddress((void**)&quB, g_quB);
    cudaGetSymbolAddress((void**)&selfp, g_selfp);
    cudaGetSymbolAddress((void**)&selfq, g_selfq);

    cudaFuncSetAttribute(adjq_kernel, cudaFuncAttributeMaxDynamicSharedMemorySize, ADJ_SMEM);

    prep_kernel<<<1921, 256>>>(ppg, qqg, pmask, qmask, qumask,
                               W_self, W_pp, W_qq, W_p, W_q, W_qu);

    const float* pc = p_in;  const float* qc = q_in;  const float* quc = qu_in;
    float* pn = pA;  float* qn = qA;  float* qun = quA;

    for (int step = 0; step < 2; step++) {
        steppre_kernel<<<3200, 256>>>(pc, qc, quc, pmask, qmask, W_node, b_node);
        gemm_all_kernel<<<398, 256>>>(b_self, W_qd, W_qup, W_quq);
        adjq_kernel<<<512, 256, ADJ_SMEM>>>(selfp, selfq, pn, qn, qun);
        pc = pn; qc = qn; quc = qun;
        pn = pB; qn = qB; qun = quB;
    }

    asplit_all_kernel<<<3104, 256>>>(pc, qc, quc);
    gemm_out_kernel<<<97, 256>>>(b_p, b_q, b_qu, out);
}

// round 11
// speedup vs baseline: 3.2007x; 1.0051x over previous
#include <cuda_runtime.h>
#include <cuda_bf16.h>
#include <math.h>
#include <stdint.h>

#define BB  4
#define PP  2048
#define QQ  1024
#define QNN 32
#define DD  256
#define HH  128

// ---------------- persistent scratch ----------------
__device__ float g_pA[BB*PP*DD];
__device__ float g_pB[BB*PP*DD];
__device__ float g_qA[BB*QQ*DD];
__device__ float g_qB[BB*QQ*DD];
__device__ float g_quA[BB*QNN*DD];
__device__ float g_quB[BB*QNN*DD];
__device__ float g_selfp[BB*PP*DD];
__device__ float g_selfq[BB*QQ*DD];
__device__ float g_selfqu[BB*QNN*DD];
__device__ __nv_bfloat16 g_Yphi[BB*DD*PP];
__device__ __nv_bfloat16 g_Yplo[BB*DD*PP];
__device__ __nv_bfloat16 g_Yqhi[BB*DD*QQ];
__device__ __nv_bfloat16 g_Yqlo[BB*DD*QQ];
__device__ __nv_bfloat16 g_Gpbf[(size_t)BB*PP*PP];
__device__ __nv_bfloat16 g_Gqbf[(size_t)BB*QQ*QQ];
__device__ __nv_bfloat16 g_Aphi[BB*PP*DD];
__device__ __nv_bfloat16 g_Aplo[BB*PP*DD];
__device__ __nv_bfloat16 g_Aqhi[BB*QQ*DD];
__device__ __nv_bfloat16 g_Aqlo[BB*QQ*DD];
__device__ __nv_bfloat16 g_Aquhi[BB*QNN*DD];
__device__ __nv_bfloat16 g_Aqulo[BB*QNN*DD];
__device__ __nv_bfloat16 g_Wth[294912];
__device__ __nv_bfloat16 g_Wtl[294912];
#define OFF_SELF 0
#define OFF_PPW  65536
#define OFF_QQW  131072
#define OFF_PW   196608
#define OFF_QW   229376
#define OFF_QUW  262144
__device__ float g_rsp[BB*PP];
__device__ float g_rsq[BB*QQ];
__device__ float g_coefp[BB*PP];
__device__ float g_coefq[BB*QQ];
__device__ float g_coefqu[BB*QNN];
__device__ float g_sppart[BB*16*DD];
__device__ float g_sqpart[BB*8*DD];
__device__ float g_vqd[BB*DD];
__device__ float g_vqup[BB*DD];
__device__ float g_vquq[BB*DD];

// ---------------- asm helpers ----------------
#define CPA(dst, src) asm volatile("cp.async.cg.shared.global [%0], [%1], 16;" :: "r"(dst), "l"(src) : "memory")
#define CPC() asm volatile("cp.async.commit_group;" ::: "memory")
#define CPW2() asm volatile("cp.async.wait_group 2;" ::: "memory")
#define CPW1() asm volatile("cp.async.wait_group 1;" ::: "memory")
#define CPW0() asm volatile("cp.async.wait_group 0;" ::: "memory")
#define LDSM4(r0, r1, r2, r3, addr) \
    asm volatile("ldmatrix.sync.aligned.m8n8.x4.shared.b16 {%0,%1,%2,%3}, [%4];" \
        : "=r"(r0), "=r"(r1), "=r"(r2), "=r"(r3) : "r"(addr))

__device__ __forceinline__ void mma_bf16(float c[4], uint32_t a0, uint32_t a1,
                                         uint32_t a2, uint32_t a3,
                                         uint32_t b0, uint32_t b1) {
    asm volatile(
        "mma.sync.aligned.m16n8k16.row.col.f32.bf16.bf16.f32 "
        "{%0,%1,%2,%3}, {%4,%5,%6,%7}, {%8,%9}, {%0,%1,%2,%3};"
        : "+f"(c[0]), "+f"(c[1]), "+f"(c[2]), "+f"(c[3])
        : "r"(a0), "r"(a1), "r"(a2), "r"(a3), "r"(b0), "r"(b1));
}

__device__ __forceinline__ void split_pack2(float x, float y, uint32_t& h, uint32_t& l) {
    __nv_bfloat16 hx = __float2bfloat16(x), hy = __float2bfloat16(y);
    float rx = x - __bfloat162float(hx), ry = y - __bfloat162float(hy);
    __nv_bfloat16 lx = __float2bfloat16(rx), ly = __float2bfloat16(ry);
    h = (uint32_t)__bfloat16_as_ushort(hy) << 16 | __bfloat16_as_ushort(hx);
    l = (uint32_t)__bfloat16_as_ushort(ly) << 16 | __bfloat16_as_ushort(lx);
}

// ---------------- PREP über-kernel ----------------
__global__ __launch_bounds__(256)
void prep_kernel(const int* __restrict__ Gp, const int* __restrict__ Gq,
                 const int* __restrict__ pm, const int* __restrict__ qm,
                 const int* __restrict__ qum,
                 const float* __restrict__ W_self, const float* __restrict__ W_pp,
                 const float* __restrict__ W_qq, const float* __restrict__ W_p,
                 const float* __restrict__ W_q, const float* __restrict__ W_qu) {
    __shared__ float shp[2112];
    int bx = blockIdx.x, tid = threadIdx.x;
    if (bx < 1024) {
        int b = bx >> 8, xtile = bx & 255;
        for (int i = tid; i < PP; i += 256) shp[i] = (float)pm[b*PP + i];
        __syncthreads();
        int warp = tid >> 5, lane = tid & 31;
        int row = xtile * 8 + warp;
        const int* g = Gp + ((size_t)b*PP + row) * PP;
        __nv_bfloat16* go = g_Gpbf + ((size_t)b*PP + row) * PP;
        float s = 0.f;
        for (int j = lane * 4; j < PP; j += 128) {
            int4 v = *(const int4*)(g + j);
            uint32_t r0 = (v.x ? 0x3F80u : 0u) | ((v.y ? 0x3F80u : 0u) << 16);
            uint32_t r1 = (v.z ? 0x3F80u : 0u) | ((v.w ? 0x3F80u : 0u) << 16);
            *(uint2*)(go + j) = make_uint2(r0, r1);
            s += shp[j] * (float)v.x + shp[j+1] * (float)v.y
               + shp[j+2] * (float)v.z + shp[j+3] * (float)v.w;
        }
        #pragma unroll
        for (int o = 16; o; o >>= 1) s += __shfl_xor_sync(0xffffffffu, s, o);
        if (lane == 0)
            g_coefp[b*PP + row] = pm[b*PP + row] ? 1.f / fmaxf(s, 1.f) : 0.f;
    } else if (bx < 1536) {
        int i2 = bx - 1024;
        int b = i2 >> 7, xtile = i2 & 127;
        float ps = 0.f;
        for (int i = tid; i < PP; i += 256) ps += (float)pm[b*PP + i];
        for (int i = tid; i < QQ; i += 256) shp[i] = (float)qm[b*QQ + i];
        shp[1024 + tid] = ps;
        __syncthreads();
        if (tid < 128) shp[1024 + tid] += shp[1024 + tid + 128];
        __syncthreads();
        if (tid < 64) shp[1024 + tid] += shp[1024 + tid + 64];
        __syncthreads();
        if (tid < 32) {
            float v = shp[1024 + tid] + shp[1024 + tid + 32];
            #pragma unroll
            for (int o = 16; o; o >>= 1) v += __shfl_xor_sync(0xffffffffu, v, o);
            if (tid == 0) shp[2048] = v;
        }
        __syncthreads();
        float psum = shp[2048];
        int warp = tid >> 5, lane = tid & 31;
        int row = xtile * 8 + warp;
        const int* g = Gq + ((size_t)b*QQ + row) * QQ;
        __nv_bfloat16* go = g_Gqbf + ((size_t)b*QQ + row) * QQ;
        float s = 0.f;
        for (int j = lane * 4; j < QQ; j += 128) {
            int4 v = *(const int4*)(g + j);
            uint32_t r0 = (v.x ? 0x3F80u : 0u) | ((v.y ? 0x3F80u : 0u) << 16);
            uint32_t r1 = (v.z ? 0x3F80u : 0u) | ((v.w ? 0x3F80u : 0u) << 16);
            *(uint2*)(go + j) = make_uint2(r0, r1);
            s += shp[j] * (float)v.x + shp[j+1] * (float)v.y
               + shp[j+2] * (float)v.z + shp[j+3] * (float)v.w;
        }
        #pragma unroll
        for (int o = 16; o; o >>= 1) s += __shfl_xor_sync(0xffffffffu, s, o);
        if (lane == 0)
            g_coefq[b*QQ + row] = qm[b*QQ + row] ? 1.f / fmaxf(psum + s, 1.f) : 0.f;
    } else if (bx == 1536) {
        for (int b = 0; b < BB; b++) {
            float s = 0.f;
            for (int i = tid; i < PP; i += 256) s += (float)pm[b*PP + i];
            for (int i = tid; i < QQ; i += 256) s += (float)qm[b*QQ + i];
            shp[tid] = s;
            __syncthreads();
            for (int o = 128; o; o >>= 1) { if (tid < o) shp[tid] += shp[tid + o]; __syncthreads(); }
            if (tid == 0) shp[1024 + b] = shp[0];
            __syncthreads();
        }
        if (tid < BB*QNN) {
            int b = tid / QNN;
            g_coefqu[tid] = qum[tid] ? 1.f / fmaxf(shp[1024 + b], 1.f) : 0.f;
        }
    } else {
        int w = bx - 1537;
        int z = w / 64, ww = w % 64;
        const float* W; int N; int off;
        switch (z) {
            case 0: W = W_self; N = 256; off = OFF_SELF; break;
            case 1: W = W_pp;   N = 256; off = OFF_PPW;  break;
            case 2: W = W_qq;   N = 256; off = OFF_QQW;  break;
            case 3: W = W_p;    N = 128; off = OFF_PW;   break;
            case 4: W = W_q;    N = 128; off = OFF_QW;   break;
            default: W = W_qu;  N = 128; off = OFF_QUW;  break;
        }
        int nb = (ww & 7) * 32, kb = (ww >> 3) * 32;
        if (nb >= N) return;
        int tx = tid & 31, ty = tid >> 5;
        #pragma unroll
        for (int r = 0; r < 32; r += 8)
            shp[(ty + r) * 33 + tx] = W[(size_t)(kb + ty + r) * N + nb + tx];
        __syncthreads();
        __nv_bfloat16* Wth = g_Wth + off;
        __nv_bfloat16* Wtl = g_Wtl + off;
        #pragma unroll
        for (int r = 0; r < 32; r += 8) {
            int n = nb + ty + r, k = kb + tx;
            float v = shp[tx * 33 + ty + r];
            __nv_bfloat16 h = __float2bfloat16(v);
            Wth[(size_t)n * 256 + k] = h;
            Wtl[(size_t)n * 256 + k] = __float2bfloat16(v - __bfloat162float(h));
        }
    }
}

// ---------------- asplit body + standalone ----------------
__device__ __forceinline__ void asplit_body(int lb, const float* __restrict__ P,
                                            const float* __restrict__ Q,
                                            const float* __restrict__ QU) {
    const float* A; __nv_bfloat16 *Ahi, *Alo; int l2;
    if (lb < 2048) { A = P; Ahi = g_Aphi; Alo = g_Aplo; l2 = lb; }
    else if (lb < 3072) { A = Q; Ahi = g_Aqhi; Alo = g_Aqlo; l2 = lb - 2048; }
    else { A = QU; Ahi = g_Aquhi; Alo = g_Aqulo; l2 = lb - 3072; }
    size_t i4 = ((size_t)l2 * 256 + threadIdx.x) * 4;
    float4 v = *(const float4*)(A + i4);
    uint32_t h0, l0, h1, l1;
    split_pack2(v.x, v.y, h0, l0);
    split_pack2(v.z, v.w, h1, l1);
    *(uint2*)(Ahi + i4) = make_uint2(h0, h1);
    *(uint2*)(Alo + i4) = make_uint2(l0, l1);
}

__global__ void asplit_all_kernel(const float* __restrict__ P, const float* __restrict__ Q,
                                  const float* __restrict__ QU) {
    asplit_body(blockIdx.x, P, Q, QU);
}

// ---------------- step-pre über-kernel: pws + asplit ----------------
__global__ __launch_bounds__(256)
void steppre_kernel(const float* __restrict__ pcur, const float* __restrict__ qcur,
                    const float* __restrict__ qucur,
                    const int* __restrict__ pmask, const int* __restrict__ qmask,
                    const float* __restrict__ Wn, const float* __restrict__ bn) {
    int bx = blockIdx.x;
    if (bx >= 96) { asplit_body(bx - 96, pcur, qcur, qucur); return; }
    int b = bx / 24, chunk = bx % 24;
    int tid = threadIdx.x, wid = tid >> 5, lane = tid & 31;
    const float* node; const int* mask; float* rsout; float* sout; int rowbase;
    if (chunk < 16) {
        node = pcur + (size_t)b*PP*DD; mask = pmask + b*PP;
        rsout = g_rsp + b*PP; sout = g_sppart + (b*16 + chunk)*DD; rowbase = chunk * 128;
    } else {
        node = qcur + (size_t)b*QQ*DD; mask = qmask + b*QQ;
        rsout = g_rsq + b*QQ; sout = g_sqpart + (b*8 + (chunk - 16))*DD; rowbase = (chunk - 16) * 128;
    }
    __shared__ float wsh[DD];
    __shared__ float wrow[128];
    for (int k = tid; k < DD; k += 256) wsh[k] = Wn[k];
    __syncthreads();
    float bv = bn[0];
    #pragma unroll
    for (int r = 0; r < 16; r++) {
        int lrow = wid * 16 + r;
        const float* nrow = node + (size_t)(rowbase + lrow) * DD;
        float s = 0.f;
        #pragma unroll
        for (int k = lane; k < DD; k += 32) s += nrow[k] * wsh[k];
        #pragma unroll
        for (int o = 16; o; o >>= 1) s += __shfl_xor_sync(0xffffffffu, s, o);
        if (lane == 0) {
            float sig = 1.f / (1.f + expf(-(s + bv)));
            float w = mask[rowbase + lrow] ? sig : 0.f;
            wrow[lrow] = w;
            rsout[rowbase + lrow] = w;
        }
    }
    __syncthreads();
    float acc = 0.f;
    #pragma unroll 4
    for (int i = 0; i < 128; i++) {
        float w = wrow[i];
        if (w != 0.f) acc += w * node[(size_t)(rowbase + i) * DD + tid];
    }
    sout[tid] = acc;
}

// ---------------- shared GEMM mainloop (cp.async dbuf + ldmatrix) ----------------
#define KCP2 40
#define GST_B 40960   // per-stage: Ah | Al | Wh | Wl, 10240 each
#define GEMM_SMEM (2*GST_B)

__device__ __forceinline__ void gemm_mainloop(
        const __nv_bfloat16* __restrict__ Ahi, const __nv_bfloat16* __restrict__ Alo,
        const __nv_bfloat16* __restrict__ Wth, const __nv_bfloat16* __restrict__ Wtl,
        int bm, int bn, float c[2][8][4], char* smem) {
    uint32_t sb = (uint32_t)__cvta_generic_to_shared(smem);

    int tid = threadIdx.x, wid = tid >> 5, lane = tid & 31;
    int wm = wid >> 1, wn = wid & 1;
    int m8 = lane >> 3, r8 = lane & 7;
    int rowoff = r8 + ((m8 & 1) ? 8 : 0);
    int koff8 = (m8 >= 2) ? 8 : 0;

    auto issue = [&](int ch, int st) {
        uint32_t base = sb + st * GST_B;
        int k0 = ch * 32;
        #pragma unroll
        for (int it = 0; it < 2; it++) {
            int u = tid + it * 256;
            int row = u >> 2, c8 = u & 3;
            size_t src = (size_t)(bm + row) * DD + k0 + c8 * 8;
            CPA(base + row * 80 + c8 * 16, Ahi + src);
            CPA(base + 10240 + row * 80 + c8 * 16, Alo + src);
        }
        #pragma unroll
        for (int it = 0; it < 2; it++) {
            int u = tid + it * 256;
            int n = u >> 2, c8 = u & 3;
            size_t src = (size_t)(bn + n) * 256 + k0 + c8 * 8;
            CPA(base + 20480 + n * 80 + c8 * 16, Wth + src);
            CPA(base + 30720 + n * 80 + c8 * 16, Wtl + src);
        }
    };

    issue(0, 0);
    CPC();
    int buf = 0;
    for (int ch = 0; ch < 8; ch++) {
        bool hn = (ch < 7);
        if (hn) { issue(ch + 1, buf ^ 1); CPC(); }
        if (hn) { CPW1(); } else { CPW0(); }
        __syncthreads();
        uint32_t base = sb + buf * GST_B;
        #pragma unroll
        for (int kt = 0; kt < 2; kt++) {
            int kcol = kt * 16 + koff8;
            uint32_t ah[2][4], al[2][4];
            #pragma unroll
            for (int mt = 0; mt < 2; mt++) {
                uint32_t aoff = (uint32_t)((wm*32 + mt*16 + rowoff) * KCP2 + kcol) * 2;
                LDSM4(ah[mt][0], ah[mt][1], ah[mt][2], ah[mt][3], base + aoff);
                LDSM4(al[mt][0], al[mt][1], al[mt][2], al[mt][3], base + 10240 + aoff);
            }
            #pragma unroll
            for (int j = 0; j < 4; j++) {
                uint32_t woff = (uint32_t)((wn*64 + j*16 + rowoff) * KCP2 + kcol) * 2;
                uint32_t wh0, wh1, wh2, wh3, wl0, wl1, wl2, wl3;
                LDSM4(wh0, wh1, wh2, wh3, base + 20480 + woff);
                LDSM4(wl0, wl1, wl2, wl3, base + 30720 + woff);
                #pragma unroll
                for (int mt = 0; mt < 2; mt++) {
                    mma_bf16(c[mt][2*j],   ah[mt][0], ah[mt][1], ah[mt][2], ah[mt][3], wh0, wh2);
                    mma_bf16(c[mt][2*j],   al[mt][0], al[mt][1], al[mt][2], al[mt][3], wh0, wh2);
                    mma_bf16(c[mt][2*j],   ah[mt][0], ah[mt][1], ah[mt][2], ah[mt][3], wl0, wl2);
                    mma_bf16(c[mt][2*j+1], ah[mt][0], ah[mt][1], ah[mt][2], ah[mt][3], wh1, wh3);
                    mma_bf16(c[mt][2*j+1], al[mt][0], al[mt][1], al[mt][2], al[mt][3], wh1, wh3);
                    mma_bf16(c[mt][2*j+1], ah[mt][0], ah[mt][1], ah[mt][2], ah[mt][3], wl1, wl3);
                }
            }
        }
        __syncthreads();
        buf ^= 1;
    }
}

__device__ __forceinline__ void gemm_epi_self(float c[2][8][4], float* Cself,
                                              const float* bias, int bm, int bn, int N) {
    int tid = threadIdx.x, wid = tid >> 5, lane = tid & 31;
    int wm = wid >> 1, wn = wid & 1;
    #pragma unroll
    for (int mt = 0; mt < 2; mt++)
        #pragma unroll
        for (int h = 0; h < 2; h++) {
            int row = bm + wm * 32 + mt * 16 + (lane >> 2) + h * 8;
            float* orow = Cself + (size_t)row * N;
            #pragma unroll
            for (int nt = 0; nt < 8; nt++) {
                int col = bn + wn * 64 + nt * 8 + (lane & 3) * 2;
                float2 o;
                o.x = c[mt][nt][h * 2 + 0] + bias[col];
                o.y = c[mt][nt][h * 2 + 1] + bias[col + 1];
                *(float2*)(orow + col) = o;
            }
        }
}

// step-phase GEMM + vec über-kernel
__global__ __launch_bounds__(256)
void gemm_all_kernel(const float* __restrict__ b_self,
                     const float* __restrict__ Wqd, const float* __restrict__ Wqup,
                     const float* __restrict__ Wquq) {
    extern __shared__ char gsm[];
    int idx = blockIdx.x;
    if (idx >= 386) {
        int v = idx - 386;
        int b = v & 3, sel = v >> 2, tid = threadIdx.x;
        float* sh = (float*)gsm;
        const float* W = (sel == 0) ? Wqd : (sel == 1) ? Wqup : Wquq;
        float* out = (sel == 0) ? g_vqd : (sel == 1) ? g_vqup : g_vquq;
        float sv = 0.f;
        if (sel < 2) {
            #pragma unroll
            for (int cc = 0; cc < 16; cc++) sv += g_sppart[(b*16 + cc)*DD + tid];
        } else {
            #pragma unroll
            for (int cc = 0; cc < 8; cc++) sv += g_sqpart[(b*8 + cc)*DD + tid];
        }
        sh[tid] = sv;
        __syncthreads();
        float acc = 0.f;
        #pragma unroll 8
        for (int k = 0; k < DD; k++) acc += sh[k] * W[(size_t)k*DD + tid];
        out[b*DD + tid] = acc;
        return;
    }
    const __nv_bfloat16 *Ahi, *Alo, *WthS, *WtlS, *WthY, *WtlY;
    float* Cself; const float* rowscale;
    __nv_bfloat16 *Yhi, *Ylo; int NNbatch, bm, by;
    if (idx < 256) {
        by = idx >> 6; bm = (idx & 63) * 128;
        Ahi = g_Aphi; Alo = g_Aplo;
        WthY = g_Wth + OFF_PPW; WtlY = g_Wtl + OFF_PPW;
        Cself = g_selfp; rowscale = g_rsp; Yhi = g_Yphi; Ylo = g_Yplo; NNbatch = PP;
    } else if (idx < 384) {
        int i2 = idx - 256;
        by = i2 >> 5; bm = (i2 & 31) * 128;
        Ahi = g_Aqhi; Alo = g_Aqlo;
        WthY = g_Wth + OFF_QQW; WtlY = g_Wtl + OFF_QQW;
        Cself = g_selfq; rowscale = g_rsq; Yhi = g_Yqhi; Ylo = g_Yqlo; NNbatch = QQ;
    } else {
        by = idx - 384; bm = 0;
        Ahi = g_Aquhi; Alo = g_Aqulo;
        WthY = nullptr; WtlY = nullptr;
        Cself = g_selfqu; rowscale = nullptr; Yhi = nullptr; Ylo = nullptr; NNbatch = 0;
    }
    WthS = g_Wth + OFF_SELF; WtlS = g_Wtl + OFF_SELF;
    int mode = by >> 1;
    int bn = (by & 1) * 128;
    const __nv_bfloat16* Wth = mode ? WthY : WthS;
    const __nv_bfloat16* Wtl = mode ? WtlY : WtlS;

    float c[2][8][4];
    #pragma unroll
    for (int mt = 0; mt < 2; mt++)
        #pragma unroll
        for (int nt = 0; nt < 8; nt++)
            #pragma unroll
            for (int r = 0; r < 4; r++) c[mt][nt][r] = 0.f;

    gemm_mainloop(Ahi, Alo, Wth, Wtl, bm, bn, c, gsm);

    int tid = threadIdx.x, wid = tid >> 5, lane = tid & 31;
    int wm = wid >> 1, wn = wid & 1;
    if (mode == 0) {
        gemm_epi_self(c, Cself, b_self, bm, bn, DD);
    } else {
        #pragma unroll
        for (int mt = 0; mt < 2; mt++)
            #pragma unroll
            for (int h = 0; h < 2; h++) {
                int gr = bm + wm * 32 + mt * 16 + (lane >> 2) + h * 8;
                float rs = rowscale[gr];
                int b = gr / NNbatch;
                int i = gr - b * NNbatch;
                #pragma unroll
                for (int nt = 0; nt < 8; nt++) {
                    int col = bn + wn * 64 + nt * 8 + (lane & 3) * 2;
                    size_t base = ((size_t)b * DD + col) * NNbatch + i;
                    float v0 = c[mt][nt][h * 2 + 0] * rs;
                    float v1 = c[mt][nt][h * 2 + 1] * rs;
                    __nv_bfloat16 h0 = __float2bfloat16(v0);
                    __nv_bfloat16 h1 = __float2bfloat16(v1);
                    Yhi[base] = h0;
                    Yhi[base + NNbatch] = h1;
                    Ylo[base] = __float2bfloat16(v0 - __bfloat162float(h0));
                    Ylo[base + NNbatch] = __float2bfloat16(v1 - __bfloat162float(h1));
                }
            }
    }
}

// merged output projections: [0,64) p, [64,96) q, 96 qu
__global__ __launch_bounds__(256)
void gemm_out_kernel(const float* __restrict__ b_p, const float* __restrict__ b_q,
                     const float* __restrict__ b_qu, float* __restrict__ out) {
    extern __shared__ char gsm[];
    int bx = blockIdx.x;
    const __nv_bfloat16 *Ahi, *Alo, *Wth, *Wtl; const float* bias; float* O; int bm;
    if (bx < 64) {
        Ahi = g_Aphi; Alo = g_Aplo; Wth = g_Wth + OFF_PW; Wtl = g_Wtl + OFF_PW;
        bias = b_p; O = out; bm = bx * 128;
    } else if (bx < 96) {
        Ahi = g_Aqhi; Alo = g_Aqlo; Wth = g_Wth + OFF_QW; Wtl = g_Wtl + OFF_QW;
        bias = b_q; O = out + (size_t)BB*PP*HH; bm = (bx - 64) * 128;
    } else {
        Ahi = g_Aquhi; Alo = g_Aqulo; Wth = g_Wth + OFF_QUW; Wtl = g_Wtl + OFF_QUW;
        bias = b_qu; O = out + (size_t)BB*PP*HH + (size_t)BB*QQ*HH; bm = 0;
    }
    float c[2][8][4];
    #pragma unroll
    for (int mt = 0; mt < 2; mt++)
        #pragma unroll
        for (int nt = 0; nt < 8; nt++)
            #pragma unroll
            for (int r = 0; r < 4; r++) c[mt][nt][r] = 0.f;

    gemm_mainloop(Ahi, Alo, Wth, Wtl, bm, 0, c, gsm);
    gemm_epi_self(c, O, bias, bm, 0, HH);
}

// ---------------- adjacency: 4-stage, single-barrier pipeline + qu_update ----------------
// [0,256) p-adj | [256,384) q-adj | [384,512) qu_update
#define KC 32
#define KCP 40
#define AS_B 5120
#define BH_B 10240
#define ST_B (AS_B + 2*BH_B)       // 25600 per stage
#define ADJ_SMEM (4*ST_B)          // 102400

__global__ __launch_bounds__(256, 2)
void adjq_kernel(const float* __restrict__ selfp, const float* __restrict__ selfq,
                 float* __restrict__ Op, float* __restrict__ Oq,
                 float* __restrict__ qunxt) {
    extern __shared__ __align__(16) char dsm[];
    int bx = blockIdx.x;
    int tid = threadIdx.x;
    if (bx >= 384) {
        int r = bx - 384;
        int b = r / QNN;
        float v = g_selfqu[(size_t)r*DD + tid] + g_coefqu[r] * (g_vqup[b*DD + tid] + g_vquq[b*DD + tid]);
        qunxt[(size_t)r*DD + tid] = fmaxf(v, 0.f);
        return;
    }
    uint32_t smemBase = (uint32_t)__cvta_generic_to_shared(dsm);

    const __nv_bfloat16 *Gbf, *Yh, *Yl; const float *S, *coef, *ev;
    float* O; int NN, b, mtile, nhalf;
    if (bx < 256) {
        nhalf = bx & 1;
        int rest = bx >> 1;
        b = rest >> 5; mtile = rest & 31; NN = PP;
        Gbf = g_Gpbf + (size_t)b*PP*PP;
        Yh = g_Yphi + (size_t)b*DD*PP;  Yl = g_Yplo + (size_t)b*DD*PP;
        S = selfp + (size_t)b*PP*DD;    coef = g_coefp + b*PP;
        ev = nullptr;                   O = Op + (size_t)b*PP*DD;
    } else {
        int i2 = bx - 256;
        nhalf = i2 & 1;
        int rest = i2 >> 1;
        b = rest >> 4; mtile = rest & 15; NN = QQ;
        Gbf = g_Gqbf + (size_t)b*QQ*QQ;
        Yh = g_Yqhi + (size_t)b*DD*QQ;  Yl = g_Yqlo + (size_t)b*DD*QQ;
        S = selfq + (size_t)b*QQ*DD;    coef = g_coefq + b*QQ;
        ev = g_vqd + b*DD;              O = Oq + (size_t)b*QQ*DD;
    }
    int bm = mtile * 64, bn = nhalf * 128;
    int wid = tid >> 5, lane = tid & 31;
    int wm = wid >> 2, wn = wid & 3;
    int m8 = lane >> 3, r8 = lane & 7;
    int rowoff = r8 + ((m8 & 1) ? 8 : 0);
    int koff8 = (m8 >= 2) ? 8 : 0;

    float c[2][4][4];
    #pragma unroll
    for (int mt = 0; mt < 2; mt++)
        #pragma unroll
        for (int nt = 0; nt < 4; nt++)
            #pragma unroll
            for (int r = 0; r < 4; r++) c[mt][nt][r] = 0.f;

    int arow = tid >> 2, ac8 = tid & 3;

    auto issue = [&](int k0, int stage) {
        uint32_t asb = smemBase + stage * ST_B;
        CPA(asb + arow * 80 + ac8 * 16, Gbf + (size_t)(bm + arow) * NN + k0 + ac8 * 8);
        uint32_t bhb = asb + AS_B;
        uint32_t blb = bhb + BH_B;
        #pragma unroll
        for (int it = 0; it < 2; it++) {
            int idx = tid + it * 256;
            int d = idx >> 2, c8 = idx & 3;
            size_t src = (size_t)(bn + d) * NN + k0 + c8 * 8;
            CPA(bhb + d * 80 + c8 * 16, Yh + src);
            CPA(blb + d * 80 + c8 * 16, Yl + src);
        }
    };

    const int nchunks = NN / KC;
    // prologue: fill stages 0..2
    #pragma unroll
    for (int s = 0; s < 3; s++) { issue(s * KC, s); CPC(); }

    for (int ch = 0; ch < nchunks; ch++) {
        // wait for chunk ch (in flight at most ch..ch+2 before this iteration's commit)
        int rem = nchunks - 1 - ch;
        if (rem >= 2) { CPW2(); } else if (rem == 1) { CPW1(); } else { CPW0(); }
        __syncthreads();   // single barrier: data ready AND stage (ch-1)&3 free for reuse
        int nx = ch + 3;
        if (nx < nchunks) { issue(nx * KC, nx & 3); CPC(); }

        uint32_t stB = smemBase + (ch & 3) * ST_B;
        uint32_t asB = stB;
        uint32_t bhB = stB + AS_B;
        uint32_t blB = bhB + BH_B;

        #pragma unroll
        for (int kt = 0; kt < 2; kt++) {
            int kcol = kt * 16 + koff8;
            uint32_t a[2][4];
            #pragma unroll
            for (int mt = 0; mt < 2; mt++) {
                uint32_t aoff = (uint32_t)((wm*32 + mt*16 + rowoff) * KCP + kcol) * 2;
                LDSM4(a[mt][0], a[mt][1], a[mt][2], a[mt][3], asB + aoff);
            }
            #pragma unroll
            for (int j = 0; j < 2; j++) {
                uint32_t boff = (uint32_t)((wn*32 + j*16 + rowoff) * KCP + kcol) * 2;
                uint32_t bh0, bh1, bh2, bh3, bl0, bl1, bl2, bl3;
                LDSM4(bh0, bh1, bh2, bh3, bhB + boff);
                LDSM4(bl0, bl1, bl2, bl3, blB + boff);
                mma_bf16(c[0][2*j],   a[0][0], a[0][1], a[0][2], a[0][3], bh0, bh2);
                mma_bf16(c[1][2*j],   a[1][0], a[1][1], a[1][2], a[1][3], bh0, bh2);
                mma_bf16(c[0][2*j],   a[0][0], a[0][1], a[0][2], a[0][3], bl0, bl2);
                mma_bf16(c[1][2*j],   a[1][0], a[1][1], a[1][2], a[1][3], bl0, bl2);
                mma_bf16(c[0][2*j+1], a[0][0], a[0][1], a[0][2], a[0][3], bh1, bh3);
                mma_bf16(c[1][2*j+1], a[1][0], a[1][1], a[1][2], a[1][3], bh1, bh3);
                mma_bf16(c[0][2*j+1], a[0][0], a[0][1], a[0][2], a[0][3], bl1, bl3);
                mma_bf16(c[1][2*j+1], a[1][0], a[1][1], a[1][2], a[1][3], bl1, bl3);
            }
        }
        // no trailing barrier: next iteration's barrier orders reuse
    }

    #pragma unroll
    for (int mt = 0; mt < 2; mt++) {
        #pragma unroll
        for (int h = 0; h < 2; h++) {
            int row = bm + wm * 32 + mt * 16 + (lane >> 2) + h * 8;
            float cf = coef[row];
            const float* srow = S + (size_t)row * DD;
            float* orow = O + (size_t)row * DD;
            #pragma unroll
            for (int nt = 0; nt < 4; nt++) {
                int col = bn + wn * 32 + (nt >> 1) * 16 + (nt & 1) * 8 + (lane & 3) * 2;
                float v0 = c[mt][nt][h * 2 + 0];
                float v1 = c[mt][nt][h * 2 + 1];
                if (ev) { v0 += ev[col]; v1 += ev[col + 1]; }
                float2 s2 = *(const float2*)(srow + col);
                float2 o;
                o.x = fmaxf(s2.x + cf * v0, 0.f);
                o.y = fmaxf(s2.y + cf * v1, 0.f);
                *(float2*)(orow + col) = o;
            }
        }
    }
}

// ---------------- launch ----------------
extern "C" void kernel_launch(void* const* d_in, const int* in_sizes, int n_in,
                              void* d_out, int out_size) {
    const float* p_in   = (const float*)d_in[0];
    const float* q_in   = (const float*)d_in[1];
    const float* qu_in  = (const float*)d_in[2];
    const int*   pmask  = (const int*)d_in[3];
    const int*   qmask  = (const int*)d_in[4];
    const int*   qumask = (const int*)d_in[5];
    const int*   ppg    = (const int*)d_in[6];
    const int*   qqg    = (const int*)d_in[7];
    const float* W_node = (const float*)d_in[10];
    const float* b_node = (const float*)d_in[11];
    const float* W_self = (const float*)d_in[12];
    const float* b_self = (const float*)d_in[13];
    const float* W_pp   = (const float*)d_in[14];
    const float* W_qd   = (const float*)d_in[15];
    const float* W_qq   = (const float*)d_in[16];
    const float* W_qup  = (const float*)d_in[17];
    const float* W_quq  = (const float*)d_in[18];
    const float* W_p    = (const float*)d_in[19];
    const float* b_p    = (const float*)d_in[20];
    const float* W_q    = (const float*)d_in[21];
    const float* b_q    = (const float*)d_in[22];
    const float* W_qu   = (const float*)d_in[23];
    const float* b_qu   = (const float*)d_in[24];
    float* out = (float*)d_out;

    float *pA, *pB, *qA, *qB, *quA, *quB, *selfp, *selfq;
    cudaGetSymbolAddress((void**)&pA, g_pA);
    cudaGetSymbolAddress((void**)&pB, g_pB);
    cudaGetSymbolAddress((void**)&qA, g_qA);
    cudaGetSymbolAddress((void**)&qB, g_qB);
    cudaGetSymbolAddress((void**)&quA, g_quA);
    cudaGetSymbolAddress((void**)&quB, g_quB);
    cudaGetSymbolAddress((void**)&selfp, g_selfp);
    cudaGetSymbolAddress((void**)&selfq, g_selfq);

    cudaFuncSetAttribute(adjq_kernel, cudaFuncAttributeMaxDynamicSharedMemorySize, ADJ_SMEM);
    cudaFuncSetAttribute(gemm_all_kernel, cudaFuncAttributeMaxDynamicSharedMemorySize, GEMM_SMEM);
    cudaFuncSetAttribute(gemm_out_kernel, cudaFuncAttributeMaxDynamicSharedMemorySize, GEMM_SMEM);

    prep_kernel<<<1921, 256>>>(ppg, qqg, pmask, qmask, qumask,
                               W_self, W_pp, W_qq, W_p, W_q, W_qu);

    const float* pc = p_in;  const float* qc = q_in;  const float* quc = qu_in;
    float* pn = pA;  float* qn = qA;  float* qun = quA;

    for (int step = 0; step < 2; step++) {
        steppre_kernel<<<3200, 256>>>(pc, qc, quc, pmask, qmask, W_node, b_node);
        gemm_all_kernel<<<398, 256, GEMM_SMEM>>>(b_self, W_qd, W_qup, W_quq);
        adjq_kernel<<<512, 256, ADJ_SMEM>>>(selfp, selfq, pn, qn, qun);
        pc = pn; qc = qn; quc = qun;
        pn = pB; qn = qB; qun = quB;
    }

    asplit_all_kernel<<<3104, 256>>>(pc, qc, quc);
    gemm_out_kernel<<<97, 256, GEMM_SMEM>>>(b_p, b_q, b_qu, out);
}

// round 12
// speedup vs baseline: 3.2484x; 1.0149x over previous
#include <cuda_runtime.h>
#include <cuda_bf16.h>
#include <math.h>
#include <stdint.h>

#define BB  4
#define PP  2048
#define QQ  1024
#define QNN 32
#define DD  256
#define HH  128

// ---------------- persistent scratch ----------------
__device__ float g_pA[BB*PP*DD];
__device__ float g_pB[BB*PP*DD];
__device__ float g_qA[BB*QQ*DD];
__device__ float g_qB[BB*QQ*DD];
__device__ float g_quA[BB*QNN*DD];
__device__ float g_quB[BB*QNN*DD];
__device__ float g_selfp[BB*PP*DD];
__device__ float g_selfq[BB*QQ*DD];
__device__ float g_selfqu[BB*QNN*DD];
__device__ __nv_bfloat16 g_Yphi[BB*DD*PP];
__device__ __nv_bfloat16 g_Yplo[BB*DD*PP];
__device__ __nv_bfloat16 g_Yqhi[BB*DD*QQ];
__device__ __nv_bfloat16 g_Yqlo[BB*DD*QQ];
__device__ __nv_bfloat16 g_Gpbf[(size_t)BB*PP*PP];
__device__ __nv_bfloat16 g_Gqbf[(size_t)BB*QQ*QQ];
__device__ __nv_bfloat16 g_Aphi[BB*PP*DD];
__device__ __nv_bfloat16 g_Aplo[BB*PP*DD];
__device__ __nv_bfloat16 g_Aqhi[BB*QQ*DD];
__device__ __nv_bfloat16 g_Aqlo[BB*QQ*DD];
__device__ __nv_bfloat16 g_Aquhi[BB*QNN*DD];
__device__ __nv_bfloat16 g_Aqulo[BB*QNN*DD];
__device__ __nv_bfloat16 g_Wth[294912];
__device__ __nv_bfloat16 g_Wtl[294912];
#define OFF_SELF 0
#define OFF_PPW  65536
#define OFF_QQW  131072
#define OFF_PW   196608
#define OFF_QW   229376
#define OFF_QUW  262144
__device__ float g_rsp[BB*PP];
__device__ float g_rsq[BB*QQ];
__device__ float g_coefp[BB*PP];
__device__ float g_coefq[BB*QQ];
__device__ float g_coefqu[BB*QNN];
__device__ float g_sppart[BB*16*DD];
__device__ float g_sqpart[BB*8*DD];
__device__ float g_vqd[BB*DD];
__device__ float g_vqup[BB*DD];
__device__ float g_vquq[BB*DD];

// ---------------- asm helpers ----------------
#define CPA(dst, src) asm volatile("cp.async.cg.shared.global [%0], [%1], 16;" :: "r"(dst), "l"(src) : "memory")
#define CPC() asm volatile("cp.async.commit_group;" ::: "memory")
#define CPW2() asm volatile("cp.async.wait_group 2;" ::: "memory")
#define CPW1() asm volatile("cp.async.wait_group 1;" ::: "memory")
#define CPW0() asm volatile("cp.async.wait_group 0;" ::: "memory")
#define LDSM4(r0, r1, r2, r3, addr) \
    asm volatile("ldmatrix.sync.aligned.m8n8.x4.shared.b16 {%0,%1,%2,%3}, [%4];" \
        : "=r"(r0), "=r"(r1), "=r"(r2), "=r"(r3) : "r"(addr))

__device__ __forceinline__ void mma_bf16(float c[4], uint32_t a0, uint32_t a1,
                                         uint32_t a2, uint32_t a3,
                                         uint32_t b0, uint32_t b1) {
    asm volatile(
        "mma.sync.aligned.m16n8k16.row.col.f32.bf16.bf16.f32 "
        "{%0,%1,%2,%3}, {%4,%5,%6,%7}, {%8,%9}, {%0,%1,%2,%3};"
        : "+f"(c[0]), "+f"(c[1]), "+f"(c[2]), "+f"(c[3])
        : "r"(a0), "r"(a1), "r"(a2), "r"(a3), "r"(b0), "r"(b1));
}

__device__ __forceinline__ void split_pack2(float x, float y, uint32_t& h, uint32_t& l) {
    __nv_bfloat16 hx = __float2bfloat16(x), hy = __float2bfloat16(y);
    float rx = x - __bfloat162float(hx), ry = y - __bfloat162float(hy);
    __nv_bfloat16 lx = __float2bfloat16(rx), ly = __float2bfloat16(ry);
    h = (uint32_t)__bfloat16_as_ushort(hy) << 16 | __bfloat16_as_ushort(hx);
    l = (uint32_t)__bfloat16_as_ushort(ly) << 16 | __bfloat16_as_ushort(lx);
}

// ---------------- PREP über-kernel ----------------
__global__ __launch_bounds__(256)
void prep_kernel(const int* __restrict__ Gp, const int* __restrict__ Gq,
                 const int* __restrict__ pm, const int* __restrict__ qm,
                 const int* __restrict__ qum,
                 const float* __restrict__ W_self, const float* __restrict__ W_pp,
                 const float* __restrict__ W_qq, const float* __restrict__ W_p,
                 const float* __restrict__ W_q, const float* __restrict__ W_qu) {
    __shared__ float shp[2112];
    int bx = blockIdx.x, tid = threadIdx.x;
    if (bx < 1024) {
        int b = bx >> 8, xtile = bx & 255;
        for (int i = tid; i < PP; i += 256) shp[i] = (float)pm[b*PP + i];
        __syncthreads();
        int warp = tid >> 5, lane = tid & 31;
        int row = xtile * 8 + warp;
        const int* g = Gp + ((size_t)b*PP + row) * PP;
        __nv_bfloat16* go = g_Gpbf + ((size_t)b*PP + row) * PP;
        float s = 0.f;
        for (int j = lane * 4; j < PP; j += 128) {
            int4 v = *(const int4*)(g + j);
            uint32_t r0 = (v.x ? 0x3F80u : 0u) | ((v.y ? 0x3F80u : 0u) << 16);
            uint32_t r1 = (v.z ? 0x3F80u : 0u) | ((v.w ? 0x3F80u : 0u) << 16);
            *(uint2*)(go + j) = make_uint2(r0, r1);
            s += shp[j] * (float)v.x + shp[j+1] * (float)v.y
               + shp[j+2] * (float)v.z + shp[j+3] * (float)v.w;
        }
        #pragma unroll
        for (int o = 16; o; o >>= 1) s += __shfl_xor_sync(0xffffffffu, s, o);
        if (lane == 0)
            g_coefp[b*PP + row] = pm[b*PP + row] ? 1.f / fmaxf(s, 1.f) : 0.f;
    } else if (bx < 1536) {
        int i2 = bx - 1024;
        int b = i2 >> 7, xtile = i2 & 127;
        float ps = 0.f;
        for (int i = tid; i < PP; i += 256) ps += (float)pm[b*PP + i];
        for (int i = tid; i < QQ; i += 256) shp[i] = (float)qm[b*QQ + i];
        shp[1024 + tid] = ps;
        __syncthreads();
        if (tid < 128) shp[1024 + tid] += shp[1024 + tid + 128];
        __syncthreads();
        if (tid < 64) shp[1024 + tid] += shp[1024 + tid + 64];
        __syncthreads();
        if (tid < 32) {
            float v = shp[1024 + tid] + shp[1024 + tid + 32];
            #pragma unroll
            for (int o = 16; o; o >>= 1) v += __shfl_xor_sync(0xffffffffu, v, o);
            if (tid == 0) shp[2048] = v;
        }
        __syncthreads();
        float psum = shp[2048];
        int warp = tid >> 5, lane = tid & 31;
        int row = xtile * 8 + warp;
        const int* g = Gq + ((size_t)b*QQ + row) * QQ;
        __nv_bfloat16* go = g_Gqbf + ((size_t)b*QQ + row) * QQ;
        float s = 0.f;
        for (int j = lane * 4; j < QQ; j += 128) {
            int4 v = *(const int4*)(g + j);
            uint32_t r0 = (v.x ? 0x3F80u : 0u) | ((v.y ? 0x3F80u : 0u) << 16);
            uint32_t r1 = (v.z ? 0x3F80u : 0u) | ((v.w ? 0x3F80u : 0u) << 16);
            *(uint2*)(go + j) = make_uint2(r0, r1);
            s += shp[j] * (float)v.x + shp[j+1] * (float)v.y
               + shp[j+2] * (float)v.z + shp[j+3] * (float)v.w;
        }
        #pragma unroll
        for (int o = 16; o; o >>= 1) s += __shfl_xor_sync(0xffffffffu, s, o);
        if (lane == 0)
            g_coefq[b*QQ + row] = qm[b*QQ + row] ? 1.f / fmaxf(psum + s, 1.f) : 0.f;
    } else if (bx == 1536) {
        for (int b = 0; b < BB; b++) {
            float s = 0.f;
            for (int i = tid; i < PP; i += 256) s += (float)pm[b*PP + i];
            for (int i = tid; i < QQ; i += 256) s += (float)qm[b*QQ + i];
            shp[tid] = s;
            __syncthreads();
            for (int o = 128; o; o >>= 1) { if (tid < o) shp[tid] += shp[tid + o]; __syncthreads(); }
            if (tid == 0) shp[1024 + b] = shp[0];
            __syncthreads();
        }
        if (tid < BB*QNN) {
            int b = tid / QNN;
            g_coefqu[tid] = qum[tid] ? 1.f / fmaxf(shp[1024 + b], 1.f) : 0.f;
        }
    } else {
        int w = bx - 1537;
        int z = w / 64, ww = w % 64;
        const float* W; int N; int off;
        switch (z) {
            case 0: W = W_self; N = 256; off = OFF_SELF; break;
            case 1: W = W_pp;   N = 256; off = OFF_PPW;  break;
            case 2: W = W_qq;   N = 256; off = OFF_QQW;  break;
            case 3: W = W_p;    N = 128; off = OFF_PW;   break;
            case 4: W = W_q;    N = 128; off = OFF_QW;   break;
            default: W = W_qu;  N = 128; off = OFF_QUW;  break;
        }
        int nb = (ww & 7) * 32, kb = (ww >> 3) * 32;
        if (nb >= N) return;
        int tx = tid & 31, ty = tid >> 5;
        #pragma unroll
        for (int r = 0; r < 32; r += 8)
            shp[(ty + r) * 33 + tx] = W[(size_t)(kb + ty + r) * N + nb + tx];
        __syncthreads();
        __nv_bfloat16* Wth = g_Wth + off;
        __nv_bfloat16* Wtl = g_Wtl + off;
        #pragma unroll
        for (int r = 0; r < 32; r += 8) {
            int n = nb + ty + r, k = kb + tx;
            float v = shp[tx * 33 + ty + r];
            __nv_bfloat16 h = __float2bfloat16(v);
            Wth[(size_t)n * 256 + k] = h;
            Wtl[(size_t)n * 256 + k] = __float2bfloat16(v - __bfloat162float(h));
        }
    }
}

// ---------------- asplit body + standalone ----------------
__device__ __forceinline__ void asplit_body(int lb, const float* __restrict__ P,
                                            const float* __restrict__ Q,
                                            const float* __restrict__ QU) {
    const float* A; __nv_bfloat16 *Ahi, *Alo; int l2;
    if (lb < 2048) { A = P; Ahi = g_Aphi; Alo = g_Aplo; l2 = lb; }
    else if (lb < 3072) { A = Q; Ahi = g_Aqhi; Alo = g_Aqlo; l2 = lb - 2048; }
    else { A = QU; Ahi = g_Aquhi; Alo = g_Aqulo; l2 = lb - 3072; }
    size_t i4 = ((size_t)l2 * 256 + threadIdx.x) * 4;
    float4 v = *(const float4*)(A + i4);
    uint32_t h0, l0, h1, l1;
    split_pack2(v.x, v.y, h0, l0);
    split_pack2(v.z, v.w, h1, l1);
    *(uint2*)(Ahi + i4) = make_uint2(h0, h1);
    *(uint2*)(Alo + i4) = make_uint2(l0, l1);
}

__global__ void asplit_all_kernel(const float* __restrict__ P, const float* __restrict__ Q,
                                  const float* __restrict__ QU) {
    asplit_body(blockIdx.x, P, Q, QU);
}

// ---------------- step-pre über-kernel: pws + asplit ----------------
__global__ __launch_bounds__(256)
void steppre_kernel(const float* __restrict__ pcur, const float* __restrict__ qcur,
                    const float* __restrict__ qucur,
                    const int* __restrict__ pmask, const int* __restrict__ qmask,
                    const float* __restrict__ Wn, const float* __restrict__ bn) {
    int bx = blockIdx.x;
    if (bx >= 96) { asplit_body(bx - 96, pcur, qcur, qucur); return; }
    int b = bx / 24, chunk = bx % 24;
    int tid = threadIdx.x, wid = tid >> 5, lane = tid & 31;
    const float* node; const int* mask; float* rsout; float* sout; int rowbase;
    if (chunk < 16) {
        node = pcur + (size_t)b*PP*DD; mask = pmask + b*PP;
        rsout = g_rsp + b*PP; sout = g_sppart + (b*16 + chunk)*DD; rowbase = chunk * 128;
    } else {
        node = qcur + (size_t)b*QQ*DD; mask = qmask + b*QQ;
        rsout = g_rsq + b*QQ; sout = g_sqpart + (b*8 + (chunk - 16))*DD; rowbase = (chunk - 16) * 128;
    }
    __shared__ float wsh[DD];
    __shared__ float wrow[128];
    for (int k = tid; k < DD; k += 256) wsh[k] = Wn[k];
    __syncthreads();
    float bv = bn[0];
    #pragma unroll
    for (int r = 0; r < 16; r++) {
        int lrow = wid * 16 + r;
        const float* nrow = node + (size_t)(rowbase + lrow) * DD;
        float s = 0.f;
        #pragma unroll
        for (int k = lane; k < DD; k += 32) s += nrow[k] * wsh[k];
        #pragma unroll
        for (int o = 16; o; o >>= 1) s += __shfl_xor_sync(0xffffffffu, s, o);
        if (lane == 0) {
            float sig = 1.f / (1.f + expf(-(s + bv)));
            float w = mask[rowbase + lrow] ? sig : 0.f;
            wrow[lrow] = w;
            rsout[rowbase + lrow] = w;
        }
    }
    __syncthreads();
    float acc = 0.f;
    #pragma unroll 4
    for (int i = 0; i < 128; i++) {
        float w = wrow[i];
        if (w != 0.f) acc += w * node[(size_t)(rowbase + i) * DD + tid];
    }
    sout[tid] = acc;
}

// ---------------- shared GEMM mainloop (cp.async dbuf + ldmatrix, ILP-ordered) ----------------
#define KCP2 40
#define GST_B 40960
#define GEMM_SMEM (2*GST_B)

__device__ __forceinline__ void gemm_mainloop(
        const __nv_bfloat16* __restrict__ Ahi, const __nv_bfloat16* __restrict__ Alo,
        const __nv_bfloat16* __restrict__ Wth, const __nv_bfloat16* __restrict__ Wtl,
        int bm, int bn, float c[2][8][4], char* smem) {
    uint32_t sb = (uint32_t)__cvta_generic_to_shared(smem);

    int tid = threadIdx.x, wid = tid >> 5, lane = tid & 31;
    int wm = wid >> 1, wn = wid & 1;
    int m8 = lane >> 3, r8 = lane & 7;
    int rowoff = r8 + ((m8 & 1) ? 8 : 0);
    int koff8 = (m8 >= 2) ? 8 : 0;

    auto issue = [&](int ch, int st) {
        uint32_t base = sb + st * GST_B;
        int k0 = ch * 32;
        #pragma unroll
        for (int it = 0; it < 2; it++) {
            int u = tid + it * 256;
            int row = u >> 2, c8 = u & 3;
            size_t src = (size_t)(bm + row) * DD + k0 + c8 * 8;
            CPA(base + row * 80 + c8 * 16, Ahi + src);
            CPA(base + 10240 + row * 80 + c8 * 16, Alo + src);
        }
        #pragma unroll
        for (int it = 0; it < 2; it++) {
            int u = tid + it * 256;
            int n = u >> 2, c8 = u & 3;
            size_t src = (size_t)(bn + n) * 256 + k0 + c8 * 8;
            CPA(base + 20480 + n * 80 + c8 * 16, Wth + src);
            CPA(base + 30720 + n * 80 + c8 * 16, Wtl + src);
        }
    };

    issue(0, 0);
    CPC();
    int buf = 0;
    for (int ch = 0; ch < 8; ch++) {
        bool hn = (ch < 7);
        if (hn) { issue(ch + 1, buf ^ 1); CPC(); }
        if (hn) { CPW1(); } else { CPW0(); }
        __syncthreads();
        uint32_t base = sb + buf * GST_B;
        #pragma unroll
        for (int kt = 0; kt < 2; kt++) {
            int kcol = kt * 16 + koff8;
            uint32_t ah[2][4], al[2][4];
            #pragma unroll
            for (int mt = 0; mt < 2; mt++) {
                uint32_t aoff = (uint32_t)((wm*32 + mt*16 + rowoff) * KCP2 + kcol) * 2;
                LDSM4(ah[mt][0], ah[mt][1], ah[mt][2], ah[mt][3], base + aoff);
                LDSM4(al[mt][0], al[mt][1], al[mt][2], al[mt][3], base + 10240 + aoff);
            }
            #pragma unroll
            for (int j = 0; j < 4; j++) {
                uint32_t woff = (uint32_t)((wn*64 + j*16 + rowoff) * KCP2 + kcol) * 2;
                uint32_t wh0, wh1, wh2, wh3, wl0, wl1, wl2, wl3;
                LDSM4(wh0, wh1, wh2, wh3, base + 20480 + woff);
                LDSM4(wl0, wl1, wl2, wl3, base + 30720 + woff);
                // pass 1: ah x wh  (4 independent accumulators)
                mma_bf16(c[0][2*j],   ah[0][0], ah[0][1], ah[0][2], ah[0][3], wh0, wh2);
                mma_bf16(c[1][2*j],   ah[1][0], ah[1][1], ah[1][2], ah[1][3], wh0, wh2);
                mma_bf16(c[0][2*j+1], ah[0][0], ah[0][1], ah[0][2], ah[0][3], wh1, wh3);
                mma_bf16(c[1][2*j+1], ah[1][0], ah[1][1], ah[1][2], ah[1][3], wh1, wh3);
                // pass 2: al x wh
                mma_bf16(c[0][2*j],   al[0][0], al[0][1], al[0][2], al[0][3], wh0, wh2);
                mma_bf16(c[1][2*j],   al[1][0], al[1][1], al[1][2], al[1][3], wh0, wh2);
                mma_bf16(c[0][2*j+1], al[0][0], al[0][1], al[0][2], al[0][3], wh1, wh3);
                mma_bf16(c[1][2*j+1], al[1][0], al[1][1], al[1][2], al[1][3], wh1, wh3);
                // pass 3: ah x wl
                mma_bf16(c[0][2*j],   ah[0][0], ah[0][1], ah[0][2], ah[0][3], wl0, wl2);
                mma_bf16(c[1][2*j],   ah[1][0], ah[1][1], ah[1][2], ah[1][3], wl0, wl2);
                mma_bf16(c[0][2*j+1], ah[0][0], ah[0][1], ah[0][2], ah[0][3], wl1, wl3);
                mma_bf16(c[1][2*j+1], ah[1][0], ah[1][1], ah[1][2], ah[1][3], wl1, wl3);
            }
        }
        __syncthreads();
        buf ^= 1;
    }
}

__device__ __forceinline__ void gemm_epi_self(float c[2][8][4], float* Cself,
                                              const float* bias, int bm, int bn, int N) {
    int tid = threadIdx.x, wid = tid >> 5, lane = tid & 31;
    int wm = wid >> 1, wn = wid & 1;
    #pragma unroll
    for (int mt = 0; mt < 2; mt++)
        #pragma unroll
        for (int h = 0; h < 2; h++) {
            int row = bm + wm * 32 + mt * 16 + (lane >> 2) + h * 8;
            float* orow = Cself + (size_t)row * N;
            #pragma unroll
            for (int nt = 0; nt < 8; nt++) {
                int col = bn + wn * 64 + nt * 8 + (lane & 3) * 2;
                float2 o;
                o.x = c[mt][nt][h * 2 + 0] + bias[col];
                o.y = c[mt][nt][h * 2 + 1] + bias[col + 1];
                *(float2*)(orow + col) = o;
            }
        }
}

// step-phase GEMM + vec über-kernel
__global__ __launch_bounds__(256)
void gemm_all_kernel(const float* __restrict__ b_self,
                     const float* __restrict__ Wqd, const float* __restrict__ Wqup,
                     const float* __restrict__ Wquq) {
    extern __shared__ char gsm[];
    int idx = blockIdx.x;
    if (idx >= 386) {
        int v = idx - 386;
        int b = v & 3, sel = v >> 2, tid = threadIdx.x;
        float* sh = (float*)gsm;
        const float* W = (sel == 0) ? Wqd : (sel == 1) ? Wqup : Wquq;
        float* out = (sel == 0) ? g_vqd : (sel == 1) ? g_vqup : g_vquq;
        float sv = 0.f;
        if (sel < 2) {
            #pragma unroll
            for (int cc = 0; cc < 16; cc++) sv += g_sppart[(b*16 + cc)*DD + tid];
        } else {
            #pragma unroll
            for (int cc = 0; cc < 8; cc++) sv += g_sqpart[(b*8 + cc)*DD + tid];
        }
        sh[tid] = sv;
        __syncthreads();
        float acc = 0.f;
        #pragma unroll 8
        for (int k = 0; k < DD; k++) acc += sh[k] * W[(size_t)k*DD + tid];
        out[b*DD + tid] = acc;
        return;
    }
    const __nv_bfloat16 *Ahi, *Alo, *WthS, *WtlS, *WthY, *WtlY;
    float* Cself; const float* rowscale;
    __nv_bfloat16 *Yhi, *Ylo; int NNbatch, bm, by;
    if (idx < 256) {
        by = idx >> 6; bm = (idx & 63) * 128;
        Ahi = g_Aphi; Alo = g_Aplo;
        WthY = g_Wth + OFF_PPW; WtlY = g_Wtl + OFF_PPW;
        Cself = g_selfp; rowscale = g_rsp; Yhi = g_Yphi; Ylo = g_Yplo; NNbatch = PP;
    } else if (idx < 384) {
        int i2 = idx - 256;
        by = i2 >> 5; bm = (i2 & 31) * 128;
        Ahi = g_Aqhi; Alo = g_Aqlo;
        WthY = g_Wth + OFF_QQW; WtlY = g_Wtl + OFF_QQW;
        Cself = g_selfq; rowscale = g_rsq; Yhi = g_Yqhi; Ylo = g_Yqlo; NNbatch = QQ;
    } else {
        by = idx - 384; bm = 0;
        Ahi = g_Aquhi; Alo = g_Aqulo;
        WthY = nullptr; WtlY = nullptr;
        Cself = g_selfqu; rowscale = nullptr; Yhi = nullptr; Ylo = nullptr; NNbatch = 0;
    }
    WthS = g_Wth + OFF_SELF; WtlS = g_Wtl + OFF_SELF;
    int mode = by >> 1;
    int bn = (by & 1) * 128;
    const __nv_bfloat16* Wth = mode ? WthY : WthS;
    const __nv_bfloat16* Wtl = mode ? WtlY : WtlS;

    float c[2][8][4];
    #pragma unroll
    for (int mt = 0; mt < 2; mt++)
        #pragma unroll
        for (int nt = 0; nt < 8; nt++)
            #pragma unroll
            for (int r = 0; r < 4; r++) c[mt][nt][r] = 0.f;

    gemm_mainloop(Ahi, Alo, Wth, Wtl, bm, bn, c, gsm);

    int tid = threadIdx.x, wid = tid >> 5, lane = tid & 31;
    int wm = wid >> 1, wn = wid & 1;
    if (mode == 0) {
        gemm_epi_self(c, Cself, b_self, bm, bn, DD);
    } else {
        #pragma unroll
        for (int mt = 0; mt < 2; mt++)
            #pragma unroll
            for (int h = 0; h < 2; h++) {
                int gr = bm + wm * 32 + mt * 16 + (lane >> 2) + h * 8;
                float rs = rowscale[gr];
                int b = gr / NNbatch;
                int i = gr - b * NNbatch;
                #pragma unroll
                for (int nt = 0; nt < 8; nt++) {
                    int col = bn + wn * 64 + nt * 8 + (lane & 3) * 2;
                    size_t base = ((size_t)b * DD + col) * NNbatch + i;
                    float v0 = c[mt][nt][h * 2 + 0] * rs;
                    float v1 = c[mt][nt][h * 2 + 1] * rs;
                    __nv_bfloat16 h0 = __float2bfloat16(v0);
                    __nv_bfloat16 h1 = __float2bfloat16(v1);
                    Yhi[base] = h0;
                    Yhi[base + NNbatch] = h1;
                    Ylo[base] = __float2bfloat16(v0 - __bfloat162float(h0));
                    Ylo[base + NNbatch] = __float2bfloat16(v1 - __bfloat162float(h1));
                }
            }
    }
}

// merged output projections: [0,64) p, [64,96) q, 96 qu
__global__ __launch_bounds__(256)
void gemm_out_kernel(const float* __restrict__ b_p, const float* __restrict__ b_q,
                     const float* __restrict__ b_qu, float* __restrict__ out) {
    extern __shared__ char gsm[];
    int bx = blockIdx.x;
    const __nv_bfloat16 *Ahi, *Alo, *Wth, *Wtl; const float* bias; float* O; int bm;
    if (bx < 64) {
        Ahi = g_Aphi; Alo = g_Aplo; Wth = g_Wth + OFF_PW; Wtl = g_Wtl + OFF_PW;
        bias = b_p; O = out; bm = bx * 128;
    } else if (bx < 96) {
        Ahi = g_Aqhi; Alo = g_Aqlo; Wth = g_Wth + OFF_QW; Wtl = g_Wtl + OFF_QW;
        bias = b_q; O = out + (size_t)BB*PP*HH; bm = (bx - 64) * 128;
    } else {
        Ahi = g_Aquhi; Alo = g_Aqulo; Wth = g_Wth + OFF_QUW; Wtl = g_Wtl + OFF_QUW;
        bias = b_qu; O = out + (size_t)BB*PP*HH + (size_t)BB*QQ*HH; bm = 0;
    }
    float c[2][8][4];
    #pragma unroll
    for (int mt = 0; mt < 2; mt++)
        #pragma unroll
        for (int nt = 0; nt < 8; nt++)
            #pragma unroll
            for (int r = 0; r < 4; r++) c[mt][nt][r] = 0.f;

    gemm_mainloop(Ahi, Alo, Wth, Wtl, bm, 0, c, gsm);
    gemm_epi_self(c, O, bias, bm, 0, HH);
}

// ---------------- adjacency: 4-stage pipeline, ILP-ordered MMA + qu_update ----------------
#define KC 32
#define KCP 40
#define AS_B 5120
#define BH_B 10240
#define ST_B (AS_B + 2*BH_B)
#define ADJ_SMEM (4*ST_B)

__global__ __launch_bounds__(256, 2)
void adjq_kernel(const float* __restrict__ selfp, const float* __restrict__ selfq,
                 float* __restrict__ Op, float* __restrict__ Oq,
                 float* __restrict__ qunxt) {
    extern __shared__ __align__(16) char dsm[];
    int bx = blockIdx.x;
    int tid = threadIdx.x;
    if (bx >= 384) {
        int r = bx - 384;
        int b = r / QNN;
        float v = g_selfqu[(size_t)r*DD + tid] + g_coefqu[r] * (g_vqup[b*DD + tid] + g_vquq[b*DD + tid]);
        qunxt[(size_t)r*DD + tid] = fmaxf(v, 0.f);
        return;
    }
    uint32_t smemBase = (uint32_t)__cvta_generic_to_shared(dsm);

    const __nv_bfloat16 *Gbf, *Yh, *Yl; const float *S, *coef, *ev;
    float* O; int NN, b, mtile, nhalf;
    if (bx < 256) {
        nhalf = bx & 1;
        int rest = bx >> 1;
        b = rest >> 5; mtile = rest & 31; NN = PP;
        Gbf = g_Gpbf + (size_t)b*PP*PP;
        Yh = g_Yphi + (size_t)b*DD*PP;  Yl = g_Yplo + (size_t)b*DD*PP;
        S = selfp + (size_t)b*PP*DD;    coef = g_coefp + b*PP;
        ev = nullptr;                   O = Op + (size_t)b*PP*DD;
    } else {
        int i2 = bx - 256;
        nhalf = i2 & 1;
        int rest = i2 >> 1;
        b = rest >> 4; mtile = rest & 15; NN = QQ;
        Gbf = g_Gqbf + (size_t)b*QQ*QQ;
        Yh = g_Yqhi + (size_t)b*DD*QQ;  Yl = g_Yqlo + (size_t)b*DD*QQ;
        S = selfq + (size_t)b*QQ*DD;    coef = g_coefq + b*QQ;
        ev = g_vqd + b*DD;              O = Oq + (size_t)b*QQ*DD;
    }
    int bm = mtile * 64, bn = nhalf * 128;
    int wid = tid >> 5, lane = tid & 31;
    int wm = wid >> 2, wn = wid & 3;
    int m8 = lane >> 3, r8 = lane & 7;
    int rowoff = r8 + ((m8 & 1) ? 8 : 0);
    int koff8 = (m8 >= 2) ? 8 : 0;

    float c[2][4][4];
    #pragma unroll
    for (int mt = 0; mt < 2; mt++)
        #pragma unroll
        for (int nt = 0; nt < 4; nt++)
            #pragma unroll
            for (int r = 0; r < 4; r++) c[mt][nt][r] = 0.f;

    int arow = tid >> 2, ac8 = tid & 3;

    auto issue = [&](int k0, int stage) {
        uint32_t asb = smemBase + stage * ST_B;
        CPA(asb + arow * 80 + ac8 * 16, Gbf + (size_t)(bm + arow) * NN + k0 + ac8 * 8);
        uint32_t bhb = asb + AS_B;
        uint32_t blb = bhb + BH_B;
        #pragma unroll
        for (int it = 0; it < 2; it++) {
            int idx = tid + it * 256;
            int d = idx >> 2, c8 = idx & 3;
            size_t src = (size_t)(bn + d) * NN + k0 + c8 * 8;
            CPA(bhb + d * 80 + c8 * 16, Yh + src);
            CPA(blb + d * 80 + c8 * 16, Yl + src);
        }
    };

    const int nchunks = NN / KC;
    #pragma unroll
    for (int s = 0; s < 3; s++) { issue(s * KC, s); CPC(); }

    for (int ch = 0; ch < nchunks; ch++) {
        int rem = nchunks - 1 - ch;
        if (rem >= 2) { CPW2(); } else if (rem == 1) { CPW1(); } else { CPW0(); }
        __syncthreads();
        int nx = ch + 3;
        if (nx < nchunks) { issue(nx * KC, nx & 3); CPC(); }

        uint32_t stB = smemBase + (ch & 3) * ST_B;
        uint32_t asB = stB;
        uint32_t bhB = stB + AS_B;
        uint32_t blB = bhB + BH_B;

        #pragma unroll
        for (int kt = 0; kt < 2; kt++) {
            int kcol = kt * 16 + koff8;
            uint32_t a[2][4];
            #pragma unroll
            for (int mt = 0; mt < 2; mt++) {
                uint32_t aoff = (uint32_t)((wm*32 + mt*16 + rowoff) * KCP + kcol) * 2;
                LDSM4(a[mt][0], a[mt][1], a[mt][2], a[mt][3], asB + aoff);
            }
            // load ALL B fragments (both j), then hi pass over 8 accumulators, then lo pass
            uint32_t bh[2][4], bl[2][4];
            #pragma unroll
            for (int j = 0; j < 2; j++) {
                uint32_t boff = (uint32_t)((wn*32 + j*16 + rowoff) * KCP + kcol) * 2;
                LDSM4(bh[j][0], bh[j][1], bh[j][2], bh[j][3], bhB + boff);
                LDSM4(bl[j][0], bl[j][1], bl[j][2], bl[j][3], blB + boff);
            }
            // hi pass: 8 independent accumulators
            mma_bf16(c[0][0], a[0][0], a[0][1], a[0][2], a[0][3], bh[0][0], bh[0][2]);
            mma_bf16(c[1][0], a[1][0], a[1][1], a[1][2], a[1][3], bh[0][0], bh[0][2]);
            mma_bf16(c[0][1], a[0][0], a[0][1], a[0][2], a[0][3], bh[0][1], bh[0][3]);
            mma_bf16(c[1][1], a[1][0], a[1][1], a[1][2], a[1][3], bh[0][1], bh[0][3]);
            mma_bf16(c[0][2], a[0][0], a[0][1], a[0][2], a[0][3], bh[1][0], bh[1][2]);
            mma_bf16(c[1][2], a[1][0], a[1][1], a[1][2], a[1][3], bh[1][0], bh[1][2]);
            mma_bf16(c[0][3], a[0][0], a[0][1], a[0][2], a[0][3], bh[1][1], bh[1][3]);
            mma_bf16(c[1][3], a[1][0], a[1][1], a[1][2], a[1][3], bh[1][1], bh[1][3]);
            // lo pass
            mma_bf16(c[0][0], a[0][0], a[0][1], a[0][2], a[0][3], bl[0][0], bl[0][2]);
            mma_bf16(c[1][0], a[1][0], a[1][1], a[1][2], a[1][3], bl[0][0], bl[0][2]);
            mma_bf16(c[0][1], a[0][0], a[0][1], a[0][2], a[0][3], bl[0][1], bl[0][3]);
            mma_bf16(c[1][1], a[1][0], a[1][1], a[1][2], a[1][3], bl[0][1], bl[0][3]);
            mma_bf16(c[0][2], a[0][0], a[0][1], a[0][2], a[0][3], bl[1][0], bl[1][2]);
            mma_bf16(c[1][2], a[1][0], a[1][1], a[1][2], a[1][3], bl[1][0], bl[1][2]);
            mma_bf16(c[0][3], a[0][0], a[0][1], a[0][2], a[0][3], bl[1][1], bl[1][3]);
            mma_bf16(c[1][3], a[1][0], a[1][1], a[1][2], a[1][3], bl[1][1], bl[1][3]);
        }
    }

    #pragma unroll
    for (int mt = 0; mt < 2; mt++) {
        #pragma unroll
        for (int h = 0; h < 2; h++) {
            int row = bm + wm * 32 + mt * 16 + (lane >> 2) + h * 8;
            float cf = coef[row];
            const float* srow = S + (size_t)row * DD;
            float* orow = O + (size_t)row * DD;
            #pragma unroll
            for (int nt = 0; nt < 4; nt++) {
                int col = bn + wn * 32 + (nt >> 1) * 16 + (nt & 1) * 8 + (lane & 3) * 2;
                float v0 = c[mt][nt][h * 2 + 0];
                float v1 = c[mt][nt][h * 2 + 1];
                if (ev) { v0 += ev[col]; v1 += ev[col + 1]; }
                float2 s2 = *(const float2*)(srow + col);
                float2 o;
                o.x = fmaxf(s2.x + cf * v0, 0.f);
                o.y = fmaxf(s2.y + cf * v1, 0.f);
                *(float2*)(orow + col) = o;
            }
        }
    }
}

// ---------------- launch ----------------
extern "C" void kernel_launch(void* const* d_in, const int* in_sizes, int n_in,
                              void* d_out, int out_size) {
    const float* p_in   = (const float*)d_in[0];
    const float* q_in   = (const float*)d_in[1];
    const float* qu_in  = (const float*)d_in[2];
    const int*   pmask  = (const int*)d_in[3];
    const int*   qmask  = (const int*)d_in[4];
    const int*   qumask = (const int*)d_in[5];
    const int*   ppg    = (const int*)d_in[6];
    const int*   qqg    = (const int*)d_in[7];
    const float* W_node = (const float*)d_in[10];
    const float* b_node = (const float*)d_in[11];
    const float* W_self = (const float*)d_in[12];
    const float* b_self = (const float*)d_in[13];
    const float* W_pp   = (const float*)d_in[14];
    const float* W_qd   = (const float*)d_in[15];
    const float* W_qq   = (const float*)d_in[16];
    const float* W_qup  = (const float*)d_in[17];
    const float* W_quq  = (const float*)d_in[18];
    const float* W_p    = (const float*)d_in[19];
    const float* b_p    = (const float*)d_in[20];
    const float* W_q    = (const float*)d_in[21];
    const float* b_q    = (const float*)d_in[22];
    const float* W_qu   = (const float*)d_in[23];
    const float* b_qu   = (const float*)d_in[24];
    float* out = (float*)d_out;

    float *pA, *pB, *qA, *qB, *quA, *quB, *selfp, *selfq;
    cudaGetSymbolAddress((void**)&pA, g_pA);
    cudaGetSymbolAddress((void**)&pB, g_pB);
    cudaGetSymbolAddress((void**)&qA, g_qA);
    cudaGetSymbolAddress((void**)&qB, g_qB);
    cudaGetSymbolAddress((void**)&quA, g_quA);
    cudaGetSymbolAddress((void**)&quB, g_quB);
    cudaGetSymbolAddress((void**)&selfp, g_selfp);
    cudaGetSymbolAddress((void**)&selfq, g_selfq);

    cudaFuncSetAttribute(adjq_kernel, cudaFuncAttributeMaxDynamicSharedMemorySize, ADJ_SMEM);
    cudaFuncSetAttribute(gemm_all_kernel, cudaFuncAttributeMaxDynamicSharedMemorySize, GEMM_SMEM);
    cudaFuncSetAttribute(gemm_out_kernel, cudaFuncAttributeMaxDynamicSharedMemorySize, GEMM_SMEM);

    prep_kernel<<<1921, 256>>>(ppg, qqg, pmask, qmask, qumask,
                               W_self, W_pp, W_qq, W_p, W_q, W_qu);

    const float* pc = p_in;  const float* qc = q_in;  const float* quc = qu_in;
    float* pn = pA;  float* qn = qA;  float* qun = quA;

    for (int step = 0; step < 2; step++) {
        steppre_kernel<<<3200, 256>>>(pc, qc, quc, pmask, qmask, W_node, b_node);
        gemm_all_kernel<<<398, 256, GEMM_SMEM>>>(b_self, W_qd, W_qup, W_quq);
        adjq_kernel<<<512, 256, ADJ_SMEM>>>(selfp, selfq, pn, qn, qun);
        pc = pn; qc = qn; quc = qun;
        pn = pB; qn = qB; qun = quB;
    }

    asplit_all_kernel<<<3104, 256>>>(pc, qc, quc);
    gemm_out_kernel<<<97, 256, GEMM_SMEM>>>(b_p, b_q, b_qu, out);
}